// round 2
// baseline (speedup 1.0000x reference)
#include <cuda_runtime.h>
#include <cstdint>

// ---------------- problem constants ----------------
#define BATCH   2
#define TSEQ    2048
#define NEMBD   1024
#define NHEAD   16
#define HEADD   64
#define NHID    2816
#define MROWS   (BATCH*TSEQ)          // 4096
#define QKVC    (3*NEMBD)             // 3072

// ---------------- scratch (no allocations allowed) ----------------
// offsets (floats)
#define OFF_H    0u
#define OFF_QKV  4194304u             // 4096*1024
#define OFF_Y    16777216u            // + 4096*3072
#define OFF_X1   20971520u
#define OFF_H2   25165824u
#define OFF_FC1  29360128u
#define OFF_FC2  40894464u            // + 4096*2816
#define OFF_TRIG 52428800u            // + 4096*2816 ; cos[65536] then sin[65536]
#define BUF_TOTAL 52559872u

__device__ float g_buf[BUF_TOTAL];

// ---------------- RoPE trig table (double-precision arg reduction) ---------
// Fast-math demotes sincosf to sin.approx which is wildly inaccurate for
// args ~2000 rad. Build the table once per launch with fp64 reduction.
__global__ void trig_k(float* __restrict__ trig) {
    int i = blockIdx.x * blockDim.x + threadIdx.x;  // 65536 = 2048*32
    int pair = i & 31;
    int t    = i >> 5;
    double theta = pow(10000.0, -(double)pair / 32.0);
    double ang   = fmod((double)t * theta, 6.283185307179586);
    trig[i]         = (float)cos(ang);
    trig[65536 + i] = (float)sin(ang);
}

// ---------------- RMSNorm: one block per row ----------------
__global__ void rmsnorm_k(const float* __restrict__ x,
                          const float* __restrict__ scale,
                          float* __restrict__ out) {
    int row = blockIdx.x;
    int tid = threadIdx.x; // 256 threads, 4 floats each = 1024
    const float4* xr = (const float4*)(x + (size_t)row * NEMBD);
    float4 v = xr[tid];
    float ss = v.x*v.x + v.y*v.y + v.z*v.z + v.w*v.w;
    #pragma unroll
    for (int o = 16; o > 0; o >>= 1) ss += __shfl_xor_sync(0xffffffffu, ss, o);
    __shared__ float red[8];
    __shared__ float stot;
    if ((tid & 31) == 0) red[tid >> 5] = ss;
    __syncthreads();
    if (tid == 0) {
        float t = 0.f;
        #pragma unroll
        for (int i = 0; i < 8; i++) t += red[i];
        stot = rsqrtf(t * (1.0f/NEMBD) + 1e-5f);
    }
    __syncthreads();
    float rs = stot;
    float4 s4 = ((const float4*)scale)[tid];
    float4 o4;
    o4.x = v.x * rs * s4.x;
    o4.y = v.y * rs * s4.y;
    o4.z = v.z * rs * s4.z;
    o4.w = v.w * rs * s4.w;
    ((float4*)(out + (size_t)row * NEMBD))[tid] = o4;
}

// ---------------- SGEMM: C[M,N] = A[M,K] @ B[K,N] (+ res) ----------------
// BM=BN=128, BK=8, 256 threads, 8x8 per thread. All dims divide evenly here.
template<bool RES>
__global__ __launch_bounds__(256)
void sgemm_k(const float* __restrict__ A, const float* __restrict__ B,
             const float* __restrict__ res, float* __restrict__ C,
             int M, int N, int K) {
    __shared__ float As[8][128];
    __shared__ float Bs[8][128];
    int tid = threadIdx.x;
    int bm = blockIdx.y * 128;
    int bn = blockIdx.x * 128;

    int arow  = tid >> 1;            // 0..127
    int acol4 = (tid & 1) * 4;       // 0 or 4
    int brow  = tid >> 5;            // 0..7
    int bcol4 = (tid & 31) * 4;      // 0..124

    int tr = (tid >> 4) * 8;         // 0..120
    int tc = (tid & 15) * 8;

    float acc[8][8];
    #pragma unroll
    for (int i = 0; i < 8; i++)
        #pragma unroll
        for (int j = 0; j < 8; j++) acc[i][j] = 0.f;

    const float* Aptr = A + (size_t)(bm + arow) * K + acol4;
    const float* Bptr = B + (size_t)brow * N + bn + bcol4;

    for (int k0 = 0; k0 < K; k0 += 8) {
        float4 av = *(const float4*)(Aptr + k0);
        As[acol4+0][arow] = av.x;
        As[acol4+1][arow] = av.y;
        As[acol4+2][arow] = av.z;
        As[acol4+3][arow] = av.w;
        *(float4*)(&Bs[brow][bcol4]) = *(const float4*)(Bptr + (size_t)k0 * N);
        __syncthreads();
        #pragma unroll
        for (int k = 0; k < 8; k++) {
            float ar[8], br[8];
            *(float4*)(&ar[0]) = *(const float4*)(&As[k][tr]);
            *(float4*)(&ar[4]) = *(const float4*)(&As[k][tr+4]);
            *(float4*)(&br[0]) = *(const float4*)(&Bs[k][tc]);
            *(float4*)(&br[4]) = *(const float4*)(&Bs[k][tc+4]);
            #pragma unroll
            for (int i = 0; i < 8; i++)
                #pragma unroll
                for (int j = 0; j < 8; j++)
                    acc[i][j] = fmaf(ar[i], br[j], acc[i][j]);
        }
        __syncthreads();
    }

    #pragma unroll
    for (int i = 0; i < 8; i++) {
        size_t ro = (size_t)(bm + tr + i) * N + bn + tc;
        if (RES) {
            float4 r0 = *(const float4*)(res + ro);
            float4 r1 = *(const float4*)(res + ro + 4);
            acc[i][0]+=r0.x; acc[i][1]+=r0.y; acc[i][2]+=r0.z; acc[i][3]+=r0.w;
            acc[i][4]+=r1.x; acc[i][5]+=r1.y; acc[i][6]+=r1.z; acc[i][7]+=r1.w;
        }
        float4 o0 = make_float4(acc[i][0], acc[i][1], acc[i][2], acc[i][3]);
        float4 o1 = make_float4(acc[i][4], acc[i][5], acc[i][6], acc[i][7]);
        *(float4*)(C + ro)     = o0;
        *(float4*)(C + ro + 4) = o1;
    }
}

// ---------------- RoPE (in-place on q,k slabs of qkv) ----------------
__global__ void rope_k(float* __restrict__ qkv, const float* __restrict__ trig) {
    int idx = blockIdx.x * blockDim.x + threadIdx.x; // 4,194,304 total
    int pair = idx & 31;
    int h    = (idx >> 5) & 15;
    int slot = (idx >> 9) & 1;
    int m    = idx >> 10;            // 0..4095
    int t    = m & (TSEQ - 1);
    float c = trig[t * 32 + pair];
    float s = trig[65536 + t * 32 + pair];
    size_t base = (size_t)m * QKVC + (size_t)slot * NEMBD + h * HEADD + 2*pair;
    float xe = qkv[base], xo = qkv[base+1];
    qkv[base]   = xe*c - xo*s;
    qkv[base+1] = xe*s + xo*c;
}

// ---------------- Flash attention (fp32, online softmax) ----------------
// grid: (qtile=16, head=16, batch=2); block: 128 threads (1 query row each)
__global__ __launch_bounds__(128)
void attn_k(const float* __restrict__ qkv, const int* __restrict__ y_mask,
            float* __restrict__ y) {
    int qt = blockIdx.x, h = blockIdx.y, b = blockIdx.z;
    int r  = threadIdx.x;
    int qi = qt * 128 + r;                     // local sequence index

    __shared__ float Ks[64][64];
    __shared__ float Vs[64][64];
    __shared__ int   ymS[64];

    const float* base = qkv + (size_t)b * TSEQ * QKVC;

    // Q row into registers
    float q[64];
    {
        const float4* qp = (const float4*)(base + (size_t)qi * QKVC + h * HEADD);
        #pragma unroll
        for (int d4 = 0; d4 < 16; d4++) {
            float4 t4 = qp[d4];
            q[4*d4+0]=t4.x; q[4*d4+1]=t4.y; q[4*d4+2]=t4.z; q[4*d4+3]=t4.w;
        }
    }
    if (r < 64) ymS[r] = y_mask[b * 64 + r];
    bool ymq = (qi < 64) && (y_mask[b * 64 + qi] != 0);

    float o[64];
    #pragma unroll
    for (int d = 0; d < 64; d++) o[d] = 0.f;
    float mrun = -1e30f, l = 0.f;

    int nkv = 2*qt + 2;  // 64-wide kv tiles needed for causal coverage
    for (int kt = 0; kt < nkv; kt++) {
        // cooperative K/V tile load (64x64 each)
        for (int i = r; i < 64*16; i += 128) {
            int row = i >> 4;
            int c4  = (i & 15) << 2;
            const float* kp = base + (size_t)(kt*64 + row) * QKVC + NEMBD  + h*HEADD + c4;
            const float* vp = base + (size_t)(kt*64 + row) * QKVC + 2*NEMBD + h*HEADD + c4;
            *(float4*)(&Ks[row][c4]) = *(const float4*)kp;
            *(float4*)(&Vs[row][c4]) = *(const float4*)vp;
        }
        __syncthreads();

        for (int jc = 0; jc < 4; jc++) {    // 16-key chunks (bounds regs)
            float sc[16];
            #pragma unroll
            for (int jj = 0; jj < 16; jj++) {
                int j = jc*16 + jj;
                const float4* kr = (const float4*)(&Ks[j][0]);
                float s = 0.f;
                #pragma unroll
                for (int d4 = 0; d4 < 16; d4++) {
                    float4 kv = kr[d4];
                    s = fmaf(q[4*d4+0], kv.x, s);
                    s = fmaf(q[4*d4+1], kv.y, s);
                    s = fmaf(q[4*d4+2], kv.z, s);
                    s = fmaf(q[4*d4+3], kv.w, s);
                }
                int kj = kt*64 + j;
                bool ok = (kj <= qi) || (ymq && kj < 64 && ymS[kj] != 0);
                sc[jj] = ok ? s * 0.125f : -1e30f;
            }
            float tmax = sc[0];
            #pragma unroll
            for (int jj = 1; jj < 16; jj++) tmax = fmaxf(tmax, sc[jj]);
            float mnew = fmaxf(mrun, tmax);
            float corr = __expf(mrun - mnew);
            l *= corr;
            #pragma unroll
            for (int d = 0; d < 64; d++) o[d] *= corr;
            #pragma unroll
            for (int jj = 0; jj < 16; jj++) {
                sc[jj] = __expf(sc[jj] - mnew);
                l += sc[jj];
            }
            #pragma unroll
            for (int jj = 0; jj < 16; jj++) {
                int j = jc*16 + jj;
                float p = sc[jj];
                const float4* vr = (const float4*)(&Vs[j][0]);
                #pragma unroll
                for (int d4 = 0; d4 < 16; d4++) {
                    float4 vv = vr[d4];
                    o[4*d4+0] = fmaf(p, vv.x, o[4*d4+0]);
                    o[4*d4+1] = fmaf(p, vv.y, o[4*d4+1]);
                    o[4*d4+2] = fmaf(p, vv.z, o[4*d4+2]);
                    o[4*d4+3] = fmaf(p, vv.w, o[4*d4+3]);
                }
            }
            mrun = mnew;
        }
        __syncthreads();
    }

    float inv = 1.0f / l;
    float* yp = y + (size_t)(b * TSEQ + qi) * NEMBD + h * HEADD;
    #pragma unroll
    for (int d4 = 0; d4 < 16; d4++) {
        float4 o4 = make_float4(o[4*d4+0]*inv, o[4*d4+1]*inv, o[4*d4+2]*inv, o[4*d4+3]*inv);
        ((float4*)yp)[d4] = o4;
    }
}

// ---------------- SwiGLU: fc1 = silu(fc1) * fc2 ----------------
__global__ void swiglu_k(float* __restrict__ a, const float* __restrict__ b) {
    int idx = blockIdx.x * blockDim.x + threadIdx.x;  // float4 granularity
    float4 av = ((const float4*)a)[idx];
    float4 bv = ((const float4*)b)[idx];
    float4 ov;
    ov.x = av.x / (1.f + __expf(-av.x)) * bv.x;
    ov.y = av.y / (1.f + __expf(-av.y)) * bv.y;
    ov.z = av.z / (1.f + __expf(-av.z)) * bv.z;
    ov.w = av.w / (1.f + __expf(-av.w)) * bv.w;
    ((float4*)a)[idx] = ov;
}

// ---------------- launch ----------------
extern "C" void kernel_launch(void* const* d_in, const int* in_sizes, int n_in,
                              void* d_out, int out_size) {
    const float* x    = (const float*)d_in[0];
    const int*   ym   = (const int*)  d_in[1];
    const float* Wqkv = (const float*)d_in[2];
    const float* Wap  = (const float*)d_in[3];
    const float* s1   = (const float*)d_in[4];
    const float* s2   = (const float*)d_in[5];
    const float* Wfc1 = (const float*)d_in[6];
    const float* Wfc2 = (const float*)d_in[7];
    const float* Wmp  = (const float*)d_in[8];
    float* out = (float*)d_out;

    float* buf = nullptr;
    cudaGetSymbolAddress((void**)&buf, g_buf);
    float* h    = buf + OFF_H;
    float* qkv  = buf + OFF_QKV;
    float* y    = buf + OFF_Y;
    float* x1   = buf + OFF_X1;
    float* h2   = buf + OFF_H2;
    float* fc1  = buf + OFF_FC1;
    float* fc2  = buf + OFF_FC2;
    float* trig = buf + OFF_TRIG;

    // trig table (fp64 arg reduction; immune to fast-math sin.approx)
    trig_k<<<65536/256, 256>>>(trig);
    // h = rmsnorm(x, scale1)
    rmsnorm_k<<<MROWS, 256>>>(x, s1, h);
    // qkv = h @ Wqkv
    sgemm_k<false><<<dim3(QKVC/128, MROWS/128), 256>>>(h, Wqkv, nullptr, qkv, MROWS, QKVC, NEMBD);
    // RoPE on q,k
    rope_k<<<(MROWS*2*NEMBD/(2*256)), 256>>>(qkv, trig);   // 4,194,304 threads
    // attention -> y
    attn_k<<<dim3(TSEQ/128, NHEAD, BATCH), 128>>>(qkv, ym, y);
    // x1 = x + y @ Wattn_proj
    sgemm_k<true><<<dim3(NEMBD/128, MROWS/128), 256>>>(y, Wap, x, x1, MROWS, NEMBD, NEMBD);
    // h2 = rmsnorm(x1, scale2)
    rmsnorm_k<<<MROWS, 256>>>(x1, s2, h2);
    // fc1 = h2 @ Wfc1 ; fc2 = h2 @ Wfc2
    sgemm_k<false><<<dim3(NHID/128, MROWS/128), 256>>>(h2, Wfc1, nullptr, fc1, MROWS, NHID, NEMBD);
    sgemm_k<false><<<dim3(NHID/128, MROWS/128), 256>>>(h2, Wfc2, nullptr, fc2, MROWS, NHID, NEMBD);
    // fc1 = silu(fc1)*fc2
    swiglu_k<<<(MROWS*NHID)/(4*256), 256>>>(fc1, fc2);
    // out = x1 + fc1 @ Wmlp_proj
    sgemm_k<true><<<dim3(NEMBD/128, MROWS/128), 256>>>(fc1, Wmp, x1, out, MROWS, NEMBD, NHID);
}

// round 3
// speedup vs baseline: 1.4941x; 1.4941x over previous
#include <cuda_runtime.h>
#include <cstdint>

// ---------------- problem constants ----------------
#define BATCH   2
#define TSEQ    2048
#define NEMBD   1024
#define NHEAD   16
#define HEADD   64
#define NHID    2816
#define MROWS   (BATCH*TSEQ)          // 4096
#define QKVC    (3*NEMBD)             // 3072

// ---------------- scratch (no allocations allowed) ----------------
#define OFF_H    0u
#define OFF_QKV  4194304u
#define OFF_Y    16777216u
#define OFF_X1   20971520u
#define OFF_H2   25165824u
#define OFF_FC1  29360128u
#define OFF_FC2  40894464u
#define OFF_TRIG 52428800u
#define BUF_TOTAL 52559872u

__device__ float g_buf[BUF_TOTAL];

// ---------------- packed f32x2 helpers (sm_100+ FFMA2 path) ----------------
__device__ __forceinline__ void fma2(unsigned long long& d,
                                     unsigned long long a,
                                     unsigned long long b) {
    asm("fma.rn.f32x2 %0, %1, %2, %0;" : "+l"(d) : "l"(a), "l"(b));
}
__device__ __forceinline__ void mul2(unsigned long long& d,
                                     unsigned long long a,
                                     unsigned long long b) {
    asm("mul.rn.f32x2 %0, %1, %2;" : "=l"(d) : "l"(a), "l"(b));
}
__device__ __forceinline__ unsigned long long pk(float x, float y) {
    unsigned long long r;
    asm("mov.b64 %0, {%1, %2};" : "=l"(r) : "f"(x), "f"(y));
    return r;
}
__device__ __forceinline__ float2 upk(unsigned long long v) {
    float2 r;
    asm("mov.b64 {%0, %1}, %2;" : "=f"(r.x), "=f"(r.y) : "l"(v));
    return r;
}

// ---------------- RoPE trig table (fp64 arg reduction) ----------------
__global__ void trig_k(float* __restrict__ trig) {
    int i = blockIdx.x * blockDim.x + threadIdx.x;  // 65536 = 2048*32
    int pair = i & 31;
    int t    = i >> 5;
    double theta = pow(10000.0, -(double)pair / 32.0);
    double ang   = fmod((double)t * theta, 6.283185307179586);
    trig[i]         = (float)cos(ang);
    trig[65536 + i] = (float)sin(ang);
}

// ---------------- RMSNorm ----------------
__global__ void rmsnorm_k(const float* __restrict__ x,
                          const float* __restrict__ scale,
                          float* __restrict__ out) {
    int row = blockIdx.x;
    int tid = threadIdx.x;
    const float4* xr = (const float4*)(x + (size_t)row * NEMBD);
    float4 v = xr[tid];
    float ss = v.x*v.x + v.y*v.y + v.z*v.z + v.w*v.w;
    #pragma unroll
    for (int o = 16; o > 0; o >>= 1) ss += __shfl_xor_sync(0xffffffffu, ss, o);
    __shared__ float red[8];
    __shared__ float stot;
    if ((tid & 31) == 0) red[tid >> 5] = ss;
    __syncthreads();
    if (tid == 0) {
        float t = 0.f;
        #pragma unroll
        for (int i = 0; i < 8; i++) t += red[i];
        stot = rsqrtf(t * (1.0f/NEMBD) + 1e-5f);
    }
    __syncthreads();
    float rs = stot;
    float4 s4 = ((const float4*)scale)[tid];
    float4 o4;
    o4.x = v.x * rs * s4.x;
    o4.y = v.y * rs * s4.y;
    o4.z = v.z * rs * s4.z;
    o4.w = v.w * rs * s4.w;
    ((float4*)(out + (size_t)row * NEMBD))[tid] = o4;
}

// ---------------- SGEMM, FFMA2 + double buffer ----------------
// BM=BN=128, BK=16, 256 threads, 8x8 per thread (as 8x4 f32x2 pairs).
// A tile stored DUPLICATED in smem (float2(a,a)) so packed A operands come
// straight from broadcast LDS.128 with no pack instructions in the hot loop.
template<bool RES>
__global__ __launch_bounds__(256, 2)
void sgemm_k(const float* __restrict__ A, const float* __restrict__ B,
             const float* __restrict__ res, float* __restrict__ C,
             int M, int N, int K) {
    __shared__ float2 As2[2][16][128];   // 32 KB
    __shared__ float  Bs [2][16][128];   // 16 KB  (total 48 KB)

    int tid = threadIdx.x;
    int bm = blockIdx.y * 128;
    int bn = blockIdx.x * 128;

    int arow  = tid >> 1;            // 0..127
    int acol8 = (tid & 1) * 8;       // 0 or 8
    int brow  = tid >> 4;            // 0..15
    int bcol8 = (tid & 15) * 8;      // 0..120

    int tr = (tid >> 4) * 8;         // 0..120
    int tc = (tid & 15) * 8;

    unsigned long long acc2[8][4];
    #pragma unroll
    for (int i = 0; i < 8; i++)
        #pragma unroll
        for (int j = 0; j < 4; j++) acc2[i][j] = 0ULL;

    const float* Ap = A + (size_t)(bm + arow) * K + acol8;
    const float* Bp = B + (size_t)brow * N + bn + bcol8;

    float4 a0, a1, b0, b1;
    // prologue: tile 0
    a0 = *(const float4*)(Ap);
    a1 = *(const float4*)(Ap + 4);
    b0 = *(const float4*)(Bp);
    b1 = *(const float4*)(Bp + 4);
    {
        float av[8] = {a0.x,a0.y,a0.z,a0.w,a1.x,a1.y,a1.z,a1.w};
        #pragma unroll
        for (int j = 0; j < 8; j++) As2[0][acol8+j][arow] = make_float2(av[j], av[j]);
        *(float4*)(&Bs[0][brow][bcol8])   = b0;
        *(float4*)(&Bs[0][brow][bcol8+4]) = b1;
    }
    __syncthreads();

    int nIt = K >> 4;
    for (int it = 0; it < nIt; it++) {
        int cur = it & 1;
        bool more = (it + 1 < nIt);
        if (more) {
            const float* Ag = Ap + (it + 1) * 16;
            const float* Bg = Bp + (size_t)(it + 1) * 16 * N;
            a0 = *(const float4*)(Ag);
            a1 = *(const float4*)(Ag + 4);
            b0 = *(const float4*)(Bg);
            b1 = *(const float4*)(Bg + 4);
        }
        #pragma unroll
        for (int k = 0; k < 16; k++) {
            unsigned long long a2[8], bb[4];
            ulonglong2 t;
            t = *(const ulonglong2*)(&As2[cur][k][tr  ]); a2[0]=t.x; a2[1]=t.y;
            t = *(const ulonglong2*)(&As2[cur][k][tr+2]); a2[2]=t.x; a2[3]=t.y;
            t = *(const ulonglong2*)(&As2[cur][k][tr+4]); a2[4]=t.x; a2[5]=t.y;
            t = *(const ulonglong2*)(&As2[cur][k][tr+6]); a2[6]=t.x; a2[7]=t.y;
            t = *(const ulonglong2*)(&Bs[cur][k][tc  ]);  bb[0]=t.x; bb[1]=t.y;
            t = *(const ulonglong2*)(&Bs[cur][k][tc+4]);  bb[2]=t.x; bb[3]=t.y;
            #pragma unroll
            for (int i = 0; i < 8; i++)
                #pragma unroll
                for (int j = 0; j < 4; j++)
                    fma2(acc2[i][j], a2[i], bb[j]);
        }
        if (more) {
            int nxt = cur ^ 1;
            float av[8] = {a0.x,a0.y,a0.z,a0.w,a1.x,a1.y,a1.z,a1.w};
            #pragma unroll
            for (int j = 0; j < 8; j++) As2[nxt][acol8+j][arow] = make_float2(av[j], av[j]);
            *(float4*)(&Bs[nxt][brow][bcol8])   = b0;
            *(float4*)(&Bs[nxt][brow][bcol8+4]) = b1;
            __syncthreads();
        }
    }

    #pragma unroll
    for (int i = 0; i < 8; i++) {
        size_t ro = (size_t)(bm + tr + i) * N + bn + tc;
        float o[8];
        #pragma unroll
        for (int j = 0; j < 4; j++) {
            float2 f = upk(acc2[i][j]);
            o[2*j] = f.x; o[2*j+1] = f.y;
        }
        if (RES) {
            float4 r0 = *(const float4*)(res + ro);
            float4 r1 = *(const float4*)(res + ro + 4);
            o[0]+=r0.x; o[1]+=r0.y; o[2]+=r0.z; o[3]+=r0.w;
            o[4]+=r1.x; o[5]+=r1.y; o[6]+=r1.z; o[7]+=r1.w;
        }
        *(float4*)(C + ro)     = make_float4(o[0],o[1],o[2],o[3]);
        *(float4*)(C + ro + 4) = make_float4(o[4],o[5],o[6],o[7]);
    }
}

// ---------------- RoPE ----------------
__global__ void rope_k(float* __restrict__ qkv, const float* __restrict__ trig) {
    int idx = blockIdx.x * blockDim.x + threadIdx.x;
    int pair = idx & 31;
    int h    = (idx >> 5) & 15;
    int slot = (idx >> 9) & 1;
    int m    = idx >> 10;
    int t    = m & (TSEQ - 1);
    float c = trig[t * 32 + pair];
    float s = trig[65536 + t * 32 + pair];
    size_t base = (size_t)m * QKVC + (size_t)slot * NEMBD + h * HEADD + 2*pair;
    float xe = qkv[base], xo = qkv[base+1];
    qkv[base]   = xe*c - xo*s;
    qkv[base+1] = xe*s + xo*c;
}

// ---------------- Flash attention, FFMA2 inner loops ----------------
__global__ __launch_bounds__(128)
void attn_k(const float* __restrict__ qkv, const int* __restrict__ y_mask,
            float* __restrict__ y) {
    int qt = blockIdx.x, h = blockIdx.y, b = blockIdx.z;
    int r  = threadIdx.x;
    int qi = qt * 128 + r;

    __shared__ float Ks[64][64];
    __shared__ float Vs[64][64];
    __shared__ int   ymS[64];

    const float* base = qkv + (size_t)b * TSEQ * QKVC;

    unsigned long long q2[32];
    {
        const float4* qp = (const float4*)(base + (size_t)qi * QKVC + h * HEADD);
        #pragma unroll
        for (int d4 = 0; d4 < 16; d4++) {
            float4 t4 = qp[d4];
            q2[2*d4]   = pk(t4.x, t4.y);
            q2[2*d4+1] = pk(t4.z, t4.w);
        }
    }
    if (r < 64) ymS[r] = y_mask[b * 64 + r];
    bool ymq = (qi < 64) && (y_mask[b * 64 + qi] != 0);

    unsigned long long o2[32];
    #pragma unroll
    for (int d = 0; d < 32; d++) o2[d] = 0ULL;
    float mrun = -1e30f, l = 0.f;

    int nkv = 2*qt + 2;
    for (int kt = 0; kt < nkv; kt++) {
        for (int i = r; i < 64*16; i += 128) {
            int row = i >> 4;
            int c4  = (i & 15) << 2;
            const float* kp = base + (size_t)(kt*64 + row) * QKVC + NEMBD   + h*HEADD + c4;
            const float* vp = base + (size_t)(kt*64 + row) * QKVC + 2*NEMBD + h*HEADD + c4;
            *(float4*)(&Ks[row][c4]) = *(const float4*)kp;
            *(float4*)(&Vs[row][c4]) = *(const float4*)vp;
        }
        __syncthreads();

        for (int jc = 0; jc < 4; jc++) {
            float sc[16];
            #pragma unroll
            for (int jj = 0; jj < 16; jj++) {
                int j = jc*16 + jj;
                const ulonglong2* kr = (const ulonglong2*)(&Ks[j][0]);
                unsigned long long sA = 0ULL, sB = 0ULL;
                #pragma unroll
                for (int p = 0; p < 16; p++) {
                    ulonglong2 kv = kr[p];
                    fma2(sA, q2[2*p],   kv.x);
                    fma2(sB, q2[2*p+1], kv.y);
                }
                float2 fa = upk(sA), fb = upk(sB);
                float s = (fa.x + fa.y) + (fb.x + fb.y);
                int kj = kt*64 + j;
                bool ok = (kj <= qi) || (ymq && kj < 64 && ymS[kj] != 0);
                sc[jj] = ok ? s * 0.125f : -1e30f;
            }
            float tmax = sc[0];
            #pragma unroll
            for (int jj = 1; jj < 16; jj++) tmax = fmaxf(tmax, sc[jj]);
            float mnew = fmaxf(mrun, tmax);
            float corr = __expf(mrun - mnew);
            l *= corr;
            unsigned long long c2 = pk(corr, corr);
            #pragma unroll
            for (int d = 0; d < 32; d++) mul2(o2[d], o2[d], c2);
            #pragma unroll
            for (int jj = 0; jj < 16; jj++) {
                sc[jj] = __expf(sc[jj] - mnew);
                l += sc[jj];
            }
            #pragma unroll
            for (int jj = 0; jj < 16; jj++) {
                int j = jc*16 + jj;
                unsigned long long pp = pk(sc[jj], sc[jj]);
                const ulonglong2* vr = (const ulonglong2*)(&Vs[j][0]);
                #pragma unroll
                for (int p = 0; p < 16; p++) {
                    ulonglong2 vv = vr[p];
                    fma2(o2[2*p],   pp, vv.x);
                    fma2(o2[2*p+1], pp, vv.y);
                }
            }
            mrun = mnew;
        }
        __syncthreads();
    }

    float inv = 1.0f / l;
    unsigned long long i2 = pk(inv, inv);
    float* yp = y + (size_t)(b * TSEQ + qi) * NEMBD + h * HEADD;
    #pragma unroll
    for (int d4 = 0; d4 < 16; d4++) {
        unsigned long long r0, r1;
        mul2(r0, o2[2*d4],   i2);
        mul2(r1, o2[2*d4+1], i2);
        float2 f0 = upk(r0), f1 = upk(r1);
        ((float4*)yp)[d4] = make_float4(f0.x, f0.y, f1.x, f1.y);
    }
}

// ---------------- SwiGLU ----------------
__global__ void swiglu_k(float* __restrict__ a, const float* __restrict__ b) {
    int idx = blockIdx.x * blockDim.x + threadIdx.x;
    float4 av = ((const float4*)a)[idx];
    float4 bv = ((const float4*)b)[idx];
    float4 ov;
    ov.x = av.x / (1.f + __expf(-av.x)) * bv.x;
    ov.y = av.y / (1.f + __expf(-av.y)) * bv.y;
    ov.z = av.z / (1.f + __expf(-av.z)) * bv.z;
    ov.w = av.w / (1.f + __expf(-av.w)) * bv.w;
    ((float4*)a)[idx] = ov;
}

// ---------------- launch ----------------
extern "C" void kernel_launch(void* const* d_in, const int* in_sizes, int n_in,
                              void* d_out, int out_size) {
    const float* x    = (const float*)d_in[0];
    const int*   ym   = (const int*)  d_in[1];
    const float* Wqkv = (const float*)d_in[2];
    const float* Wap  = (const float*)d_in[3];
    const float* s1   = (const float*)d_in[4];
    const float* s2   = (const float*)d_in[5];
    const float* Wfc1 = (const float*)d_in[6];
    const float* Wfc2 = (const float*)d_in[7];
    const float* Wmp  = (const float*)d_in[8];
    float* out = (float*)d_out;

    float* buf = nullptr;
    cudaGetSymbolAddress((void**)&buf, g_buf);
    float* h    = buf + OFF_H;
    float* qkv  = buf + OFF_QKV;
    float* y    = buf + OFF_Y;
    float* x1   = buf + OFF_X1;
    float* h2   = buf + OFF_H2;
    float* fc1  = buf + OFF_FC1;
    float* fc2  = buf + OFF_FC2;
    float* trig = buf + OFF_TRIG;

    trig_k<<<65536/256, 256>>>(trig);
    rmsnorm_k<<<MROWS, 256>>>(x, s1, h);
    sgemm_k<false><<<dim3(QKVC/128, MROWS/128), 256>>>(h, Wqkv, nullptr, qkv, MROWS, QKVC, NEMBD);
    rope_k<<<(MROWS*2*NEMBD/(2*256)), 256>>>(qkv, trig);
    attn_k<<<dim3(TSEQ/128, NHEAD, BATCH), 128>>>(qkv, ym, y);
    sgemm_k<true><<<dim3(NEMBD/128, MROWS/128), 256>>>(y, Wap, x, x1, MROWS, NEMBD, NEMBD);
    rmsnorm_k<<<MROWS, 256>>>(x1, s2, h2);
    sgemm_k<false><<<dim3(NHID/128, MROWS/128), 256>>>(h2, Wfc1, nullptr, fc1, MROWS, NHID, NEMBD);
    sgemm_k<false><<<dim3(NHID/128, MROWS/128), 256>>>(h2, Wfc2, nullptr, fc2, MROWS, NHID, NEMBD);
    swiglu_k<<<(MROWS*NHID)/(4*256), 256>>>(fc1, fc2);
    sgemm_k<true><<<dim3(NEMBD/128, MROWS/128), 256>>>(fc1, Wmp, x1, out, MROWS, NEMBD, NHID);
}

// round 6
// speedup vs baseline: 2.6379x; 1.7656x over previous
#include <cuda_runtime.h>
#include <cuda_bf16.h>
#include <cstdint>

// ---------------- problem constants ----------------
#define BATCH   2
#define TSEQ    2048
#define NEMBD   1024
#define NHEAD   16
#define HEADD   64
#define NHID    2816
#define MROWS   (BATCH*TSEQ)          // 4096
#define QKVC    (3*NEMBD)             // 3072

// ---------------- static scratch (no allocations allowed) ----------------
__device__ float d_qkv[MROWS*QKVC];
__device__ float d_x1 [MROWS*NEMBD];
__device__ float d_fc1[MROWS*NHID];
__device__ float d_fc2[MROWS*NHID];
__device__ float d_trig[131072];

__device__ __nv_bfloat16 d_ah [MROWS*NEMBD],  d_al [MROWS*NEMBD];
__device__ __nv_bfloat16 d_yh [MROWS*NEMBD],  d_yl [MROWS*NEMBD];
__device__ __nv_bfloat16 d_h2h[MROWS*NEMBD],  d_h2l[MROWS*NEMBD];
__device__ __nv_bfloat16 d_gh [MROWS*NHID],   d_gl [MROWS*NHID];
__device__ __nv_bfloat16 d_wqkvh[QKVC*NEMBD], d_wqkvl[QKVC*NEMBD];
__device__ __nv_bfloat16 d_waph [NEMBD*NEMBD],d_wapl [NEMBD*NEMBD];
__device__ __nv_bfloat16 d_wf1h [NHID*NEMBD], d_wf1l [NHID*NEMBD];
__device__ __nv_bfloat16 d_wf2h [NHID*NEMBD], d_wf2l [NHID*NEMBD];
__device__ __nv_bfloat16 d_wmph [NEMBD*NHID], d_wmpl [NEMBD*NHID];

// ---------------- helpers ----------------
__device__ __forceinline__ uint32_t smem_to_u32(const void* p) {
    uint32_t a;
    asm("{ .reg .u64 t; cvta.to.shared.u64 t, %1; cvt.u32.u64 %0, t; }" : "=r"(a) : "l"(p));
    return a;
}
__device__ __forceinline__ void ldsm4(uint32_t r[4], uint32_t addr) {
    asm volatile("ldmatrix.sync.aligned.m8n8.x4.shared.b16 {%0,%1,%2,%3}, [%4];"
        : "=r"(r[0]), "=r"(r[1]), "=r"(r[2]), "=r"(r[3]) : "r"(addr));
}
__device__ __forceinline__ void mma16816(float c[4], const uint32_t a[4],
                                         uint32_t b0, uint32_t b1) {
    asm volatile("mma.sync.aligned.m16n8k16.row.col.f32.bf16.bf16.f32 "
        "{%0,%1,%2,%3}, {%4,%5,%6,%7}, {%8,%9}, {%0,%1,%2,%3};"
        : "+f"(c[0]), "+f"(c[1]), "+f"(c[2]), "+f"(c[3])
        : "r"(a[0]), "r"(a[1]), "r"(a[2]), "r"(a[3]), "r"(b0), "r"(b1));
}
// packed f32x2
__device__ __forceinline__ void fma2(unsigned long long& d, unsigned long long a, unsigned long long b) {
    asm("fma.rn.f32x2 %0, %1, %2, %0;" : "+l"(d) : "l"(a), "l"(b));
}
__device__ __forceinline__ void mul2(unsigned long long& d, unsigned long long a, unsigned long long b) {
    asm("mul.rn.f32x2 %0, %1, %2;" : "=l"(d) : "l"(a), "l"(b));
}
__device__ __forceinline__ unsigned long long pk(float x, float y) {
    unsigned long long r;
    asm("mov.b64 %0, {%1, %2};" : "=l"(r) : "f"(x), "f"(y));
    return r;
}
__device__ __forceinline__ float2 upk(unsigned long long v) {
    float2 r;
    asm("mov.b64 {%0, %1}, %2;" : "=f"(r.x), "=f"(r.y) : "l"(v));
    return r;
}

// ---------------- trig table (fp64 arg reduction) ----------------
__global__ void trig_k(float* __restrict__ trig) {
    int i = blockIdx.x * blockDim.x + threadIdx.x;
    int pair = i & 31;
    int t    = i >> 5;
    double theta = pow(10000.0, -(double)pair / 32.0);
    double ang   = fmod((double)t * theta, 6.283185307179586);
    trig[i]         = (float)cos(ang);
    trig[65536 + i] = (float)sin(ang);
}

// ---------------- RMSNorm + bf16 split ----------------
__global__ void rmsnorm_split_k(const float* __restrict__ x, const float* __restrict__ scale,
                                __nv_bfloat16* __restrict__ oh, __nv_bfloat16* __restrict__ ol) {
    int row = blockIdx.x;
    int tid = threadIdx.x;
    const float4* xr = (const float4*)(x + (size_t)row * NEMBD);
    float4 v = xr[tid];
    float ss = v.x*v.x + v.y*v.y + v.z*v.z + v.w*v.w;
    #pragma unroll
    for (int o = 16; o > 0; o >>= 1) ss += __shfl_xor_sync(0xffffffffu, ss, o);
    __shared__ float red[8];
    __shared__ float stot;
    if ((tid & 31) == 0) red[tid >> 5] = ss;
    __syncthreads();
    if (tid == 0) {
        float t = 0.f;
        #pragma unroll
        for (int i = 0; i < 8; i++) t += red[i];
        stot = rsqrtf(t * (1.0f/NEMBD) + 1e-5f);
    }
    __syncthreads();
    float rs = stot;
    float4 s4 = ((const float4*)scale)[tid];
    float o0 = v.x*rs*s4.x, o1 = v.y*rs*s4.y, o2 = v.z*rs*s4.z, o3 = v.w*rs*s4.w;
    __nv_bfloat16 h0 = __float2bfloat16(o0), h1 = __float2bfloat16(o1);
    __nv_bfloat16 h2 = __float2bfloat16(o2), h3 = __float2bfloat16(o3);
    size_t off = (size_t)row * NEMBD + tid*4;
    *(__nv_bfloat162*)(oh + off)     = __nv_bfloat162(h0, h1);
    *(__nv_bfloat162*)(oh + off + 2) = __nv_bfloat162(h2, h3);
    *(__nv_bfloat162*)(ol + off)     = __nv_bfloat162(__float2bfloat16(o0 - __bfloat162float(h0)),
                                                      __float2bfloat16(o1 - __bfloat162float(h1)));
    *(__nv_bfloat162*)(ol + off + 2) = __nv_bfloat162(__float2bfloat16(o2 - __bfloat162float(h2)),
                                                      __float2bfloat16(o3 - __bfloat162float(h3)));
}

// ---------------- weight transpose + split: W[K,N] -> Wt_hi/lo[N,K] ----------------
__global__ void wprep_k(const float* __restrict__ W, __nv_bfloat16* __restrict__ Th,
                        __nv_bfloat16* __restrict__ Tl, int K, int N) {
    __shared__ float s[32][33];
    int n0 = blockIdx.x * 32, k0 = blockIdx.y * 32;
    int c = threadIdx.x & 31, r0 = threadIdx.x >> 5;
    #pragma unroll
    for (int i = 0; i < 4; i++) {
        int r = r0 + i*8;
        s[r][c] = W[(size_t)(k0 + r) * N + n0 + c];
    }
    __syncthreads();
    #pragma unroll
    for (int i = 0; i < 4; i++) {
        int r = r0 + i*8;
        float v = s[c][r];
        __nv_bfloat16 h = __float2bfloat16(v);
        Th[(size_t)(n0 + r) * K + k0 + c] = h;
        Tl[(size_t)(n0 + r) * K + k0 + c] = __float2bfloat16(v - __bfloat162float(h));
    }
}

// ---------------- HMMA GEMM: C[M,N] = (Ah+Al)[M,K] @ (Bh+Bl)[N,K]^T (+res) --------
// 3-product bf16 split accumulated in the same fp32 acc registers.
// BM=BN=128, BK=32, 8 warps (2x4), warp tile 64x32, mma.m16n8k16, cp.async 2-stage.
#define PADK    40
#define TILE_B  (128*PADK*2)       // 10240 B
#define STAGE_B (4*TILE_B)         // 40960 B
#define GSMEM_B (2*STAGE_B)        // 81920 B

#define LOAD_STAGE(kt, s) do {                                                      \
    int _kof = (kt) * 32;                                                           \
    _Pragma("unroll")                                                               \
    for (int _i = 0; _i < 8; _i++) {                                                \
        int _id   = _i * 256 + tid;                                                 \
        int _tile = _id >> 9;                                                       \
        int _row  = (_id >> 2) & 127;                                               \
        int _ch   = _id & 3;                                                        \
        const __nv_bfloat16* _g =                                                   \
            (_tile == 0 ? gA0 : _tile == 1 ? gA1 : _tile == 2 ? gB0 : gB1)          \
            + (size_t)_row * K + _kof + _ch * 8;                                    \
        uint32_t _sa = sb + (uint32_t)(s) * STAGE_B + (uint32_t)_tile * TILE_B      \
                     + (uint32_t)(_row * PADK + _ch * 8) * 2u;                      \
        asm volatile("cp.async.cg.shared.global [%0], [%1], 16;" :: "r"(_sa), "l"(_g)); \
    }                                                                               \
    asm volatile("cp.async.commit_group;" ::: "memory");                            \
} while (0)

template<bool RES>
__global__ __launch_bounds__(256)
void hgemm_k(const __nv_bfloat16* __restrict__ Ah, const __nv_bfloat16* __restrict__ Al,
             const __nv_bfloat16* __restrict__ Bh, const __nv_bfloat16* __restrict__ Bl,
             const float* __restrict__ res, float* __restrict__ C, int N, int K) {
    extern __shared__ char smem[];
    uint32_t sb = smem_to_u32(smem);
    int tid  = threadIdx.x;
    int warp = tid >> 5, lane = tid & 31;
    int bm = blockIdx.y * 128, bn = blockIdx.x * 128;
    int wm = (warp & 1) * 64, wn = (warp >> 1) * 32;

    const __nv_bfloat16* gA0 = Ah + (size_t)bm * K;
    const __nv_bfloat16* gA1 = Al + (size_t)bm * K;
    const __nv_bfloat16* gB0 = Bh + (size_t)bn * K;
    const __nv_bfloat16* gB1 = Bl + (size_t)bn * K;

    float acc[4][4][4];
    #pragma unroll
    for (int a = 0; a < 4; a++)
        #pragma unroll
        for (int b = 0; b < 4; b++)
            #pragma unroll
            for (int c = 0; c < 4; c++) acc[a][b][c] = 0.f;

    int nkt = K >> 5;
    LOAD_STAGE(0, 0);
    for (int it = 0; it < nkt; it++) {
        int s = it & 1;
        if (it + 1 < nkt) {
            LOAD_STAGE(it + 1, s ^ 1);
            asm volatile("cp.async.wait_group 1;" ::: "memory");
        } else {
            asm volatile("cp.async.wait_group 0;" ::: "memory");
        }
        __syncthreads();
        uint32_t stb = sb + (uint32_t)s * STAGE_B;
        #pragma unroll
        for (int ks = 0; ks < 2; ks++) {
            #pragma unroll
            for (int p = 0; p < 3; p++) {
                uint32_t aT = stb + (p == 2 ? (uint32_t)TILE_B : 0u);
                uint32_t bT = stb + 2u*TILE_B + (p == 1 ? (uint32_t)TILE_B : 0u);
                uint32_t ar[4][4];
                #pragma unroll
                for (int mi = 0; mi < 4; mi++)
                    ldsm4(ar[mi], aT + (uint32_t)(((wm + mi*16 + (lane & 15)) * PADK)
                                                  + ks*16 + (lane >> 4) * 8) * 2u);
                uint32_t br[2][4];
                #pragma unroll
                for (int nq = 0; nq < 2; nq++)
                    ldsm4(br[nq], bT + (uint32_t)(((wn + nq*16 + (lane & 15)) * PADK)
                                                  + ks*16 + (lane >> 4) * 8) * 2u);
                #pragma unroll
                for (int mi = 0; mi < 4; mi++)
                    #pragma unroll
                    for (int j = 0; j < 4; j++)
                        mma16816(acc[mi][j], ar[mi], br[j >> 1][j & 1], br[j >> 1][(j & 1) + 2]);
            }
        }
        __syncthreads();
    }

    int r0 = lane >> 2, c0 = (lane & 3) * 2;
    #pragma unroll
    for (int mi = 0; mi < 4; mi++) {
        int gr = bm + wm + mi*16 + r0;
        #pragma unroll
        for (int j = 0; j < 4; j++) {
            int gc = bn + wn + j*8 + c0;
            size_t o1 = (size_t)gr * N + gc;
            size_t o2 = (size_t)(gr + 8) * N + gc;
            float2 v1 = make_float2(acc[mi][j][0], acc[mi][j][1]);
            float2 v2 = make_float2(acc[mi][j][2], acc[mi][j][3]);
            if (RES) {
                float2 rr = *(const float2*)(res + o1); v1.x += rr.x; v1.y += rr.y;
                float2 r2 = *(const float2*)(res + o2); v2.x += r2.x; v2.y += r2.y;
            }
            *(float2*)(C + o1) = v1;
            *(float2*)(C + o2) = v2;
        }
    }
}

// ---------------- RoPE ----------------
__global__ void rope_k(float* __restrict__ qkv, const float* __restrict__ trig) {
    int idx = blockIdx.x * blockDim.x + threadIdx.x;
    int pair = idx & 31;
    int h    = (idx >> 5) & 15;
    int slot = (idx >> 9) & 1;
    int m    = idx >> 10;
    int t    = m & (TSEQ - 1);
    float c = trig[t * 32 + pair];
    float s = trig[65536 + t * 32 + pair];
    size_t base = (size_t)m * QKVC + (size_t)slot * NEMBD + h * HEADD + 2*pair;
    float xe = qkv[base], xo = qkv[base+1];
    qkv[base]   = xe*c - xo*s;
    qkv[base+1] = xe*s + xo*c;
}

// ---------------- Flash attention (fp32 FFMA2), writes split-bf16 y --------------
__global__ __launch_bounds__(128)
void attn_k(const float* __restrict__ qkv, const int* __restrict__ y_mask,
            __nv_bfloat16* __restrict__ yh, __nv_bfloat16* __restrict__ yl) {
    int qt = blockIdx.x, h = blockIdx.y, b = blockIdx.z;
    int r  = threadIdx.x;
    int qi = qt * 128 + r;

    __shared__ float Ks[64][64];
    __shared__ float Vs[64][64];
    __shared__ int   ymS[64];

    const float* base = qkv + (size_t)b * TSEQ * QKVC;

    unsigned long long q2[32];
    {
        const float4* qp = (const float4*)(base + (size_t)qi * QKVC + h * HEADD);
        #pragma unroll
        for (int d4 = 0; d4 < 16; d4++) {
            float4 t4 = qp[d4];
            q2[2*d4]   = pk(t4.x, t4.y);
            q2[2*d4+1] = pk(t4.z, t4.w);
        }
    }
    if (r < 64) ymS[r] = y_mask[b * 64 + r];
    bool ymq = (qi < 64) && (y_mask[b * 64 + qi] != 0);

    unsigned long long o2[32];
    #pragma unroll
    for (int d = 0; d < 32; d++) o2[d] = 0ULL;
    float mrun = -1e30f, l = 0.f;

    int nkv = 2*qt + 2;
    for (int kt = 0; kt < nkv; kt++) {
        for (int i = r; i < 64*16; i += 128) {
            int row = i >> 4;
            int c4  = (i & 15) << 2;
            const float* kp = base + (size_t)(kt*64 + row) * QKVC + NEMBD   + h*HEADD + c4;
            const float* vp = base + (size_t)(kt*64 + row) * QKVC + 2*NEMBD + h*HEADD + c4;
            *(float4*)(&Ks[row][c4]) = *(const float4*)kp;
            *(float4*)(&Vs[row][c4]) = *(const float4*)vp;
        }
        __syncthreads();

        for (int jc = 0; jc < 4; jc++) {
            float sc[16];
            #pragma unroll
            for (int jj = 0; jj < 16; jj++) {
                int j = jc*16 + jj;
                const ulonglong2* kr = (const ulonglong2*)(&Ks[j][0]);
                unsigned long long sA = 0ULL, sB = 0ULL;
                #pragma unroll
                for (int p = 0; p < 16; p++) {
                    ulonglong2 kv = kr[p];
                    fma2(sA, q2[2*p],   kv.x);
                    fma2(sB, q2[2*p+1], kv.y);
                }
                float2 fa = upk(sA), fb = upk(sB);
                float s = (fa.x + fa.y) + (fb.x + fb.y);
                int kj = kt*64 + j;
                bool ok = (kj <= qi) || (ymq && kj < 64 && ymS[kj] != 0);
                sc[jj] = ok ? s * 0.125f : -1e30f;
            }
            float tmax = sc[0];
            #pragma unroll
            for (int jj = 1; jj < 16; jj++) tmax = fmaxf(tmax, sc[jj]);
            float mnew = fmaxf(mrun, tmax);
            float corr = __expf(mrun - mnew);
            l *= corr;
            unsigned long long c2 = pk(corr, corr);
            #pragma unroll
            for (int d = 0; d < 32; d++) mul2(o2[d], o2[d], c2);
            #pragma unroll
            for (int jj = 0; jj < 16; jj++) {
                sc[jj] = __expf(sc[jj] - mnew);
                l += sc[jj];
            }
            #pragma unroll
            for (int jj = 0; jj < 16; jj++) {
                int j = jc*16 + jj;
                unsigned long long pp = pk(sc[jj], sc[jj]);
                const ulonglong2* vr = (const ulonglong2*)(&Vs[j][0]);
                #pragma unroll
                for (int p = 0; p < 16; p++) {
                    ulonglong2 vv = vr[p];
                    fma2(o2[2*p],   pp, vv.x);
                    fma2(o2[2*p+1], pp, vv.y);
                }
            }
            mrun = mnew;
        }
        __syncthreads();
    }

    float inv = 1.0f / l;
    size_t yo = (size_t)(b * TSEQ + qi) * NEMBD + h * HEADD;
    #pragma unroll
    for (int d4 = 0; d4 < 16; d4++) {
        float2 f0 = upk(o2[2*d4]), f1 = upk(o2[2*d4+1]);
        float v0 = f0.x*inv, v1 = f0.y*inv, v2 = f1.x*inv, v3 = f1.y*inv;
        __nv_bfloat16 h0 = __float2bfloat16(v0), h1 = __float2bfloat16(v1);
        __nv_bfloat16 h2 = __float2bfloat16(v2), h3 = __float2bfloat16(v3);
        *(__nv_bfloat162*)(yh + yo + d4*4)     = __nv_bfloat162(h0, h1);
        *(__nv_bfloat162*)(yh + yo + d4*4 + 2) = __nv_bfloat162(h2, h3);
        *(__nv_bfloat162*)(yl + yo + d4*4)     = __nv_bfloat162(__float2bfloat16(v0 - __bfloat162float(h0)),
                                                                __float2bfloat16(v1 - __bfloat162float(h1)));
        *(__nv_bfloat162*)(yl + yo + d4*4 + 2) = __nv_bfloat162(__float2bfloat16(v2 - __bfloat162float(h2)),
                                                                __float2bfloat16(v3 - __bfloat162float(h3)));
    }
}

// ---------------- SwiGLU + bf16 split ----------------
__global__ void swiglu_split_k(const float* __restrict__ a, const float* __restrict__ b,
                               __nv_bfloat16* __restrict__ gh, __nv_bfloat16* __restrict__ gl) {
    int idx = blockIdx.x * blockDim.x + threadIdx.x;
    float4 av = ((const float4*)a)[idx];
    float4 bv = ((const float4*)b)[idx];
    float v0 = av.x / (1.f + __expf(-av.x)) * bv.x;
    float v1 = av.y / (1.f + __expf(-av.y)) * bv.y;
    float v2 = av.z / (1.f + __expf(-av.z)) * bv.z;
    float v3 = av.w / (1.f + __expf(-av.w)) * bv.w;
    __nv_bfloat16 h0 = __float2bfloat16(v0), h1 = __float2bfloat16(v1);
    __nv_bfloat16 h2 = __float2bfloat16(v2), h3 = __float2bfloat16(v3);
    size_t off = (size_t)idx * 4;
    *(__nv_bfloat162*)(gh + off)     = __nv_bfloat162(h0, h1);
    *(__nv_bfloat162*)(gh + off + 2) = __nv_bfloat162(h2, h3);
    *(__nv_bfloat162*)(gl + off)     = __nv_bfloat162(__float2bfloat16(v0 - __bfloat162float(h0)),
                                                      __float2bfloat16(v1 - __bfloat162float(h1)));
    *(__nv_bfloat162*)(gl + off + 2) = __nv_bfloat162(__float2bfloat16(v2 - __bfloat162float(h2)),
                                                      __float2bfloat16(v3 - __bfloat162float(h3)));
}

// ---------------- launch ----------------
static void* sym(const void* s) { void* p = nullptr; cudaGetSymbolAddress(&p, s); return p; }

extern "C" void kernel_launch(void* const* d_in, const int* in_sizes, int n_in,
                              void* d_out, int out_size) {
    const float* x    = (const float*)d_in[0];
    const int*   ym   = (const int*)  d_in[1];
    const float* Wqkv = (const float*)d_in[2];
    const float* Wap  = (const float*)d_in[3];
    const float* s1   = (const float*)d_in[4];
    const float* s2   = (const float*)d_in[5];
    const float* Wfc1 = (const float*)d_in[6];
    const float* Wfc2 = (const float*)d_in[7];
    const float* Wmp  = (const float*)d_in[8];
    float* out = (float*)d_out;

    float* qkv  = (float*)sym(d_qkv);
    float* x1   = (float*)sym(d_x1);
    float* fc1  = (float*)sym(d_fc1);
    float* fc2  = (float*)sym(d_fc2);
    float* trig = (float*)sym(d_trig);
    __nv_bfloat16* ah  = (__nv_bfloat16*)sym(d_ah);
    __nv_bfloat16* al  = (__nv_bfloat16*)sym(d_al);
    __nv_bfloat16* yh  = (__nv_bfloat16*)sym(d_yh);
    __nv_bfloat16* yl  = (__nv_bfloat16*)sym(d_yl);
    __nv_bfloat16* h2h = (__nv_bfloat16*)sym(d_h2h);
    __nv_bfloat16* h2l = (__nv_bfloat16*)sym(d_h2l);
    __nv_bfloat16* gh  = (__nv_bfloat16*)sym(d_gh);
    __nv_bfloat16* gl  = (__nv_bfloat16*)sym(d_gl);
    __nv_bfloat16* wqh = (__nv_bfloat16*)sym(d_wqkvh);
    __nv_bfloat16* wql = (__nv_bfloat16*)sym(d_wqkvl);
    __nv_bfloat16* wah = (__nv_bfloat16*)sym(d_waph);
    __nv_bfloat16* wal = (__nv_bfloat16*)sym(d_wapl);
    __nv_bfloat16* w1h = (__nv_bfloat16*)sym(d_wf1h);
    __nv_bfloat16* w1l = (__nv_bfloat16*)sym(d_wf1l);
    __nv_bfloat16* w2h = (__nv_bfloat16*)sym(d_wf2h);
    __nv_bfloat16* w2l = (__nv_bfloat16*)sym(d_wf2l);
    __nv_bfloat16* wmh = (__nv_bfloat16*)sym(d_wmph);
    __nv_bfloat16* wml = (__nv_bfloat16*)sym(d_wmpl);

    cudaFuncSetAttribute(hgemm_k<false>, cudaFuncAttributeMaxDynamicSharedMemorySize, GSMEM_B);
    cudaFuncSetAttribute(hgemm_k<true>,  cudaFuncAttributeMaxDynamicSharedMemorySize, GSMEM_B);

    trig_k<<<65536/256, 256>>>(trig);

    // weight prep: transpose + bf16 split
    wprep_k<<<dim3(QKVC/32,  NEMBD/32), 256>>>(Wqkv, wqh, wql, NEMBD, QKVC);
    wprep_k<<<dim3(NEMBD/32, NEMBD/32), 256>>>(Wap,  wah, wal, NEMBD, NEMBD);
    wprep_k<<<dim3(NHID/32,  NEMBD/32), 256>>>(Wfc1, w1h, w1l, NEMBD, NHID);
    wprep_k<<<dim3(NHID/32,  NEMBD/32), 256>>>(Wfc2, w2h, w2l, NEMBD, NHID);
    wprep_k<<<dim3(NEMBD/32, NHID/32),  256>>>(Wmp,  wmh, wml, NHID, NEMBD);

    // h = rmsnorm(x) -> split bf16
    rmsnorm_split_k<<<MROWS, 256>>>(x, s1, ah, al);
    // qkv = h @ Wqkv
    hgemm_k<false><<<dim3(QKVC/128, MROWS/128), 256, GSMEM_B>>>(ah, al, wqh, wql, nullptr, qkv, QKVC, NEMBD);
    // RoPE
    rope_k<<<(MROWS*2*NEMBD/(2*256)), 256>>>(qkv, trig);
    // attention -> split bf16 y
    attn_k<<<dim3(TSEQ/128, NHEAD, BATCH), 128>>>(qkv, ym, yh, yl);
    // x1 = x + y @ Wap
    hgemm_k<true><<<dim3(NEMBD/128, MROWS/128), 256, GSMEM_B>>>(yh, yl, wah, wal, x, x1, NEMBD, NEMBD);
    // h2 = rmsnorm(x1) -> split
    rmsnorm_split_k<<<MROWS, 256>>>(x1, s2, h2h, h2l);
    // fc1 / fc2
    hgemm_k<false><<<dim3(NHID/128, MROWS/128), 256, GSMEM_B>>>(h2h, h2l, w1h, w1l, nullptr, fc1, NHID, NEMBD);
    hgemm_k<false><<<dim3(NHID/128, MROWS/128), 256, GSMEM_B>>>(h2h, h2l, w2h, w2l, nullptr, fc2, NHID, NEMBD);
    // g = silu(fc1)*fc2 -> split
    swiglu_split_k<<<(MROWS*NHID)/(4*256), 256>>>(fc1, fc2, gh, gl);
    // out = x1 + g @ Wmp
    hgemm_k<true><<<dim3(NEMBD/128, MROWS/128), 256, GSMEM_B>>>(gh, gl, wmh, wml, x1, out, NEMBD, NHID);
}

// round 8
// speedup vs baseline: 4.0529x; 1.5364x over previous
#include <cuda_runtime.h>
#include <cuda_bf16.h>
#include <cstdint>

// ---------------- problem constants ----------------
#define BATCH   2
#define TSEQ    2048
#define NEMBD   1024
#define NHEAD   16
#define HEADD   64
#define NHID    2816
#define MROWS   (BATCH*TSEQ)          // 4096
#define QKVC    (3*NEMBD)             // 3072

// ---------------- static scratch (no allocations allowed) ----------------
__device__ float d_qkv[MROWS*QKVC];
__device__ float d_x1 [MROWS*NEMBD];
__device__ float d_fc1[MROWS*NHID];
__device__ float d_fc2[MROWS*NHID];
__device__ float d_trig[131072];

__device__ __nv_bfloat16 d_ah [MROWS*NEMBD],  d_al [MROWS*NEMBD];
__device__ __nv_bfloat16 d_yh [MROWS*NEMBD],  d_yl [MROWS*NEMBD];
__device__ __nv_bfloat16 d_h2h[MROWS*NEMBD],  d_h2l[MROWS*NEMBD];
__device__ __nv_bfloat16 d_gh [MROWS*NHID],   d_gl [MROWS*NHID];
__device__ __nv_bfloat16 d_wqkvh[QKVC*NEMBD], d_wqkvl[QKVC*NEMBD];
__device__ __nv_bfloat16 d_waph [NEMBD*NEMBD],d_wapl [NEMBD*NEMBD];
__device__ __nv_bfloat16 d_wf1h [NHID*NEMBD], d_wf1l [NHID*NEMBD];
__device__ __nv_bfloat16 d_wf2h [NHID*NEMBD], d_wf2l [NHID*NEMBD];
__device__ __nv_bfloat16 d_wmph [NEMBD*NHID], d_wmpl [NEMBD*NHID];

// ---------------- helpers ----------------
__device__ __forceinline__ uint32_t smem_to_u32(const void* p) {
    uint32_t a;
    asm("{ .reg .u64 t; cvta.to.shared.u64 t, %1; cvt.u32.u64 %0, t; }" : "=r"(a) : "l"(p));
    return a;
}
__device__ __forceinline__ void ldsm4(uint32_t r[4], uint32_t addr) {
    asm volatile("ldmatrix.sync.aligned.m8n8.x4.shared.b16 {%0,%1,%2,%3}, [%4];"
        : "=r"(r[0]), "=r"(r[1]), "=r"(r[2]), "=r"(r[3]) : "r"(addr));
}
__device__ __forceinline__ void mma16816(float c[4], const uint32_t a[4],
                                         uint32_t b0, uint32_t b1) {
    asm volatile("mma.sync.aligned.m16n8k16.row.col.f32.bf16.bf16.f32 "
        "{%0,%1,%2,%3}, {%4,%5,%6,%7}, {%8,%9}, {%0,%1,%2,%3};"
        : "+f"(c[0]), "+f"(c[1]), "+f"(c[2]), "+f"(c[3])
        : "r"(a[0]), "r"(a[1]), "r"(a[2]), "r"(a[3]), "r"(b0), "r"(b1));
}
__device__ __forceinline__ void split2(float a, float b, uint32_t& hi, uint32_t& lo) {
    __nv_bfloat16 ha = __float2bfloat16(a), hb = __float2bfloat16(b);
    __nv_bfloat162 hh(ha, hb);
    hi = *(uint32_t*)&hh;
    __nv_bfloat162 ll(__float2bfloat16(a - __bfloat162float(ha)),
                      __float2bfloat16(b - __bfloat162float(hb)));
    lo = *(uint32_t*)&ll;
}

// ---------------- trig table (fp64 arg reduction) ----------------
__global__ void trig_k(float* __restrict__ trig) {
    int i = blockIdx.x * blockDim.x + threadIdx.x;
    int pair = i & 31;
    int t    = i >> 5;
    double theta = pow(10000.0, -(double)pair / 32.0);
    double ang   = fmod((double)t * theta, 6.283185307179586);
    trig[i]         = (float)cos(ang);
    trig[65536 + i] = (float)sin(ang);
}

// ---------------- RMSNorm + bf16 split ----------------
__global__ void rmsnorm_split_k(const float* __restrict__ x, const float* __restrict__ scale,
                                __nv_bfloat16* __restrict__ oh, __nv_bfloat16* __restrict__ ol) {
    int row = blockIdx.x;
    int tid = threadIdx.x;
    const float4* xr = (const float4*)(x + (size_t)row * NEMBD);
    float4 v = xr[tid];
    float ss = v.x*v.x + v.y*v.y + v.z*v.z + v.w*v.w;
    #pragma unroll
    for (int o = 16; o > 0; o >>= 1) ss += __shfl_xor_sync(0xffffffffu, ss, o);
    __shared__ float red[8];
    __shared__ float stot;
    if ((tid & 31) == 0) red[tid >> 5] = ss;
    __syncthreads();
    if (tid == 0) {
        float t = 0.f;
        #pragma unroll
        for (int i = 0; i < 8; i++) t += red[i];
        stot = rsqrtf(t * (1.0f/NEMBD) + 1e-5f);
    }
    __syncthreads();
    float rs = stot;
    float4 s4 = ((const float4*)scale)[tid];
    float o0 = v.x*rs*s4.x, o1 = v.y*rs*s4.y, o2 = v.z*rs*s4.z, o3 = v.w*rs*s4.w;
    uint32_t h01, l01, h23, l23;
    split2(o0, o1, h01, l01);
    split2(o2, o3, h23, l23);
    size_t off = (size_t)row * NEMBD + tid*4;
    *(uint32_t*)(oh + off)     = h01;
    *(uint32_t*)(oh + off + 2) = h23;
    *(uint32_t*)(ol + off)     = l01;
    *(uint32_t*)(ol + off + 2) = l23;
}

// ---------------- weight transpose + split: W[K,N] -> Wt_hi/lo[N,K] ----------------
__global__ void wprep_k(const float* __restrict__ W, __nv_bfloat16* __restrict__ Th,
                        __nv_bfloat16* __restrict__ Tl, int K, int N) {
    __shared__ float s[32][33];
    int n0 = blockIdx.x * 32, k0 = blockIdx.y * 32;
    int c = threadIdx.x & 31, r0 = threadIdx.x >> 5;
    #pragma unroll
    for (int i = 0; i < 4; i++) {
        int r = r0 + i*8;
        s[r][c] = W[(size_t)(k0 + r) * N + n0 + c];
    }
    __syncthreads();
    #pragma unroll
    for (int i = 0; i < 4; i++) {
        int r = r0 + i*8;
        float v = s[c][r];
        __nv_bfloat16 h = __float2bfloat16(v);
        Th[(size_t)(n0 + r) * K + k0 + c] = h;
        Tl[(size_t)(n0 + r) * K + k0 + c] = __float2bfloat16(v - __bfloat162float(h));
    }
}

// ---------------- HMMA GEMM (unchanged from round 6) ----------------
#define PADK    40
#define TILE_B  (128*PADK*2)
#define STAGE_B (4*TILE_B)
#define GSMEM_B (2*STAGE_B)

#define LOAD_STAGE(kt, s) do {                                                      \
    int _kof = (kt) * 32;                                                           \
    _Pragma("unroll")                                                               \
    for (int _i = 0; _i < 8; _i++) {                                                \
        int _id   = _i * 256 + tid;                                                 \
        int _tile = _id >> 9;                                                       \
        int _row  = (_id >> 2) & 127;                                               \
        int _ch   = _id & 3;                                                        \
        const __nv_bfloat16* _g =                                                   \
            (_tile == 0 ? gA0 : _tile == 1 ? gA1 : _tile == 2 ? gB0 : gB1)          \
            + (size_t)_row * K + _kof + _ch * 8;                                    \
        uint32_t _sa = sb + (uint32_t)(s) * STAGE_B + (uint32_t)_tile * TILE_B      \
                     + (uint32_t)(_row * PADK + _ch * 8) * 2u;                      \
        asm volatile("cp.async.cg.shared.global [%0], [%1], 16;" :: "r"(_sa), "l"(_g)); \
    }                                                                               \
    asm volatile("cp.async.commit_group;" ::: "memory");                            \
} while (0)

template<bool RES>
__global__ __launch_bounds__(256)
void hgemm_k(const __nv_bfloat16* __restrict__ Ah, const __nv_bfloat16* __restrict__ Al,
             const __nv_bfloat16* __restrict__ Bh, const __nv_bfloat16* __restrict__ Bl,
             const float* __restrict__ res, float* __restrict__ C, int N, int K) {
    extern __shared__ char smem[];
    uint32_t sb = smem_to_u32(smem);
    int tid  = threadIdx.x;
    int warp = tid >> 5, lane = tid & 31;
    int bm = blockIdx.y * 128, bn = blockIdx.x * 128;
    int wm = (warp & 1) * 64, wn = (warp >> 1) * 32;

    const __nv_bfloat16* gA0 = Ah + (size_t)bm * K;
    const __nv_bfloat16* gA1 = Al + (size_t)bm * K;
    const __nv_bfloat16* gB0 = Bh + (size_t)bn * K;
    const __nv_bfloat16* gB1 = Bl + (size_t)bn * K;

    float acc[4][4][4];
    #pragma unroll
    for (int a = 0; a < 4; a++)
        #pragma unroll
        for (int b = 0; b < 4; b++)
            #pragma unroll
            for (int c = 0; c < 4; c++) acc[a][b][c] = 0.f;

    int nkt = K >> 5;
    LOAD_STAGE(0, 0);
    for (int it = 0; it < nkt; it++) {
        int s = it & 1;
        if (it + 1 < nkt) {
            LOAD_STAGE(it + 1, s ^ 1);
            asm volatile("cp.async.wait_group 1;" ::: "memory");
        } else {
            asm volatile("cp.async.wait_group 0;" ::: "memory");
        }
        __syncthreads();
        uint32_t stb = sb + (uint32_t)s * STAGE_B;
        #pragma unroll
        for (int ks = 0; ks < 2; ks++) {
            #pragma unroll
            for (int p = 0; p < 3; p++) {
                uint32_t aT = stb + (p == 2 ? (uint32_t)TILE_B : 0u);
                uint32_t bT = stb + 2u*TILE_B + (p == 1 ? (uint32_t)TILE_B : 0u);
                uint32_t ar[4][4];
                #pragma unroll
                for (int mi = 0; mi < 4; mi++)
                    ldsm4(ar[mi], aT + (uint32_t)(((wm + mi*16 + (lane & 15)) * PADK)
                                                  + ks*16 + (lane >> 4) * 8) * 2u);
                uint32_t br[2][4];
                #pragma unroll
                for (int nq = 0; nq < 2; nq++)
                    ldsm4(br[nq], bT + (uint32_t)(((wn + nq*16 + (lane & 15)) * PADK)
                                                  + ks*16 + (lane >> 4) * 8) * 2u);
                #pragma unroll
                for (int mi = 0; mi < 4; mi++)
                    #pragma unroll
                    for (int j = 0; j < 4; j++)
                        mma16816(acc[mi][j], ar[mi], br[j >> 1][j & 1], br[j >> 1][(j & 1) + 2]);
            }
        }
        __syncthreads();
    }

    int r0 = lane >> 2, c0 = (lane & 3) * 2;
    #pragma unroll
    for (int mi = 0; mi < 4; mi++) {
        int gr = bm + wm + mi*16 + r0;
        #pragma unroll
        for (int j = 0; j < 4; j++) {
            int gc = bn + wn + j*8 + c0;
            size_t o1 = (size_t)gr * N + gc;
            size_t o2 = (size_t)(gr + 8) * N + gc;
            float2 v1 = make_float2(acc[mi][j][0], acc[mi][j][1]);
            float2 v2 = make_float2(acc[mi][j][2], acc[mi][j][3]);
            if (RES) {
                float2 rr = *(const float2*)(res + o1); v1.x += rr.x; v1.y += rr.y;
                float2 r2 = *(const float2*)(res + o2); v2.x += r2.x; v2.y += r2.y;
            }
            *(float2*)(C + o1) = v1;
            *(float2*)(C + o2) = v2;
        }
    }
}

// ---------------- RoPE ----------------
__global__ void rope_k(float* __restrict__ qkv, const float* __restrict__ trig) {
    int idx = blockIdx.x * blockDim.x + threadIdx.x;
    int pair = idx & 31;
    int h    = (idx >> 5) & 15;
    int slot = (idx >> 9) & 1;
    int m    = idx >> 10;
    int t    = m & (TSEQ - 1);
    float c = trig[t * 32 + pair];
    float s = trig[65536 + t * 32 + pair];
    size_t base = (size_t)m * QKVC + (size_t)slot * NEMBD + h * HEADD + 2*pair;
    float xe = qkv[base], xo = qkv[base+1];
    qkv[base]   = xe*c - xo*s;
    qkv[base+1] = xe*s + xo*c;
}

// ---------------- Flash attention on tensor cores (split bf16 mma) ----------------
// Block: 256 threads (8 warps), 128 query rows; KV tiles of 64.
// Smem: Qh/Ql [128][72], Kh/Kl [64][72], Vth/Vtl [64][72] (V transposed), ym[64].
#define APAD 72
#define AQ_ELE (128*APAD)
#define AK_ELE (64*APAD)
#define ASMEM_B ((2*AQ_ELE + 4*AK_ELE)*2 + 256)

__global__ __launch_bounds__(256)
void attn_mma_k(const float* __restrict__ qkv, const int* __restrict__ y_mask,
                __nv_bfloat16* __restrict__ yh, __nv_bfloat16* __restrict__ yl) {
    extern __shared__ char smem[];
    __nv_bfloat16* Qh  = (__nv_bfloat16*)smem;
    __nv_bfloat16* Ql  = Qh  + AQ_ELE;
    __nv_bfloat16* Kh  = Ql  + AQ_ELE;
    __nv_bfloat16* Kl  = Kh  + AK_ELE;
    __nv_bfloat16* Vth = Kl  + AK_ELE;
    __nv_bfloat16* Vtl = Vth + AK_ELE;
    int* ymS = (int*)(Vtl + AK_ELE);

    int qt = blockIdx.x, h = blockIdx.y, b = blockIdx.z;
    int bq = qt * 128;
    int tid = threadIdx.x, w = tid >> 5, lane = tid & 31;
    const float* base = qkv + (size_t)b * TSEQ * QKVC;

    uint32_t sQh = smem_to_u32(Qh), sQl = smem_to_u32(Ql);
    uint32_t sKh = smem_to_u32(Kh), sKl = smem_to_u32(Kl);
    uint32_t sVh = smem_to_u32(Vth), sVl = smem_to_u32(Vtl);

    // Load Q block (128 x 64 f32 -> split bf16)
    for (int i = tid; i < 128*16; i += 256) {
        int row = i >> 4, c4 = (i & 15) * 4;
        float4 v = *(const float4*)(base + (size_t)(bq + row) * QKVC + h*HEADD + c4);
        uint32_t h01, l01, h23, l23;
        split2(v.x, v.y, h01, l01);
        split2(v.z, v.w, h23, l23);
        int o = row * APAD + c4;
        *(uint32_t*)(Qh + o)     = h01;
        *(uint32_t*)(Qh + o + 2) = h23;
        *(uint32_t*)(Ql + o)     = l01;
        *(uint32_t*)(Ql + o + 2) = l23;
    }
    if (tid < 64) ymS[tid] = y_mask[b * 64 + tid];
    __syncthreads();

    // fragment row/col within warp tile
    int r0 = lane >> 2;            // 0..7
    int cq = (lane & 3) * 2;       // 0,2,4,6
    int wq = bq + w * 16;          // first q row of this warp
    int qi0 = wq + r0, qi1 = qi0 + 8;
    int ymq0 = (qi0 < 64) ? ymS[qi0] : 0;
    int ymq1 = (qi1 < 64) ? ymS[qi1] : 0;

    float Oacc[8][4];
    #pragma unroll
    for (int j = 0; j < 8; j++)
        #pragma unroll
        for (int c = 0; c < 4; c++) Oacc[j][c] = 0.f;
    float mrun0 = -1e30f, mrun1 = -1e30f, l0 = 0.f, l1 = 0.f;

    int nkv = 2*qt + 2;
    for (int kt = 0; kt < nkv; kt++) {
        // load K/V tile (64 x 64 f32 -> split bf16; V transposed)
        for (int i = tid; i < 64*16; i += 256) {
            int row = i >> 4, c4 = (i & 15) * 4;
            const float* kp = base + (size_t)(kt*64 + row) * QKVC + NEMBD   + h*HEADD + c4;
            const float* vp = base + (size_t)(kt*64 + row) * QKVC + 2*NEMBD + h*HEADD + c4;
            float4 kv4 = *(const float4*)kp;
            uint32_t h01, l01, h23, l23;
            split2(kv4.x, kv4.y, h01, l01);
            split2(kv4.z, kv4.w, h23, l23);
            int o = row * APAD + c4;
            *(uint32_t*)(Kh + o)     = h01;
            *(uint32_t*)(Kh + o + 2) = h23;
            *(uint32_t*)(Kl + o)     = l01;
            *(uint32_t*)(Kl + o + 2) = l23;
            float4 vv4 = *(const float4*)vp;
            float vv[4] = {vv4.x, vv4.y, vv4.z, vv4.w};
            #pragma unroll
            for (int jj = 0; jj < 4; jj++) {
                float fv = vv[jj];
                __nv_bfloat16 hv = __float2bfloat16(fv);
                Vth[(c4 + jj) * APAD + row] = hv;
                Vtl[(c4 + jj) * APAD + row] = __float2bfloat16(fv - __bfloat162float(hv));
            }
        }
        __syncthreads();

        // ---- S = Q K^T (3-product split) ----
        float S[8][4];
        #pragma unroll
        for (int j = 0; j < 8; j++)
            #pragma unroll
            for (int c = 0; c < 4; c++) S[j][c] = 0.f;

        #pragma unroll
        for (int ks = 0; ks < 4; ks++) {
            uint32_t ah[4], al[4];
            uint32_t aoff = (uint32_t)(((w*16 + (lane & 15)) * APAD) + ks*16 + (lane >> 4) * 8) * 2u;
            ldsm4(ah, sQh + aoff);
            ldsm4(al, sQl + aoff);
            #pragma unroll
            for (int nt = 0; nt < 4; nt++) {
                uint32_t bh[4], bl[4];
                uint32_t boff = (uint32_t)(((nt*16 + (lane & 15)) * APAD) + ks*16 + (lane >> 4) * 8) * 2u;
                ldsm4(bh, sKh + boff);
                ldsm4(bl, sKl + boff);
                int t0 = nt*2, t1 = nt*2 + 1;
                mma16816(S[t0], ah, bh[0], bh[2]);
                mma16816(S[t1], ah, bh[1], bh[3]);
                mma16816(S[t0], ah, bl[0], bl[2]);
                mma16816(S[t1], ah, bl[1], bl[3]);
                mma16816(S[t0], al, bh[0], bh[2]);
                mma16816(S[t1], al, bh[1], bh[3]);
            }
        }

        // ---- mask + scale ----
        bool needmask = (kt*64 + 63 > wq) || (wq < 64 && kt == 0);
        int kbase = kt * 64;
        if (needmask) {
            #pragma unroll
            for (int j = 0; j < 8; j++) {
                int kj = kbase + j*8 + cq;
                bool tx0 = ymq0 && (kj < 64);
                bool tx1 = ymq1 && (kj < 64);
                S[j][0] = ((kj   <= qi0) || (tx0 && ymS[kj]  )) ? S[j][0]*0.125f : -1e30f;
                S[j][1] = ((kj+1 <= qi0) || (tx0 && (kj+1<64) && ymS[kj+1])) ? S[j][1]*0.125f : -1e30f;
                S[j][2] = ((kj   <= qi1) || (tx1 && ymS[kj]  )) ? S[j][2]*0.125f : -1e30f;
                S[j][3] = ((kj+1 <= qi1) || (tx1 && (kj+1<64) && ymS[kj+1])) ? S[j][3]*0.125f : -1e30f;
            }
        } else {
            #pragma unroll
            for (int j = 0; j < 8; j++)
                #pragma unroll
                for (int c = 0; c < 4; c++) S[j][c] *= 0.125f;
        }

        // ---- online softmax ----
        float tmax0 = -1e30f, tmax1 = -1e30f;
        #pragma unroll
        for (int j = 0; j < 8; j++) {
            tmax0 = fmaxf(tmax0, fmaxf(S[j][0], S[j][1]));
            tmax1 = fmaxf(tmax1, fmaxf(S[j][2], S[j][3]));
        }
        tmax0 = fmaxf(tmax0, __shfl_xor_sync(0xffffffffu, tmax0, 1));
        tmax0 = fmaxf(tmax0, __shfl_xor_sync(0xffffffffu, tmax0, 2));
        tmax1 = fmaxf(tmax1, __shfl_xor_sync(0xffffffffu, tmax1, 1));
        tmax1 = fmaxf(tmax1, __shfl_xor_sync(0xffffffffu, tmax1, 2));
        float mnew0 = fmaxf(mrun0, tmax0);
        float mnew1 = fmaxf(mrun1, tmax1);
        float corr0 = __expf(mrun0 - mnew0);
        float corr1 = __expf(mrun1 - mnew1);
        mrun0 = mnew0; mrun1 = mnew1;

        float sum0 = 0.f, sum1 = 0.f;
        #pragma unroll
        for (int j = 0; j < 8; j++) {
            S[j][0] = __expf(S[j][0] - mnew0);
            S[j][1] = __expf(S[j][1] - mnew0);
            S[j][2] = __expf(S[j][2] - mnew1);
            S[j][3] = __expf(S[j][3] - mnew1);
            sum0 += S[j][0] + S[j][1];
            sum1 += S[j][2] + S[j][3];
        }
        sum0 += __shfl_xor_sync(0xffffffffu, sum0, 1);
        sum0 += __shfl_xor_sync(0xffffffffu, sum0, 2);
        sum1 += __shfl_xor_sync(0xffffffffu, sum1, 1);
        sum1 += __shfl_xor_sync(0xffffffffu, sum1, 2);
        l0 = l0 * corr0 + sum0;
        l1 = l1 * corr1 + sum1;

        #pragma unroll
        for (int j = 0; j < 8; j++) {
            Oacc[j][0] *= corr0; Oacc[j][1] *= corr0;
            Oacc[j][2] *= corr1; Oacc[j][3] *= corr1;
        }

        // ---- P frags (split, in-register relayout C->A) ----
        uint32_t ph[4][4], pl[4][4];
        #pragma unroll
        for (int ks = 0; ks < 4; ks++) {
            int t0 = ks*2, t1 = ks*2 + 1;
            split2(S[t0][0], S[t0][1], ph[ks][0], pl[ks][0]);
            split2(S[t0][2], S[t0][3], ph[ks][1], pl[ks][1]);
            split2(S[t1][0], S[t1][1], ph[ks][2], pl[ks][2]);
            split2(S[t1][2], S[t1][3], ph[ks][3], pl[ks][3]);
        }

        // ---- O += P V (3-product split) ----
        #pragma unroll
        for (int ks = 0; ks < 4; ks++) {
            #pragma unroll
            for (int nt = 0; nt < 4; nt++) {
                uint32_t bh[4], bl[4];
                uint32_t boff = (uint32_t)(((nt*16 + (lane & 15)) * APAD) + ks*16 + (lane >> 4) * 8) * 2u;
                ldsm4(bh, sVh + boff);
                ldsm4(bl, sVl + boff);
                int t0 = nt*2, t1 = nt*2 + 1;
                mma16816(Oacc[t0], ph[ks], bh[0], bh[2]);
                mma16816(Oacc[t1], ph[ks], bh[1], bh[3]);
                mma16816(Oacc[t0], ph[ks], bl[0], bl[2]);
                mma16816(Oacc[t1], ph[ks], bl[1], bl[3]);
                mma16816(Oacc[t0], pl[ks], bh[0], bh[2]);
                mma16816(Oacc[t1], pl[ks], bh[1], bh[3]);
            }
        }
        __syncthreads();
    }

    // ---- epilogue: normalize + split-bf16 store ----
    float inv0 = 1.0f / l0;
    float inv1 = 1.0f / l1;
    size_t yo0 = (size_t)(b * TSEQ + qi0) * NEMBD + h * HEADD;
    size_t yo1 = (size_t)(b * TSEQ + qi1) * NEMBD + h * HEADD;
    #pragma unroll
    for (int j = 0; j < 8; j++) {
        int d = j*8 + cq;
        uint32_t hh, ll;
        split2(Oacc[j][0]*inv0, Oacc[j][1]*inv0, hh, ll);
        *(uint32_t*)(yh + yo0 + d) = hh;
        *(uint32_t*)(yl + yo0 + d) = ll;
        split2(Oacc[j][2]*inv1, Oacc[j][3]*inv1, hh, ll);
        *(uint32_t*)(yh + yo1 + d) = hh;
        *(uint32_t*)(yl + yo1 + d) = ll;
    }
}

// ---------------- SwiGLU + bf16 split ----------------
__global__ void swiglu_split_k(const float* __restrict__ a, const float* __restrict__ b,
                               __nv_bfloat16* __restrict__ gh, __nv_bfloat16* __restrict__ gl) {
    int idx = blockIdx.x * blockDim.x + threadIdx.x;
    float4 av = ((const float4*)a)[idx];
    float4 bv = ((const float4*)b)[idx];
    float v0 = av.x / (1.f + __expf(-av.x)) * bv.x;
    float v1 = av.y / (1.f + __expf(-av.y)) * bv.y;
    float v2 = av.z / (1.f + __expf(-av.z)) * bv.z;
    float v3 = av.w / (1.f + __expf(-av.w)) * bv.w;
    uint32_t h01, l01, h23, l23;
    split2(v0, v1, h01, l01);
    split2(v2, v3, h23, l23);
    size_t off = (size_t)idx * 4;
    *(uint32_t*)(gh + off)     = h01;
    *(uint32_t*)(gh + off + 2) = h23;
    *(uint32_t*)(gl + off)     = l01;
    *(uint32_t*)(gl + off + 2) = l23;
}

// ---------------- launch ----------------
static void* sym(const void* s) { void* p = nullptr; cudaGetSymbolAddress(&p, s); return p; }

extern "C" void kernel_launch(void* const* d_in, const int* in_sizes, int n_in,
                              void* d_out, int out_size) {
    const float* x    = (const float*)d_in[0];
    const int*   ym   = (const int*)  d_in[1];
    const float* Wqkv = (const float*)d_in[2];
    const float* Wap  = (const float*)d_in[3];
    const float* s1   = (const float*)d_in[4];
    const float* s2   = (const float*)d_in[5];
    const float* Wfc1 = (const float*)d_in[6];
    const float* Wfc2 = (const float*)d_in[7];
    const float* Wmp  = (const float*)d_in[8];
    float* out = (float*)d_out;

    float* qkv  = (float*)sym(d_qkv);
    float* x1   = (float*)sym(d_x1);
    float* fc1  = (float*)sym(d_fc1);
    float* fc2  = (float*)sym(d_fc2);
    float* trig = (float*)sym(d_trig);
    __nv_bfloat16* ah  = (__nv_bfloat16*)sym(d_ah);
    __nv_bfloat16* al  = (__nv_bfloat16*)sym(d_al);
    __nv_bfloat16* yh  = (__nv_bfloat16*)sym(d_yh);
    __nv_bfloat16* yl  = (__nv_bfloat16*)sym(d_yl);
    __nv_bfloat16* h2h = (__nv_bfloat16*)sym(d_h2h);
    __nv_bfloat16* h2l = (__nv_bfloat16*)sym(d_h2l);
    __nv_bfloat16* gh  = (__nv_bfloat16*)sym(d_gh);
    __nv_bfloat16* gl  = (__nv_bfloat16*)sym(d_gl);
    __nv_bfloat16* wqh = (__nv_bfloat16*)sym(d_wqkvh);
    __nv_bfloat16* wql = (__nv_bfloat16*)sym(d_wqkvl);
    __nv_bfloat16* wah = (__nv_bfloat16*)sym(d_waph);
    __nv_bfloat16* wal = (__nv_bfloat16*)sym(d_wapl);
    __nv_bfloat16* w1h = (__nv_bfloat16*)sym(d_wf1h);
    __nv_bfloat16* w1l = (__nv_bfloat16*)sym(d_wf1l);
    __nv_bfloat16* w2h = (__nv_bfloat16*)sym(d_wf2h);
    __nv_bfloat16* w2l = (__nv_bfloat16*)sym(d_wf2l);
    __nv_bfloat16* wmh = (__nv_bfloat16*)sym(d_wmph);
    __nv_bfloat16* wml = (__nv_bfloat16*)sym(d_wmpl);

    cudaFuncSetAttribute(hgemm_k<false>, cudaFuncAttributeMaxDynamicSharedMemorySize, GSMEM_B);
    cudaFuncSetAttribute(hgemm_k<true>,  cudaFuncAttributeMaxDynamicSharedMemorySize, GSMEM_B);
    cudaFuncSetAttribute(attn_mma_k,     cudaFuncAttributeMaxDynamicSharedMemorySize, ASMEM_B);

    trig_k<<<65536/256, 256>>>(trig);

    wprep_k<<<dim3(QKVC/32,  NEMBD/32), 256>>>(Wqkv, wqh, wql, NEMBD, QKVC);
    wprep_k<<<dim3(NEMBD/32, NEMBD/32), 256>>>(Wap,  wah, wal, NEMBD, NEMBD);
    wprep_k<<<dim3(NHID/32,  NEMBD/32), 256>>>(Wfc1, w1h, w1l, NEMBD, NHID);
    wprep_k<<<dim3(NHID/32,  NEMBD/32), 256>>>(Wfc2, w2h, w2l, NEMBD, NHID);
    wprep_k<<<dim3(NEMBD/32, NHID/32),  256>>>(Wmp,  wmh, wml, NHID, NEMBD);

    rmsnorm_split_k<<<MROWS, 256>>>(x, s1, ah, al);
    hgemm_k<false><<<dim3(QKVC/128, MROWS/128), 256, GSMEM_B>>>(ah, al, wqh, wql, nullptr, qkv, QKVC, NEMBD);
    rope_k<<<(MROWS*2*NEMBD/(2*256)), 256>>>(qkv, trig);
    attn_mma_k<<<dim3(TSEQ/128, NHEAD, BATCH), 256, ASMEM_B>>>(qkv, ym, yh, yl);
    hgemm_k<true><<<dim3(NEMBD/128, MROWS/128), 256, GSMEM_B>>>(yh, yl, wah, wal, x, x1, NEMBD, NEMBD);
    rmsnorm_split_k<<<MROWS, 256>>>(x1, s2, h2h, h2l);
    hgemm_k<false><<<dim3(NHID/128, MROWS/128), 256, GSMEM_B>>>(h2h, h2l, w1h, w1l, nullptr, fc1, NHID, NEMBD);
    hgemm_k<false><<<dim3(NHID/128, MROWS/128), 256, GSMEM_B>>>(h2h, h2l, w2h, w2l, nullptr, fc2, NHID, NEMBD);
    swiglu_split_k<<<(MROWS*NHID)/(4*256), 256>>>(fc1, fc2, gh, gl);
    hgemm_k<true><<<dim3(NEMBD/128, MROWS/128), 256, GSMEM_B>>>(gh, gl, wmh, wml, x1, out, NEMBD, NHID);
}

// round 9
// speedup vs baseline: 4.1354x; 1.0204x over previous
#include <cuda_runtime.h>
#include <cuda_bf16.h>
#include <cuda_fp16.h>
#include <cstdint>

// ---------------- problem constants ----------------
#define BATCH   2
#define TSEQ    2048
#define NEMBD   1024
#define NHEAD   16
#define HEADD   64
#define NHID    2816
#define MROWS   (BATCH*TSEQ)          // 4096
#define QKVC    (3*NEMBD)             // 3072

// ---------------- static scratch (no allocations allowed) ----------------
__device__ float d_qkv[MROWS*QKVC];
__device__ float d_x1 [MROWS*NEMBD];
__device__ float d_fc1[MROWS*NHID];
__device__ float d_fc2[MROWS*NHID];
__device__ float d_trig[131072];

__device__ __nv_bfloat16 d_ah [MROWS*NEMBD],  d_al [MROWS*NEMBD];
__device__ __nv_bfloat16 d_yh [MROWS*NEMBD],  d_yl [MROWS*NEMBD];
__device__ __nv_bfloat16 d_h2h[MROWS*NEMBD],  d_h2l[MROWS*NEMBD];
__device__ __nv_bfloat16 d_gh [MROWS*NHID],   d_gl [MROWS*NHID];
__device__ __nv_bfloat16 d_wqkvh[QKVC*NEMBD], d_wqkvl[QKVC*NEMBD];
__device__ __nv_bfloat16 d_waph [NEMBD*NEMBD],d_wapl [NEMBD*NEMBD];
__device__ __nv_bfloat16 d_wf1h [NHID*NEMBD], d_wf1l [NHID*NEMBD];
__device__ __nv_bfloat16 d_wf2h [NHID*NEMBD], d_wf2l [NHID*NEMBD];
__device__ __nv_bfloat16 d_wmph [NEMBD*NHID], d_wmpl [NEMBD*NHID];

// ---------------- helpers ----------------
__device__ __forceinline__ uint32_t smem_to_u32(const void* p) {
    uint32_t a;
    asm("{ .reg .u64 t; cvta.to.shared.u64 t, %1; cvt.u32.u64 %0, t; }" : "=r"(a) : "l"(p));
    return a;
}
__device__ __forceinline__ void ldsm4(uint32_t r[4], uint32_t addr) {
    asm volatile("ldmatrix.sync.aligned.m8n8.x4.shared.b16 {%0,%1,%2,%3}, [%4];"
        : "=r"(r[0]), "=r"(r[1]), "=r"(r[2]), "=r"(r[3]) : "r"(addr));
}
__device__ __forceinline__ void mma16816(float c[4], const uint32_t a[4],
                                         uint32_t b0, uint32_t b1) {
    asm volatile("mma.sync.aligned.m16n8k16.row.col.f32.bf16.bf16.f32 "
        "{%0,%1,%2,%3}, {%4,%5,%6,%7}, {%8,%9}, {%0,%1,%2,%3};"
        : "+f"(c[0]), "+f"(c[1]), "+f"(c[2]), "+f"(c[3])
        : "r"(a[0]), "r"(a[1]), "r"(a[2]), "r"(a[3]), "r"(b0), "r"(b1));
}
__device__ __forceinline__ void mma16816h(float c[4], const uint32_t a[4],
                                          uint32_t b0, uint32_t b1) {
    asm volatile("mma.sync.aligned.m16n8k16.row.col.f32.f16.f16.f32 "
        "{%0,%1,%2,%3}, {%4,%5,%6,%7}, {%8,%9}, {%0,%1,%2,%3};"
        : "+f"(c[0]), "+f"(c[1]), "+f"(c[2]), "+f"(c[3])
        : "r"(a[0]), "r"(a[1]), "r"(a[2]), "r"(a[3]), "r"(b0), "r"(b1));
}
__device__ __forceinline__ void split2(float a, float b, uint32_t& hi, uint32_t& lo) {
    __nv_bfloat16 ha = __float2bfloat16(a), hb = __float2bfloat16(b);
    __nv_bfloat162 hh(ha, hb);
    hi = *(uint32_t*)&hh;
    __nv_bfloat162 ll(__float2bfloat16(a - __bfloat162float(ha)),
                      __float2bfloat16(b - __bfloat162float(hb)));
    lo = *(uint32_t*)&ll;
}
__device__ __forceinline__ void splith2(float a, float b, uint32_t& hi, uint32_t& lo) {
    __half ha = __float2half_rn(a), hb = __float2half_rn(b);
    __half2 hh(ha, hb);
    hi = *(uint32_t*)&hh;
    __half2 ll(__float2half_rn(a - __half2float(ha)),
               __float2half_rn(b - __half2float(hb)));
    lo = *(uint32_t*)&ll;
}
// packed fp16 2^x of a pair (lo slot gets 'lo', hi slot gets 'hi')
__device__ __forceinline__ uint32_t ex2x2(float lo, float hi) {
    uint32_t r;
    asm("{.reg .b32 t;\n\tcvt.rn.f16x2.f32 t, %1, %2;\n\tex2.approx.f16x2 %0, t;}"
        : "=r"(r) : "f"(hi), "f"(lo));
    return r;
}

// ---------------- trig table (fp64 arg reduction) ----------------
__global__ void trig_k(float* __restrict__ trig) {
    int i = blockIdx.x * blockDim.x + threadIdx.x;
    int pair = i & 31;
    int t    = i >> 5;
    double theta = pow(10000.0, -(double)pair / 32.0);
    double ang   = fmod((double)t * theta, 6.283185307179586);
    trig[i]         = (float)cos(ang);
    trig[65536 + i] = (float)sin(ang);
}

// ---------------- RMSNorm + bf16 split ----------------
__global__ void rmsnorm_split_k(const float* __restrict__ x, const float* __restrict__ scale,
                                __nv_bfloat16* __restrict__ oh, __nv_bfloat16* __restrict__ ol) {
    int row = blockIdx.x;
    int tid = threadIdx.x;
    const float4* xr = (const float4*)(x + (size_t)row * NEMBD);
    float4 v = xr[tid];
    float ss = v.x*v.x + v.y*v.y + v.z*v.z + v.w*v.w;
    #pragma unroll
    for (int o = 16; o > 0; o >>= 1) ss += __shfl_xor_sync(0xffffffffu, ss, o);
    __shared__ float red[8];
    __shared__ float stot;
    if ((tid & 31) == 0) red[tid >> 5] = ss;
    __syncthreads();
    if (tid == 0) {
        float t = 0.f;
        #pragma unroll
        for (int i = 0; i < 8; i++) t += red[i];
        stot = rsqrtf(t * (1.0f/NEMBD) + 1e-5f);
    }
    __syncthreads();
    float rs = stot;
    float4 s4 = ((const float4*)scale)[tid];
    float o0 = v.x*rs*s4.x, o1 = v.y*rs*s4.y, o2 = v.z*rs*s4.z, o3 = v.w*rs*s4.w;
    uint32_t h01, l01, h23, l23;
    split2(o0, o1, h01, l01);
    split2(o2, o3, h23, l23);
    size_t off = (size_t)row * NEMBD + tid*4;
    *(uint32_t*)(oh + off)     = h01;
    *(uint32_t*)(oh + off + 2) = h23;
    *(uint32_t*)(ol + off)     = l01;
    *(uint32_t*)(ol + off + 2) = l23;
}

// ---------------- weight transpose + split: W[K,N] -> Wt_hi/lo[N,K] ----------------
__global__ void wprep_k(const float* __restrict__ W, __nv_bfloat16* __restrict__ Th,
                        __nv_bfloat16* __restrict__ Tl, int K, int N) {
    __shared__ float s[32][33];
    int n0 = blockIdx.x * 32, k0 = blockIdx.y * 32;
    int c = threadIdx.x & 31, r0 = threadIdx.x >> 5;
    #pragma unroll
    for (int i = 0; i < 4; i++) {
        int r = r0 + i*8;
        s[r][c] = W[(size_t)(k0 + r) * N + n0 + c];
    }
    __syncthreads();
    #pragma unroll
    for (int i = 0; i < 4; i++) {
        int r = r0 + i*8;
        float v = s[c][r];
        __nv_bfloat16 h = __float2bfloat16(v);
        Th[(size_t)(n0 + r) * K + k0 + c] = h;
        Tl[(size_t)(n0 + r) * K + k0 + c] = __float2bfloat16(v - __bfloat162float(h));
    }
}

// ---------------- HMMA GEMM (2 CTAs/SM) ----------------
#define PADK    40
#define TILE_B  (128*PADK*2)
#define STAGE_B (4*TILE_B)
#define GSMEM_B (2*STAGE_B)

#define LOAD_STAGE(kt, s) do {                                                      \
    int _kof = (kt) * 32;                                                           \
    _Pragma("unroll")                                                               \
    for (int _i = 0; _i < 8; _i++) {                                                \
        int _id   = _i * 256 + tid;                                                 \
        int _tile = _id >> 9;                                                       \
        int _row  = (_id >> 2) & 127;                                               \
        int _ch   = _id & 3;                                                        \
        const __nv_bfloat16* _g =                                                   \
            (_tile == 0 ? gA0 : _tile == 1 ? gA1 : _tile == 2 ? gB0 : gB1)          \
            + (size_t)_row * K + _kof + _ch * 8;                                    \
        uint32_t _sa = sb + (uint32_t)(s) * STAGE_B + (uint32_t)_tile * TILE_B      \
                     + (uint32_t)(_row * PADK + _ch * 8) * 2u;                      \
        asm volatile("cp.async.cg.shared.global [%0], [%1], 16;" :: "r"(_sa), "l"(_g)); \
    }                                                                               \
    asm volatile("cp.async.commit_group;" ::: "memory");                            \
} while (0)

template<bool RES>
__global__ __launch_bounds__(256, 2)
void hgemm_k(const __nv_bfloat16* __restrict__ Ah, const __nv_bfloat16* __restrict__ Al,
             const __nv_bfloat16* __restrict__ Bh, const __nv_bfloat16* __restrict__ Bl,
             const float* __restrict__ res, float* __restrict__ C, int N, int K) {
    extern __shared__ char smem[];
    uint32_t sb = smem_to_u32(smem);
    int tid  = threadIdx.x;
    int warp = tid >> 5, lane = tid & 31;
    int bm = blockIdx.y * 128, bn = blockIdx.x * 128;
    int wm = (warp & 1) * 64, wn = (warp >> 1) * 32;

    const __nv_bfloat16* gA0 = Ah + (size_t)bm * K;
    const __nv_bfloat16* gA1 = Al + (size_t)bm * K;
    const __nv_bfloat16* gB0 = Bh + (size_t)bn * K;
    const __nv_bfloat16* gB1 = Bl + (size_t)bn * K;

    float acc[4][4][4];
    #pragma unroll
    for (int a = 0; a < 4; a++)
        #pragma unroll
        for (int b = 0; b < 4; b++)
            #pragma unroll
            for (int c = 0; c < 4; c++) acc[a][b][c] = 0.f;

    int nkt = K >> 5;
    LOAD_STAGE(0, 0);
    for (int it = 0; it < nkt; it++) {
        int s = it & 1;
        if (it + 1 < nkt) {
            LOAD_STAGE(it + 1, s ^ 1);
            asm volatile("cp.async.wait_group 1;" ::: "memory");
        } else {
            asm volatile("cp.async.wait_group 0;" ::: "memory");
        }
        __syncthreads();
        uint32_t stb = sb + (uint32_t)s * STAGE_B;
        #pragma unroll
        for (int ks = 0; ks < 2; ks++) {
            #pragma unroll
            for (int p = 0; p < 3; p++) {
                uint32_t aT = stb + (p == 2 ? (uint32_t)TILE_B : 0u);
                uint32_t bT = stb + 2u*TILE_B + (p == 1 ? (uint32_t)TILE_B : 0u);
                uint32_t ar[4][4];
                #pragma unroll
                for (int mi = 0; mi < 4; mi++)
                    ldsm4(ar[mi], aT + (uint32_t)(((wm + mi*16 + (lane & 15)) * PADK)
                                                  + ks*16 + (lane >> 4) * 8) * 2u);
                uint32_t br[2][4];
                #pragma unroll
                for (int nq = 0; nq < 2; nq++)
                    ldsm4(br[nq], bT + (uint32_t)(((wn + nq*16 + (lane & 15)) * PADK)
                                                  + ks*16 + (lane >> 4) * 8) * 2u);
                #pragma unroll
                for (int mi = 0; mi < 4; mi++)
                    #pragma unroll
                    for (int j = 0; j < 4; j++)
                        mma16816(acc[mi][j], ar[mi], br[j >> 1][j & 1], br[j >> 1][(j & 1) + 2]);
            }
        }
        __syncthreads();
    }

    int r0 = lane >> 2, c0 = (lane & 3) * 2;
    #pragma unroll
    for (int mi = 0; mi < 4; mi++) {
        int gr = bm + wm + mi*16 + r0;
        #pragma unroll
        for (int j = 0; j < 4; j++) {
            int gc = bn + wn + j*8 + c0;
            size_t o1 = (size_t)gr * N + gc;
            size_t o2 = (size_t)(gr + 8) * N + gc;
            float2 v1 = make_float2(acc[mi][j][0], acc[mi][j][1]);
            float2 v2 = make_float2(acc[mi][j][2], acc[mi][j][3]);
            if (RES) {
                float2 rr = *(const float2*)(res + o1); v1.x += rr.x; v1.y += rr.y;
                float2 r2 = *(const float2*)(res + o2); v2.x += r2.x; v2.y += r2.y;
            }
            *(float2*)(C + o1) = v1;
            *(float2*)(C + o2) = v2;
        }
    }
}

// ---------------- Flash attention: fp16 mma + packed-fp16 exp + fused RoPE --------
// Block: 256 threads (8 warps), 128 query rows; KV tiles of 64.
#define APAD 72
#define AQ_ELE (128*APAD)
#define AK_ELE (64*APAD)
#define ASMEM_B ((2*AQ_ELE + 4*AK_ELE)*2 + 256)

__global__ __launch_bounds__(256)
void attn_mma_k(const float* __restrict__ qkv, const int* __restrict__ y_mask,
                const float* __restrict__ trig,
                __nv_bfloat16* __restrict__ yh, __nv_bfloat16* __restrict__ yl) {
    extern __shared__ char smem[];
    __half* Qh  = (__half*)smem;
    __half* Ql  = Qh  + AQ_ELE;
    __half* Kh  = Ql  + AQ_ELE;
    __half* Kl  = Kh  + AK_ELE;
    __half* Vth = Kl  + AK_ELE;
    __half* Vtl = Vth + AK_ELE;
    int* ymS = (int*)(Vtl + AK_ELE);

    int qt = blockIdx.x, h = blockIdx.y, b = blockIdx.z;
    int bq = qt * 128;
    int tid = threadIdx.x, w = tid >> 5, lane = tid & 31;
    const float* base = qkv + (size_t)b * TSEQ * QKVC;

    uint32_t sQh = smem_to_u32(Qh), sQl = smem_to_u32(Ql);
    uint32_t sKh = smem_to_u32(Kh), sKl = smem_to_u32(Kl);
    uint32_t sVh = smem_to_u32(Vth), sVl = smem_to_u32(Vtl);

    // Load Q block with fused RoPE (128 x 64 f32 -> split fp16)
    for (int i = tid; i < 128*16; i += 256) {
        int row = i >> 4, c4 = (i & 15) * 4;
        int t = bq + row;
        float4 v = *(const float4*)(base + (size_t)t * QKVC + h*HEADD + c4);
        int pr = c4 >> 1;
        float c0 = trig[t*32 + pr],     s0 = trig[65536 + t*32 + pr];
        float c1 = trig[t*32 + pr + 1], s1 = trig[65536 + t*32 + pr + 1];
        float e0 = v.x*c0 - v.y*s0, o0 = v.x*s0 + v.y*c0;
        float e1 = v.z*c1 - v.w*s1, o1 = v.z*s1 + v.w*c1;
        uint32_t h01, l01, h23, l23;
        splith2(e0, o0, h01, l01);
        splith2(e1, o1, h23, l23);
        int o = row * APAD + c4;
        *(uint32_t*)(Qh + o)     = h01;
        *(uint32_t*)(Qh + o + 2) = h23;
        *(uint32_t*)(Ql + o)     = l01;
        *(uint32_t*)(Ql + o + 2) = l23;
    }
    if (tid < 64) ymS[tid] = y_mask[b * 64 + tid];
    __syncthreads();

    int r0 = lane >> 2;
    int cq = (lane & 3) * 2;
    int wq = bq + w * 16;
    int qi0 = wq + r0, qi1 = qi0 + 8;
    int ymq0 = (qi0 < 64) ? ymS[qi0] : 0;
    int ymq1 = (qi1 < 64) ? ymS[qi1] : 0;

    float Oacc[8][4];
    #pragma unroll
    for (int j = 0; j < 8; j++)
        #pragma unroll
        for (int c = 0; c < 4; c++) Oacc[j][c] = 0.f;
    float mrun0 = -1e30f, mrun1 = -1e30f, l0 = 0.f, l1 = 0.f;

    const float LS = 0.18033688011112042f;  // 0.125 * log2(e)

    int nkv = 2*qt + 2;
    for (int kt = 0; kt < nkv; kt++) {
        // load K (fused RoPE) / V tile (64 x 64 f32 -> split fp16; V transposed)
        for (int i = tid; i < 64*16; i += 256) {
            int row = i >> 4, c4 = (i & 15) * 4;
            int t = kt*64 + row;
            const float* kp = base + (size_t)t * QKVC + NEMBD   + h*HEADD + c4;
            const float* vp = base + (size_t)t * QKVC + 2*NEMBD + h*HEADD + c4;
            float4 kv4 = *(const float4*)kp;
            int pr = c4 >> 1;
            float c0 = trig[t*32 + pr],     s0 = trig[65536 + t*32 + pr];
            float c1 = trig[t*32 + pr + 1], s1 = trig[65536 + t*32 + pr + 1];
            float e0 = kv4.x*c0 - kv4.y*s0, o0 = kv4.x*s0 + kv4.y*c0;
            float e1 = kv4.z*c1 - kv4.w*s1, o1 = kv4.z*s1 + kv4.w*c1;
            uint32_t h01, l01, h23, l23;
            splith2(e0, o0, h01, l01);
            splith2(e1, o1, h23, l23);
            int o = row * APAD + c4;
            *(uint32_t*)(Kh + o)     = h01;
            *(uint32_t*)(Kh + o + 2) = h23;
            *(uint32_t*)(Kl + o)     = l01;
            *(uint32_t*)(Kl + o + 2) = l23;
            float4 vv4 = *(const float4*)vp;
            float vv[4] = {vv4.x, vv4.y, vv4.z, vv4.w};
            #pragma unroll
            for (int jj = 0; jj < 4; jj++) {
                float fv = vv[jj];
                __half hv = __float2half_rn(fv);
                Vth[(c4 + jj) * APAD + row] = hv;
                Vtl[(c4 + jj) * APAD + row] = __float2half_rn(fv - __half2float(hv));
            }
        }
        __syncthreads();

        // ---- S = Q K^T (3-product fp16 split) ----
        float S[8][4];
        #pragma unroll
        for (int j = 0; j < 8; j++)
            #pragma unroll
            for (int c = 0; c < 4; c++) S[j][c] = 0.f;

        #pragma unroll
        for (int ks = 0; ks < 4; ks++) {
            uint32_t ah[4], al[4];
            uint32_t aoff = (uint32_t)(((w*16 + (lane & 15)) * APAD) + ks*16 + (lane >> 4) * 8) * 2u;
            ldsm4(ah, sQh + aoff);
            ldsm4(al, sQl + aoff);
            #pragma unroll
            for (int nt = 0; nt < 4; nt++) {
                uint32_t bh[4], bl[4];
                uint32_t boff = (uint32_t)(((nt*16 + (lane & 15)) * APAD) + ks*16 + (lane >> 4) * 8) * 2u;
                ldsm4(bh, sKh + boff);
                ldsm4(bl, sKl + boff);
                int t0 = nt*2, t1 = nt*2 + 1;
                mma16816h(S[t0], ah, bh[0], bh[2]);
                mma16816h(S[t1], ah, bh[1], bh[3]);
                mma16816h(S[t0], ah, bl[0], bl[2]);
                mma16816h(S[t1], ah, bl[1], bl[3]);
                mma16816h(S[t0], al, bh[0], bh[2]);
                mma16816h(S[t1], al, bh[1], bh[3]);
            }
        }

        // ---- mask + scale (into log2 domain) ----
        bool needmask = (kt*64 + 63 > wq) || (wq < 64 && kt == 0);
        int kbase = kt * 64;
        if (needmask) {
            #pragma unroll
            for (int j = 0; j < 8; j++) {
                int kj = kbase + j*8 + cq;
                bool tx0 = ymq0 && (kj < 64);
                bool tx1 = ymq1 && (kj < 64);
                S[j][0] = ((kj   <= qi0) || (tx0 && ymS[kj]  )) ? S[j][0]*LS : -1e30f;
                S[j][1] = ((kj+1 <= qi0) || (tx0 && (kj+1<64) && ymS[kj+1])) ? S[j][1]*LS : -1e30f;
                S[j][2] = ((kj   <= qi1) || (tx1 && ymS[kj]  )) ? S[j][2]*LS : -1e30f;
                S[j][3] = ((kj+1 <= qi1) || (tx1 && (kj+1<64) && ymS[kj+1])) ? S[j][3]*LS : -1e30f;
            }
        } else {
            #pragma unroll
            for (int j = 0; j < 8; j++)
                #pragma unroll
                for (int c = 0; c < 4; c++) S[j][c] *= LS;
        }

        // ---- online softmax (base-2) ----
        float tmax0 = -1e30f, tmax1 = -1e30f;
        #pragma unroll
        for (int j = 0; j < 8; j++) {
            tmax0 = fmaxf(tmax0, fmaxf(S[j][0], S[j][1]));
            tmax1 = fmaxf(tmax1, fmaxf(S[j][2], S[j][3]));
        }
        tmax0 = fmaxf(tmax0, __shfl_xor_sync(0xffffffffu, tmax0, 1));
        tmax0 = fmaxf(tmax0, __shfl_xor_sync(0xffffffffu, tmax0, 2));
        tmax1 = fmaxf(tmax1, __shfl_xor_sync(0xffffffffu, tmax1, 1));
        tmax1 = fmaxf(tmax1, __shfl_xor_sync(0xffffffffu, tmax1, 2));
        float mnew0 = fmaxf(mrun0, tmax0);
        float mnew1 = fmaxf(mrun1, tmax1);
        float corr0 = exp2f(mrun0 - mnew0);
        float corr1 = exp2f(mrun1 - mnew1);
        mrun0 = mnew0; mrun1 = mnew1;

        // ---- P = 2^(S-m) in packed fp16 (direct A-fragments) + row sums ----
        uint32_t ph[4][4];
        float sum0 = 0.f, sum1 = 0.f;
        #pragma unroll
        for (int ks = 0; ks < 4; ks++) {
            int t0 = ks*2, t1 = ks*2 + 1;
            ph[ks][0] = ex2x2(S[t0][0]-mnew0, S[t0][1]-mnew0);
            ph[ks][1] = ex2x2(S[t0][2]-mnew1, S[t0][3]-mnew1);
            ph[ks][2] = ex2x2(S[t1][0]-mnew0, S[t1][1]-mnew0);
            ph[ks][3] = ex2x2(S[t1][2]-mnew1, S[t1][3]-mnew1);
            __half2 p0 = *(__half2*)&ph[ks][0];
            __half2 p1 = *(__half2*)&ph[ks][1];
            __half2 p2 = *(__half2*)&ph[ks][2];
            __half2 p3 = *(__half2*)&ph[ks][3];
            sum0 += __low2float(p0) + __high2float(p0) + __low2float(p2) + __high2float(p2);
            sum1 += __low2float(p1) + __high2float(p1) + __low2float(p3) + __high2float(p3);
        }
        sum0 += __shfl_xor_sync(0xffffffffu, sum0, 1);
        sum0 += __shfl_xor_sync(0xffffffffu, sum0, 2);
        sum1 += __shfl_xor_sync(0xffffffffu, sum1, 1);
        sum1 += __shfl_xor_sync(0xffffffffu, sum1, 2);
        l0 = l0 * corr0 + sum0;
        l1 = l1 * corr1 + sum1;

        #pragma unroll
        for (int j = 0; j < 8; j++) {
            Oacc[j][0] *= corr0; Oacc[j][1] *= corr0;
            Oacc[j][2] *= corr1; Oacc[j][3] *= corr1;
        }

        // ---- O += P V (2-product: P is exact fp16) ----
        #pragma unroll
        for (int ks = 0; ks < 4; ks++) {
            #pragma unroll
            for (int nt = 0; nt < 4; nt++) {
                uint32_t bh[4], bl[4];
                uint32_t boff = (uint32_t)(((nt*16 + (lane & 15)) * APAD) + ks*16 + (lane >> 4) * 8) * 2u;
                ldsm4(bh, sVh + boff);
                ldsm4(bl, sVl + boff);
                int t0 = nt*2, t1 = nt*2 + 1;
                mma16816h(Oacc[t0], ph[ks], bh[0], bh[2]);
                mma16816h(Oacc[t1], ph[ks], bh[1], bh[3]);
                mma16816h(Oacc[t0], ph[ks], bl[0], bl[2]);
                mma16816h(Oacc[t1], ph[ks], bl[1], bl[3]);
            }
        }
        __syncthreads();
    }

    // ---- epilogue: normalize + split-bf16 store ----
    float inv0 = 1.0f / l0;
    float inv1 = 1.0f / l1;
    size_t yo0 = (size_t)(b * TSEQ + qi0) * NEMBD + h * HEADD;
    size_t yo1 = (size_t)(b * TSEQ + qi1) * NEMBD + h * HEADD;
    #pragma unroll
    for (int j = 0; j < 8; j++) {
        int d = j*8 + cq;
        uint32_t hh, ll;
        split2(Oacc[j][0]*inv0, Oacc[j][1]*inv0, hh, ll);
        *(uint32_t*)(yh + yo0 + d) = hh;
        *(uint32_t*)(yl + yo0 + d) = ll;
        split2(Oacc[j][2]*inv1, Oacc[j][3]*inv1, hh, ll);
        *(uint32_t*)(yh + yo1 + d) = hh;
        *(uint32_t*)(yl + yo1 + d) = ll;
    }
}

// ---------------- SwiGLU + bf16 split ----------------
__global__ void swiglu_split_k(const float* __restrict__ a, const float* __restrict__ b,
                               __nv_bfloat16* __restrict__ gh, __nv_bfloat16* __restrict__ gl) {
    int idx = blockIdx.x * blockDim.x + threadIdx.x;
    float4 av = ((const float4*)a)[idx];
    float4 bv = ((const float4*)b)[idx];
    float v0 = av.x / (1.f + __expf(-av.x)) * bv.x;
    float v1 = av.y / (1.f + __expf(-av.y)) * bv.y;
    float v2 = av.z / (1.f + __expf(-av.z)) * bv.z;
    float v3 = av.w / (1.f + __expf(-av.w)) * bv.w;
    uint32_t h01, l01, h23, l23;
    split2(v0, v1, h01, l01);
    split2(v2, v3, h23, l23);
    size_t off = (size_t)idx * 4;
    *(uint32_t*)(gh + off)     = h01;
    *(uint32_t*)(gh + off + 2) = h23;
    *(uint32_t*)(gl + off)     = l01;
    *(uint32_t*)(gl + off + 2) = l23;
}

// ---------------- launch ----------------
static void* sym(const void* s) { void* p = nullptr; cudaGetSymbolAddress(&p, s); return p; }

extern "C" void kernel_launch(void* const* d_in, const int* in_sizes, int n_in,
                              void* d_out, int out_size) {
    const float* x    = (const float*)d_in[0];
    const int*   ym   = (const int*)  d_in[1];
    const float* Wqkv = (const float*)d_in[2];
    const float* Wap  = (const float*)d_in[3];
    const float* s1   = (const float*)d_in[4];
    const float* s2   = (const float*)d_in[5];
    const float* Wfc1 = (const float*)d_in[6];
    const float* Wfc2 = (const float*)d_in[7];
    const float* Wmp  = (const float*)d_in[8];
    float* out = (float*)d_out;

    float* qkv  = (float*)sym(d_qkv);
    float* x1   = (float*)sym(d_x1);
    float* fc1  = (float*)sym(d_fc1);
    float* fc2  = (float*)sym(d_fc2);
    float* trig = (float*)sym(d_trig);
    __nv_bfloat16* ah  = (__nv_bfloat16*)sym(d_ah);
    __nv_bfloat16* al  = (__nv_bfloat16*)sym(d_al);
    __nv_bfloat16* yh  = (__nv_bfloat16*)sym(d_yh);
    __nv_bfloat16* yl  = (__nv_bfloat16*)sym(d_yl);
    __nv_bfloat16* h2h = (__nv_bfloat16*)sym(d_h2h);
    __nv_bfloat16* h2l = (__nv_bfloat16*)sym(d_h2l);
    __nv_bfloat16* gh  = (__nv_bfloat16*)sym(d_gh);
    __nv_bfloat16* gl  = (__nv_bfloat16*)sym(d_gl);
    __nv_bfloat16* wqh = (__nv_bfloat16*)sym(d_wqkvh);
    __nv_bfloat16* wql = (__nv_bfloat16*)sym(d_wqkvl);
    __nv_bfloat16* wah = (__nv_bfloat16*)sym(d_waph);
    __nv_bfloat16* wal = (__nv_bfloat16*)sym(d_wapl);
    __nv_bfloat16* w1h = (__nv_bfloat16*)sym(d_wf1h);
    __nv_bfloat16* w1l = (__nv_bfloat16*)sym(d_wf1l);
    __nv_bfloat16* w2h = (__nv_bfloat16*)sym(d_wf2h);
    __nv_bfloat16* w2l = (__nv_bfloat16*)sym(d_wf2l);
    __nv_bfloat16* wmh = (__nv_bfloat16*)sym(d_wmph);
    __nv_bfloat16* wml = (__nv_bfloat16*)sym(d_wmpl);

    cudaFuncSetAttribute(hgemm_k<false>, cudaFuncAttributeMaxDynamicSharedMemorySize, GSMEM_B);
    cudaFuncSetAttribute(hgemm_k<true>,  cudaFuncAttributeMaxDynamicSharedMemorySize, GSMEM_B);
    cudaFuncSetAttribute(attn_mma_k,     cudaFuncAttributeMaxDynamicSharedMemorySize, ASMEM_B);

    trig_k<<<65536/256, 256>>>(trig);

    wprep_k<<<dim3(QKVC/32,  NEMBD/32), 256>>>(Wqkv, wqh, wql, NEMBD, QKVC);
    wprep_k<<<dim3(NEMBD/32, NEMBD/32), 256>>>(Wap,  wah, wal, NEMBD, NEMBD);
    wprep_k<<<dim3(NHID/32,  NEMBD/32), 256>>>(Wfc1, w1h, w1l, NEMBD, NHID);
    wprep_k<<<dim3(NHID/32,  NEMBD/32), 256>>>(Wfc2, w2h, w2l, NEMBD, NHID);
    wprep_k<<<dim3(NEMBD/32, NHID/32),  256>>>(Wmp,  wmh, wml, NHID, NEMBD);

    rmsnorm_split_k<<<MROWS, 256>>>(x, s1, ah, al);
    hgemm_k<false><<<dim3(QKVC/128, MROWS/128), 256, GSMEM_B>>>(ah, al, wqh, wql, nullptr, qkv, QKVC, NEMBD);
    attn_mma_k<<<dim3(TSEQ/128, NHEAD, BATCH), 256, ASMEM_B>>>(qkv, ym, trig, yh, yl);
    hgemm_k<true><<<dim3(NEMBD/128, MROWS/128), 256, GSMEM_B>>>(yh, yl, wah, wal, x, x1, NEMBD, NEMBD);
    rmsnorm_split_k<<<MROWS, 256>>>(x1, s2, h2h, h2l);
    hgemm_k<false><<<dim3(NHID/128, MROWS/128), 256, GSMEM_B>>>(h2h, h2l, w1h, w1l, nullptr, fc1, NHID, NEMBD);
    hgemm_k<false><<<dim3(NHID/128, MROWS/128), 256, GSMEM_B>>>(h2h, h2l, w2h, w2l, nullptr, fc2, NHID, NEMBD);
    swiglu_split_k<<<(MROWS*NHID)/(4*256), 256>>>(fc1, fc2, gh, gl);
    hgemm_k<true><<<dim3(NEMBD/128, MROWS/128), 256, GSMEM_B>>>(gh, gl, wmh, wml, x1, out, NEMBD, NHID);
}

// round 10
// speedup vs baseline: 5.2424x; 1.2677x over previous
#include <cuda_runtime.h>
#include <cuda_bf16.h>
#include <cuda_fp16.h>
#include <cstdint>

// ---------------- problem constants ----------------
#define BATCH   2
#define TSEQ    2048
#define NEMBD   1024
#define NHEAD   16
#define HEADD   64
#define NHID    2816
#define MROWS   (BATCH*TSEQ)          // 4096
#define QKVC    (3*NEMBD)             // 3072

// ---------------- static scratch (no allocations allowed) ----------------
__device__ float d_qkv[MROWS*QKVC];
__device__ float d_x1 [MROWS*NEMBD];
__device__ float d_fc1[MROWS*NHID];
__device__ float d_fc2[MROWS*NHID];
__device__ float d_trig[131072];

__device__ __half d_ah [MROWS*NEMBD],  d_al [MROWS*NEMBD];
__device__ __half d_yh [MROWS*NEMBD],  d_yl [MROWS*NEMBD];
__device__ __half d_h2h[MROWS*NEMBD],  d_h2l[MROWS*NEMBD];
__device__ __half d_gh [MROWS*NHID],   d_gl [MROWS*NHID];
__device__ __half d_wqkvh[QKVC*NEMBD];
__device__ __half d_waph [NEMBD*NEMBD];
__device__ __half d_wf1h [NHID*NEMBD];
__device__ __half d_wf2h [NHID*NEMBD];
__device__ __half d_wmph [NEMBD*NHID];

// ---------------- helpers ----------------
__device__ __forceinline__ uint32_t smem_to_u32(const void* p) {
    uint32_t a;
    asm("{ .reg .u64 t; cvta.to.shared.u64 t, %1; cvt.u32.u64 %0, t; }" : "=r"(a) : "l"(p));
    return a;
}
__device__ __forceinline__ void ldsm4(uint32_t r[4], uint32_t addr) {
    asm volatile("ldmatrix.sync.aligned.m8n8.x4.shared.b16 {%0,%1,%2,%3}, [%4];"
        : "=r"(r[0]), "=r"(r[1]), "=r"(r[2]), "=r"(r[3]) : "r"(addr));
}
__device__ __forceinline__ void mma16816h(float c[4], const uint32_t a[4],
                                          uint32_t b0, uint32_t b1) {
    asm volatile("mma.sync.aligned.m16n8k16.row.col.f32.f16.f16.f32 "
        "{%0,%1,%2,%3}, {%4,%5,%6,%7}, {%8,%9}, {%0,%1,%2,%3};"
        : "+f"(c[0]), "+f"(c[1]), "+f"(c[2]), "+f"(c[3])
        : "r"(a[0]), "r"(a[1]), "r"(a[2]), "r"(a[3]), "r"(b0), "r"(b1));
}
__device__ __forceinline__ void splith2(float a, float b, uint32_t& hi, uint32_t& lo) {
    __half ha = __float2half_rn(a), hb = __float2half_rn(b);
    __half2 hh(ha, hb);
    hi = *(uint32_t*)&hh;
    __half2 ll(__float2half_rn(a - __half2float(ha)),
               __float2half_rn(b - __half2float(hb)));
    lo = *(uint32_t*)&ll;
}
// packed fp16 2^x of a pair
__device__ __forceinline__ uint32_t ex2x2(float lo, float hi) {
    uint32_t r;
    asm("{.reg .b32 t;\n\tcvt.rn.f16x2.f32 t, %1, %2;\n\tex2.approx.f16x2 %0, t;}"
        : "=r"(r) : "f"(hi), "f"(lo));
    return r;
}

// ---------------- trig table (fp64 arg reduction) ----------------
__global__ void trig_k(float* __restrict__ trig) {
    int i = blockIdx.x * blockDim.x + threadIdx.x;
    int pair = i & 31;
    int t    = i >> 5;
    double theta = pow(10000.0, -(double)pair / 32.0);
    double ang   = fmod((double)t * theta, 6.283185307179586);
    trig[i]         = (float)cos(ang);
    trig[65536 + i] = (float)sin(ang);
}

// ---------------- RMSNorm + fp16 split ----------------
__global__ void rmsnorm_split_k(const float* __restrict__ x, const float* __restrict__ scale,
                                __half* __restrict__ oh, __half* __restrict__ ol) {
    int row = blockIdx.x;
    int tid = threadIdx.x;
    const float4* xr = (const float4*)(x + (size_t)row * NEMBD);
    float4 v = xr[tid];
    float ss = v.x*v.x + v.y*v.y + v.z*v.z + v.w*v.w;
    #pragma unroll
    for (int o = 16; o > 0; o >>= 1) ss += __shfl_xor_sync(0xffffffffu, ss, o);
    __shared__ float red[8];
    __shared__ float stot;
    if ((tid & 31) == 0) red[tid >> 5] = ss;
    __syncthreads();
    if (tid == 0) {
        float t = 0.f;
        #pragma unroll
        for (int i = 0; i < 8; i++) t += red[i];
        stot = rsqrtf(t * (1.0f/NEMBD) + 1e-5f);
    }
    __syncthreads();
    float rs = stot;
    float4 s4 = ((const float4*)scale)[tid];
    float o0 = v.x*rs*s4.x, o1 = v.y*rs*s4.y, o2 = v.z*rs*s4.z, o3 = v.w*rs*s4.w;
    uint32_t h01, l01, h23, l23;
    splith2(o0, o1, h01, l01);
    splith2(o2, o3, h23, l23);
    size_t off = (size_t)row * NEMBD + tid*4;
    *(uint32_t*)(oh + off)     = h01;
    *(uint32_t*)(oh + off + 2) = h23;
    *(uint32_t*)(ol + off)     = l01;
    *(uint32_t*)(ol + off + 2) = l23;
}

// ---------------- weight transpose + fp16 quantize: W[K,N] -> Wt[N,K] -----------
__global__ void wprep_k(const float* __restrict__ W, __half* __restrict__ Th,
                        int K, int N) {
    __shared__ float s[32][33];
    int n0 = blockIdx.x * 32, k0 = blockIdx.y * 32;
    int c = threadIdx.x & 31, r0 = threadIdx.x >> 5;
    #pragma unroll
    for (int i = 0; i < 4; i++) {
        int r = r0 + i*8;
        s[r][c] = W[(size_t)(k0 + r) * N + n0 + c];
    }
    __syncthreads();
    #pragma unroll
    for (int i = 0; i < 4; i++) {
        int r = r0 + i*8;
        Th[(size_t)(n0 + r) * K + k0 + c] = __float2half_rn(s[c][r]);
    }
}

// ---------------- HMMA GEMM: C[M,N] = (Ah+Al)[M,K] @ Bh[N,K]^T (+res) ------------
// 2-product fp16: Ah*Bh + Al*Bh = A*Bh (error = fp16 weight quantization only).
// BM=BN=128, BK=32, 8 warps (2x4), warp tile 64x32, cp.async 2-stage.
#define PADK    40
#define TILE_B  (128*PADK*2)       // 10240 B
#define STAGE_B (3*TILE_B)         // 30720 B (Ah, Al, Bh)
#define GSMEM_B (2*STAGE_B)        // 61440 B

#define LOAD_STAGE(kt, s) do {                                                      \
    int _kof = (kt) * 32;                                                           \
    _Pragma("unroll")                                                               \
    for (int _i = 0; _i < 6; _i++) {                                                \
        int _id   = _i * 256 + tid;                                                 \
        int _tile = _id >> 9;                                                       \
        int _row  = (_id >> 2) & 127;                                               \
        int _ch   = _id & 3;                                                        \
        const __half* _g =                                                          \
            (_tile == 0 ? gA0 : _tile == 1 ? gA1 : gB0)                             \
            + (size_t)_row * K + _kof + _ch * 8;                                    \
        uint32_t _sa = sb + (uint32_t)(s) * STAGE_B + (uint32_t)_tile * TILE_B      \
                     + (uint32_t)(_row * PADK + _ch * 8) * 2u;                      \
        asm volatile("cp.async.cg.shared.global [%0], [%1], 16;" :: "r"(_sa), "l"(_g)); \
    }                                                                               \
    asm volatile("cp.async.commit_group;" ::: "memory");                            \
} while (0)

template<bool RES>
__global__ __launch_bounds__(256)
void hgemm_k(const __half* __restrict__ Ah, const __half* __restrict__ Al,
             const __half* __restrict__ Bh,
             const float* __restrict__ res, float* __restrict__ C, int N, int K) {
    extern __shared__ char smem[];
    uint32_t sb = smem_to_u32(smem);
    int tid  = threadIdx.x;
    int warp = tid >> 5, lane = tid & 31;
    int bm = blockIdx.y * 128, bn = blockIdx.x * 128;
    int wm = (warp & 1) * 64, wn = (warp >> 1) * 32;

    const __half* gA0 = Ah + (size_t)bm * K;
    const __half* gA1 = Al + (size_t)bm * K;
    const __half* gB0 = Bh + (size_t)bn * K;

    float acc[4][4][4];
    #pragma unroll
    for (int a = 0; a < 4; a++)
        #pragma unroll
        for (int b = 0; b < 4; b++)
            #pragma unroll
            for (int c = 0; c < 4; c++) acc[a][b][c] = 0.f;

    int nkt = K >> 5;
    LOAD_STAGE(0, 0);
    for (int it = 0; it < nkt; it++) {
        int s = it & 1;
        if (it + 1 < nkt) {
            LOAD_STAGE(it + 1, s ^ 1);
            asm volatile("cp.async.wait_group 1;" ::: "memory");
        } else {
            asm volatile("cp.async.wait_group 0;" ::: "memory");
        }
        __syncthreads();
        uint32_t stb = sb + (uint32_t)s * STAGE_B;
        #pragma unroll
        for (int ks = 0; ks < 2; ks++) {
            uint32_t ar[4][4], al2[4][4], br[2][4];
            #pragma unroll
            for (int mi = 0; mi < 4; mi++) {
                uint32_t aoff = (uint32_t)(((wm + mi*16 + (lane & 15)) * PADK)
                                           + ks*16 + (lane >> 4) * 8) * 2u;
                ldsm4(ar[mi],  stb + aoff);
                ldsm4(al2[mi], stb + (uint32_t)TILE_B + aoff);
            }
            #pragma unroll
            for (int nq = 0; nq < 2; nq++)
                ldsm4(br[nq], stb + 2u*(uint32_t)TILE_B
                              + (uint32_t)(((wn + nq*16 + (lane & 15)) * PADK)
                                           + ks*16 + (lane >> 4) * 8) * 2u);
            #pragma unroll
            for (int mi = 0; mi < 4; mi++)
                #pragma unroll
                for (int j = 0; j < 4; j++)
                    mma16816h(acc[mi][j], ar[mi], br[j >> 1][j & 1], br[j >> 1][(j & 1) + 2]);
            #pragma unroll
            for (int mi = 0; mi < 4; mi++)
                #pragma unroll
                for (int j = 0; j < 4; j++)
                    mma16816h(acc[mi][j], al2[mi], br[j >> 1][j & 1], br[j >> 1][(j & 1) + 2]);
        }
        __syncthreads();
    }

    int r0 = lane >> 2, c0 = (lane & 3) * 2;
    #pragma unroll
    for (int mi = 0; mi < 4; mi++) {
        int gr = bm + wm + mi*16 + r0;
        #pragma unroll
        for (int j = 0; j < 4; j++) {
            int gc = bn + wn + j*8 + c0;
            size_t o1 = (size_t)gr * N + gc;
            size_t o2 = (size_t)(gr + 8) * N + gc;
            float2 v1 = make_float2(acc[mi][j][0], acc[mi][j][1]);
            float2 v2 = make_float2(acc[mi][j][2], acc[mi][j][3]);
            if (RES) {
                float2 rr = *(const float2*)(res + o1); v1.x += rr.x; v1.y += rr.y;
                float2 r2 = *(const float2*)(res + o2); v2.x += r2.x; v2.y += r2.y;
            }
            *(float2*)(C + o1) = v1;
            *(float2*)(C + o2) = v2;
        }
    }
}

// ---------------- Flash attention: fp16 mma + packed-fp16 exp + fused RoPE --------
#define APAD 72
#define AQ_ELE (128*APAD)
#define AK_ELE (64*APAD)
#define ASMEM_B ((2*AQ_ELE + 4*AK_ELE)*2 + 256)

__global__ __launch_bounds__(256)
void attn_mma_k(const float* __restrict__ qkv, const int* __restrict__ y_mask,
                const float* __restrict__ trig,
                __half* __restrict__ yh, __half* __restrict__ yl) {
    extern __shared__ char smem[];
    __half* Qh  = (__half*)smem;
    __half* Ql  = Qh  + AQ_ELE;
    __half* Kh  = Ql  + AQ_ELE;
    __half* Kl  = Kh  + AK_ELE;
    __half* Vth = Kl  + AK_ELE;
    __half* Vtl = Vth + AK_ELE;
    int* ymS = (int*)(Vtl + AK_ELE);

    int qt = (gridDim.x - 1) - blockIdx.x;   // heavy (large-qt) CTAs first
    int h = blockIdx.y, b = blockIdx.z;
    int bq = qt * 128;
    int tid = threadIdx.x, w = tid >> 5, lane = tid & 31;
    const float* base = qkv + (size_t)b * TSEQ * QKVC;

    uint32_t sQh = smem_to_u32(Qh), sQl = smem_to_u32(Ql);
    uint32_t sKh = smem_to_u32(Kh), sKl = smem_to_u32(Kl);
    uint32_t sVh = smem_to_u32(Vth), sVl = smem_to_u32(Vtl);

    // Load Q block with fused RoPE (128 x 64 f32 -> split fp16)
    for (int i = tid; i < 128*16; i += 256) {
        int row = i >> 4, c4 = (i & 15) * 4;
        int t = bq + row;
        float4 v = *(const float4*)(base + (size_t)t * QKVC + h*HEADD + c4);
        int pr = c4 >> 1;
        float c0 = trig[t*32 + pr],     s0 = trig[65536 + t*32 + pr];
        float c1 = trig[t*32 + pr + 1], s1 = trig[65536 + t*32 + pr + 1];
        float e0 = v.x*c0 - v.y*s0, o0 = v.x*s0 + v.y*c0;
        float e1 = v.z*c1 - v.w*s1, o1 = v.z*s1 + v.w*c1;
        uint32_t h01, l01, h23, l23;
        splith2(e0, o0, h01, l01);
        splith2(e1, o1, h23, l23);
        int o = row * APAD + c4;
        *(uint32_t*)(Qh + o)     = h01;
        *(uint32_t*)(Qh + o + 2) = h23;
        *(uint32_t*)(Ql + o)     = l01;
        *(uint32_t*)(Ql + o + 2) = l23;
    }
    if (tid < 64) ymS[tid] = y_mask[b * 64 + tid];
    __syncthreads();

    int r0 = lane >> 2;
    int cq = (lane & 3) * 2;
    int wq = bq + w * 16;
    int qi0 = wq + r0, qi1 = qi0 + 8;
    int ymq0 = (qi0 < 64) ? ymS[qi0] : 0;
    int ymq1 = (qi1 < 64) ? ymS[qi1] : 0;

    float Oacc[8][4];
    #pragma unroll
    for (int j = 0; j < 8; j++)
        #pragma unroll
        for (int c = 0; c < 4; c++) Oacc[j][c] = 0.f;
    float mrun0 = -1e30f, mrun1 = -1e30f, l0 = 0.f, l1 = 0.f;

    const float LS = 0.18033688011112042f;  // 0.125 * log2(e)

    int nkv = 2*qt + 2;
    for (int kt = 0; kt < nkv; kt++) {
        for (int i = tid; i < 64*16; i += 256) {
            int row = i >> 4, c4 = (i & 15) * 4;
            int t = kt*64 + row;
            const float* kp = base + (size_t)t * QKVC + NEMBD   + h*HEADD + c4;
            const float* vp = base + (size_t)t * QKVC + 2*NEMBD + h*HEADD + c4;
            float4 kv4 = *(const float4*)kp;
            int pr = c4 >> 1;
            float c0 = trig[t*32 + pr],     s0 = trig[65536 + t*32 + pr];
            float c1 = trig[t*32 + pr + 1], s1 = trig[65536 + t*32 + pr + 1];
            float e0 = kv4.x*c0 - kv4.y*s0, o0 = kv4.x*s0 + kv4.y*c0;
            float e1 = kv4.z*c1 - kv4.w*s1, o1 = kv4.z*s1 + kv4.w*c1;
            uint32_t h01, l01, h23, l23;
            splith2(e0, o0, h01, l01);
            splith2(e1, o1, h23, l23);
            int o = row * APAD + c4;
            *(uint32_t*)(Kh + o)     = h01;
            *(uint32_t*)(Kh + o + 2) = h23;
            *(uint32_t*)(Kl + o)     = l01;
            *(uint32_t*)(Kl + o + 2) = l23;
            float4 vv4 = *(const float4*)vp;
            float vv[4] = {vv4.x, vv4.y, vv4.z, vv4.w};
            #pragma unroll
            for (int jj = 0; jj < 4; jj++) {
                float fv = vv[jj];
                __half hv = __float2half_rn(fv);
                Vth[(c4 + jj) * APAD + row] = hv;
                Vtl[(c4 + jj) * APAD + row] = __float2half_rn(fv - __half2float(hv));
            }
        }
        __syncthreads();

        // ---- S = Q K^T (3-product fp16 split) ----
        float S[8][4];
        #pragma unroll
        for (int j = 0; j < 8; j++)
            #pragma unroll
            for (int c = 0; c < 4; c++) S[j][c] = 0.f;

        #pragma unroll
        for (int ks = 0; ks < 4; ks++) {
            uint32_t ah[4], al[4];
            uint32_t aoff = (uint32_t)(((w*16 + (lane & 15)) * APAD) + ks*16 + (lane >> 4) * 8) * 2u;
            ldsm4(ah, sQh + aoff);
            ldsm4(al, sQl + aoff);
            #pragma unroll
            for (int nt = 0; nt < 4; nt++) {
                uint32_t bh[4], bl[4];
                uint32_t boff = (uint32_t)(((nt*16 + (lane & 15)) * APAD) + ks*16 + (lane >> 4) * 8) * 2u;
                ldsm4(bh, sKh + boff);
                ldsm4(bl, sKl + boff);
                int t0 = nt*2, t1 = nt*2 + 1;
                mma16816h(S[t0], ah, bh[0], bh[2]);
                mma16816h(S[t1], ah, bh[1], bh[3]);
                mma16816h(S[t0], ah, bl[0], bl[2]);
                mma16816h(S[t1], ah, bl[1], bl[3]);
                mma16816h(S[t0], al, bh[0], bh[2]);
                mma16816h(S[t1], al, bh[1], bh[3]);
            }
        }

        // ---- mask + scale (log2 domain) ----
        bool needmask = (kt*64 + 63 > wq) || (wq < 64 && kt == 0);
        int kbase = kt * 64;
        if (needmask) {
            #pragma unroll
            for (int j = 0; j < 8; j++) {
                int kj = kbase + j*8 + cq;
                bool tx0 = ymq0 && (kj < 64);
                bool tx1 = ymq1 && (kj < 64);
                S[j][0] = ((kj   <= qi0) || (tx0 && ymS[kj]  )) ? S[j][0]*LS : -1e30f;
                S[j][1] = ((kj+1 <= qi0) || (tx0 && (kj+1<64) && ymS[kj+1])) ? S[j][1]*LS : -1e30f;
                S[j][2] = ((kj   <= qi1) || (tx1 && ymS[kj]  )) ? S[j][2]*LS : -1e30f;
                S[j][3] = ((kj+1 <= qi1) || (tx1 && (kj+1<64) && ymS[kj+1])) ? S[j][3]*LS : -1e30f;
            }
        } else {
            #pragma unroll
            for (int j = 0; j < 8; j++)
                #pragma unroll
                for (int c = 0; c < 4; c++) S[j][c] *= LS;
        }

        // ---- online softmax (base-2) ----
        float tmax0 = -1e30f, tmax1 = -1e30f;
        #pragma unroll
        for (int j = 0; j < 8; j++) {
            tmax0 = fmaxf(tmax0, fmaxf(S[j][0], S[j][1]));
            tmax1 = fmaxf(tmax1, fmaxf(S[j][2], S[j][3]));
        }
        tmax0 = fmaxf(tmax0, __shfl_xor_sync(0xffffffffu, tmax0, 1));
        tmax0 = fmaxf(tmax0, __shfl_xor_sync(0xffffffffu, tmax0, 2));
        tmax1 = fmaxf(tmax1, __shfl_xor_sync(0xffffffffu, tmax1, 1));
        tmax1 = fmaxf(tmax1, __shfl_xor_sync(0xffffffffu, tmax1, 2));
        float mnew0 = fmaxf(mrun0, tmax0);
        float mnew1 = fmaxf(mrun1, tmax1);
        float corr0 = exp2f(mrun0 - mnew0);
        float corr1 = exp2f(mrun1 - mnew1);
        mrun0 = mnew0; mrun1 = mnew1;

        // ---- P = 2^(S-m) packed fp16 (direct A-frags) + row sums ----
        uint32_t ph[4][4];
        float sum0 = 0.f, sum1 = 0.f;
        #pragma unroll
        for (int ks = 0; ks < 4; ks++) {
            int t0 = ks*2, t1 = ks*2 + 1;
            ph[ks][0] = ex2x2(S[t0][0]-mnew0, S[t0][1]-mnew0);
            ph[ks][1] = ex2x2(S[t0][2]-mnew1, S[t0][3]-mnew1);
            ph[ks][2] = ex2x2(S[t1][0]-mnew0, S[t1][1]-mnew0);
            ph[ks][3] = ex2x2(S[t1][2]-mnew1, S[t1][3]-mnew1);
            __half2 p0 = *(__half2*)&ph[ks][0];
            __half2 p1 = *(__half2*)&ph[ks][1];
            __half2 p2 = *(__half2*)&ph[ks][2];
            __half2 p3 = *(__half2*)&ph[ks][3];
            sum0 += __low2float(p0) + __high2float(p0) + __low2float(p2) + __high2float(p2);
            sum1 += __low2float(p1) + __high2float(p1) + __low2float(p3) + __high2float(p3);
        }
        sum0 += __shfl_xor_sync(0xffffffffu, sum0, 1);
        sum0 += __shfl_xor_sync(0xffffffffu, sum0, 2);
        sum1 += __shfl_xor_sync(0xffffffffu, sum1, 1);
        sum1 += __shfl_xor_sync(0xffffffffu, sum1, 2);
        l0 = l0 * corr0 + sum0;
        l1 = l1 * corr1 + sum1;

        #pragma unroll
        for (int j = 0; j < 8; j++) {
            Oacc[j][0] *= corr0; Oacc[j][1] *= corr0;
            Oacc[j][2] *= corr1; Oacc[j][3] *= corr1;
        }

        // ---- O += P V (2-product) ----
        #pragma unroll
        for (int ks = 0; ks < 4; ks++) {
            #pragma unroll
            for (int nt = 0; nt < 4; nt++) {
                uint32_t bh[4], bl[4];
                uint32_t boff = (uint32_t)(((nt*16 + (lane & 15)) * APAD) + ks*16 + (lane >> 4) * 8) * 2u;
                ldsm4(bh, sVh + boff);
                ldsm4(bl, sVl + boff);
                int t0 = nt*2, t1 = nt*2 + 1;
                mma16816h(Oacc[t0], ph[ks], bh[0], bh[2]);
                mma16816h(Oacc[t1], ph[ks], bh[1], bh[3]);
                mma16816h(Oacc[t0], ph[ks], bl[0], bl[2]);
                mma16816h(Oacc[t1], ph[ks], bl[1], bl[3]);
            }
        }
        __syncthreads();
    }

    // ---- epilogue: normalize + split-fp16 store ----
    float inv0 = 1.0f / l0;
    float inv1 = 1.0f / l1;
    size_t yo0 = (size_t)(b * TSEQ + qi0) * NEMBD + h * HEADD;
    size_t yo1 = (size_t)(b * TSEQ + qi1) * NEMBD + h * HEADD;
    #pragma unroll
    for (int j = 0; j < 8; j++) {
        int d = j*8 + cq;
        uint32_t hh, ll;
        splith2(Oacc[j][0]*inv0, Oacc[j][1]*inv0, hh, ll);
        *(uint32_t*)(yh + yo0 + d) = hh;
        *(uint32_t*)(yl + yo0 + d) = ll;
        splith2(Oacc[j][2]*inv1, Oacc[j][3]*inv1, hh, ll);
        *(uint32_t*)(yh + yo1 + d) = hh;
        *(uint32_t*)(yl + yo1 + d) = ll;
    }
}

// ---------------- SwiGLU + fp16 split ----------------
__global__ void swiglu_split_k(const float* __restrict__ a, const float* __restrict__ b,
                               __half* __restrict__ gh, __half* __restrict__ gl) {
    int idx = blockIdx.x * blockDim.x + threadIdx.x;
    float4 av = ((const float4*)a)[idx];
    float4 bv = ((const float4*)b)[idx];
    float v0 = av.x / (1.f + __expf(-av.x)) * bv.x;
    float v1 = av.y / (1.f + __expf(-av.y)) * bv.y;
    float v2 = av.z / (1.f + __expf(-av.z)) * bv.z;
    float v3 = av.w / (1.f + __expf(-av.w)) * bv.w;
    uint32_t h01, l01, h23, l23;
    splith2(v0, v1, h01, l01);
    splith2(v2, v3, h23, l23);
    size_t off = (size_t)idx * 4;
    *(uint32_t*)(gh + off)     = h01;
    *(uint32_t*)(gh + off + 2) = h23;
    *(uint32_t*)(gl + off)     = l01;
    *(uint32_t*)(gl + off + 2) = l23;
}

// ---------------- launch ----------------
static void* sym(const void* s) { void* p = nullptr; cudaGetSymbolAddress(&p, s); return p; }

extern "C" void kernel_launch(void* const* d_in, const int* in_sizes, int n_in,
                              void* d_out, int out_size) {
    const float* x    = (const float*)d_in[0];
    const int*   ym   = (const int*)  d_in[1];
    const float* Wqkv = (const float*)d_in[2];
    const float* Wap  = (const float*)d_in[3];
    const float* s1   = (const float*)d_in[4];
    const float* s2   = (const float*)d_in[5];
    const float* Wfc1 = (const float*)d_in[6];
    const float* Wfc2 = (const float*)d_in[7];
    const float* Wmp  = (const float*)d_in[8];
    float* out = (float*)d_out;

    float* qkv  = (float*)sym(d_qkv);
    float* x1   = (float*)sym(d_x1);
    float* fc1  = (float*)sym(d_fc1);
    float* fc2  = (float*)sym(d_fc2);
    float* trig = (float*)sym(d_trig);
    __half* ah  = (__half*)sym(d_ah);
    __half* al  = (__half*)sym(d_al);
    __half* yh  = (__half*)sym(d_yh);
    __half* yl  = (__half*)sym(d_yl);
    __half* h2h = (__half*)sym(d_h2h);
    __half* h2l = (__half*)sym(d_h2l);
    __half* gh  = (__half*)sym(d_gh);
    __half* gl  = (__half*)sym(d_gl);
    __half* wqh = (__half*)sym(d_wqkvh);
    __half* wah = (__half*)sym(d_waph);
    __half* w1h = (__half*)sym(d_wf1h);
    __half* w2h = (__half*)sym(d_wf2h);
    __half* wmh = (__half*)sym(d_wmph);

    cudaFuncSetAttribute(hgemm_k<false>, cudaFuncAttributeMaxDynamicSharedMemorySize, GSMEM_B);
    cudaFuncSetAttribute(hgemm_k<true>,  cudaFuncAttributeMaxDynamicSharedMemorySize, GSMEM_B);
    cudaFuncSetAttribute(attn_mma_k,     cudaFuncAttributeMaxDynamicSharedMemorySize, ASMEM_B);

    trig_k<<<65536/256, 256>>>(trig);

    wprep_k<<<dim3(QKVC/32,  NEMBD/32), 256>>>(Wqkv, wqh, NEMBD, QKVC);
    wprep_k<<<dim3(NEMBD/32, NEMBD/32), 256>>>(Wap,  wah, NEMBD, NEMBD);
    wprep_k<<<dim3(NHID/32,  NEMBD/32), 256>>>(Wfc1, w1h, NEMBD, NHID);
    wprep_k<<<dim3(NHID/32,  NEMBD/32), 256>>>(Wfc2, w2h, NEMBD, NHID);
    wprep_k<<<dim3(NEMBD/32, NHID/32),  256>>>(Wmp,  wmh, NHID, NEMBD);

    rmsnorm_split_k<<<MROWS, 256>>>(x, s1, ah, al);
    hgemm_k<false><<<dim3(QKVC/128, MROWS/128), 256, GSMEM_B>>>(ah, al, wqh, nullptr, qkv, QKVC, NEMBD);
    attn_mma_k<<<dim3(TSEQ/128, NHEAD, BATCH), 256, ASMEM_B>>>(qkv, ym, trig, yh, yl);
    hgemm_k<true><<<dim3(NEMBD/128, MROWS/128), 256, GSMEM_B>>>(yh, yl, wah, x, x1, NEMBD, NEMBD);
    rmsnorm_split_k<<<MROWS, 256>>>(x1, s2, h2h, h2l);
    hgemm_k<false><<<dim3(NHID/128, MROWS/128), 256, GSMEM_B>>>(h2h, h2l, w1h, nullptr, fc1, NHID, NEMBD);
    hgemm_k<false><<<dim3(NHID/128, MROWS/128), 256, GSMEM_B>>>(h2h, h2l, w2h, nullptr, fc2, NHID, NEMBD);
    swiglu_split_k<<<(MROWS*NHID)/(4*256), 256>>>(fc1, fc2, gh, gl);
    hgemm_k<true><<<dim3(NEMBD/128, MROWS/128), 256, GSMEM_B>>>(gh, gl, wmh, x1, out, NEMBD, NHID);
}

// round 13
// speedup vs baseline: 5.4170x; 1.0333x over previous
#include <cuda_runtime.h>
#include <cuda_fp16.h>
#include <cstdint>

// ---------------- problem constants ----------------
#define BATCH   2
#define TSEQ    2048
#define NEMBD   1024
#define NHEAD   16
#define HEADD   64
#define NHID    2816
#define MROWS   (BATCH*TSEQ)          // 4096
#define QKVC    (3*NEMBD)             // 3072

// ---------------- static scratch (no allocations allowed) ----------------
__device__ float d_qkv[MROWS*QKVC];
__device__ float d_x1 [MROWS*NEMBD];
__device__ float d_fc1[MROWS*NHID];
__device__ float d_fc2[MROWS*NHID];
__device__ float d_trig[131072];

__device__ __half d_ah [MROWS*NEMBD],  d_al [MROWS*NEMBD];
__device__ __half d_yh [MROWS*NEMBD],  d_yl [MROWS*NEMBD];
__device__ __half d_h2h[MROWS*NEMBD],  d_h2l[MROWS*NEMBD];
__device__ __half d_gh [MROWS*NHID],   d_gl [MROWS*NHID];
__device__ __half d_wqkvh[QKVC*NEMBD];
__device__ __half d_waph [NEMBD*NEMBD];
__device__ __half d_wf1h [NHID*NEMBD];
__device__ __half d_wf2h [NHID*NEMBD];
__device__ __half d_wmph [NEMBD*NHID];
// precomputed roped split-fp16 K [b,h,t,64] and transposed split V [b,h,d,T]
__device__ __half d_kh[BATCH*NHEAD*TSEQ*HEADD], d_kl[BATCH*NHEAD*TSEQ*HEADD];
__device__ __half d_vh[BATCH*NHEAD*HEADD*TSEQ], d_vl[BATCH*NHEAD*HEADD*TSEQ];

// ---------------- helpers ----------------
__device__ __forceinline__ uint32_t smem_to_u32(const void* p) {
    uint32_t a;
    asm("{ .reg .u64 t; cvta.to.shared.u64 t, %1; cvt.u32.u64 %0, t; }" : "=r"(a) : "l"(p));
    return a;
}
__device__ __forceinline__ void ldsm4(uint32_t r[4], uint32_t addr) {
    asm volatile("ldmatrix.sync.aligned.m8n8.x4.shared.b16 {%0,%1,%2,%3}, [%4];"
        : "=r"(r[0]), "=r"(r[1]), "=r"(r[2]), "=r"(r[3]) : "r"(addr));
}
__device__ __forceinline__ void mma16816h(float c[4], const uint32_t a[4],
                                          uint32_t b0, uint32_t b1) {
    asm volatile("mma.sync.aligned.m16n8k16.row.col.f32.f16.f16.f32 "
        "{%0,%1,%2,%3}, {%4,%5,%6,%7}, {%8,%9}, {%0,%1,%2,%3};"
        : "+f"(c[0]), "+f"(c[1]), "+f"(c[2]), "+f"(c[3])
        : "r"(a[0]), "r"(a[1]), "r"(a[2]), "r"(a[3]), "r"(b0), "r"(b1));
}
__device__ __forceinline__ void splith2(float a, float b, uint32_t& hi, uint32_t& lo) {
    __half ha = __float2half_rn(a), hb = __float2half_rn(b);
    __half2 hh(ha, hb);
    hi = *(uint32_t*)&hh;
    __half2 ll(__float2half_rn(a - __half2float(ha)),
               __float2half_rn(b - __half2float(hb)));
    lo = *(uint32_t*)&ll;
}
__device__ __forceinline__ uint32_t ex2x2(float lo, float hi) {
    uint32_t r;
    asm("{.reg .b32 t;\n\tcvt.rn.f16x2.f32 t, %1, %2;\n\tex2.approx.f16x2 %0, t;}"
        : "=r"(r) : "f"(hi), "f"(lo));
    return r;
}

// ---------------- trig table (fp64 arg reduction) ----------------
__global__ void trig_k(float* __restrict__ trig) {
    int i = blockIdx.x * blockDim.x + threadIdx.x;
    int pair = i & 31;
    int t    = i >> 5;
    double theta = pow(10000.0, -(double)pair / 32.0);
    double ang   = fmod((double)t * theta, 6.283185307179586);
    trig[i]         = (float)cos(ang);
    trig[65536 + i] = (float)sin(ang);
}

// ---------------- RMSNorm + fp16 split ----------------
__global__ void rmsnorm_split_k(const float* __restrict__ x, const float* __restrict__ scale,
                                __half* __restrict__ oh, __half* __restrict__ ol) {
    int row = blockIdx.x;
    int tid = threadIdx.x;
    const float4* xr = (const float4*)(x + (size_t)row * NEMBD);
    float4 v = xr[tid];
    float ss = v.x*v.x + v.y*v.y + v.z*v.z + v.w*v.w;
    #pragma unroll
    for (int o = 16; o > 0; o >>= 1) ss += __shfl_xor_sync(0xffffffffu, ss, o);
    __shared__ float red[8];
    __shared__ float stot;
    if ((tid & 31) == 0) red[tid >> 5] = ss;
    __syncthreads();
    if (tid == 0) {
        float t = 0.f;
        #pragma unroll
        for (int i = 0; i < 8; i++) t += red[i];
        stot = rsqrtf(t * (1.0f/NEMBD) + 1e-5f);
    }
    __syncthreads();
    float rs = stot;
    float4 s4 = ((const float4*)scale)[tid];
    float o0 = v.x*rs*s4.x, o1 = v.y*rs*s4.y, o2 = v.z*rs*s4.z, o3 = v.w*rs*s4.w;
    uint32_t h01, l01, h23, l23;
    splith2(o0, o1, h01, l01);
    splith2(o2, o3, h23, l23);
    size_t off = (size_t)row * NEMBD + tid*4;
    *(uint32_t*)(oh + off)     = h01;
    *(uint32_t*)(oh + off + 2) = h23;
    *(uint32_t*)(ol + off)     = l01;
    *(uint32_t*)(ol + off + 2) = l23;
}

// ---------------- weight transpose + fp16 quantize ----------------
__global__ void wprep_k(const float* __restrict__ W, __half* __restrict__ Th,
                        int K, int N) {
    __shared__ float s[32][33];
    int n0 = blockIdx.x * 32, k0 = blockIdx.y * 32;
    int c = threadIdx.x & 31, r0 = threadIdx.x >> 5;
    #pragma unroll
    for (int i = 0; i < 4; i++) {
        int r = r0 + i*8;
        s[r][c] = W[(size_t)(k0 + r) * N + n0 + c];
    }
    __syncthreads();
    #pragma unroll
    for (int i = 0; i < 4; i++) {
        int r = r0 + i*8;
        Th[(size_t)(n0 + r) * K + k0 + c] = __float2half_rn(s[c][r]);
    }
}

// ---------------- K/V prep: rope K, split fp16, transpose V ----------------
// grid (T/64, H, B), 256 threads. K -> [b,h,t,64], Vt -> [b,h,d,T].
#define APAD 72
__global__ void kvprep_k(const float* __restrict__ qkv, const float* __restrict__ trig,
                         __half* __restrict__ Kh, __half* __restrict__ Kl,
                         __half* __restrict__ Vh, __half* __restrict__ Vl) {
    __shared__ __half Vsh[64][APAD], Vsl[64][APAD];
    int kt = blockIdx.x, h = blockIdx.y, b = blockIdx.z;
    int tid = threadIdx.x;
    const float* base = qkv + (size_t)b * TSEQ * QKVC;
    size_t khead = ((size_t)(b*NHEAD + h)) * TSEQ * HEADD;
    size_t vhead = ((size_t)(b*NHEAD + h)) * HEADD * TSEQ;

    for (int i = tid; i < 64*16; i += 256) {
        int row = i >> 4, c4 = (i & 15) * 4;
        int t = kt*64 + row;
        float4 k4 = *(const float4*)(base + (size_t)t * QKVC + NEMBD + h*HEADD + c4);
        int pr = c4 >> 1;
        float c0 = trig[t*32 + pr],     s0 = trig[65536 + t*32 + pr];
        float c1 = trig[t*32 + pr + 1], s1 = trig[65536 + t*32 + pr + 1];
        float e0 = k4.x*c0 - k4.y*s0, o0 = k4.x*s0 + k4.y*c0;
        float e1 = k4.z*c1 - k4.w*s1, o1 = k4.z*s1 + k4.w*c1;
        uint32_t h01, l01, h23, l23;
        splith2(e0, o0, h01, l01);
        splith2(e1, o1, h23, l23);
        size_t ko = khead + (size_t)t * HEADD + c4;
        *(uint32_t*)(Kh + ko)     = h01;
        *(uint32_t*)(Kh + ko + 2) = h23;
        *(uint32_t*)(Kl + ko)     = l01;
        *(uint32_t*)(Kl + ko + 2) = l23;
        float4 v4 = *(const float4*)(base + (size_t)t * QKVC + 2*NEMBD + h*HEADD + c4);
        float vv[4] = {v4.x, v4.y, v4.z, v4.w};
        #pragma unroll
        for (int jj = 0; jj < 4; jj++) {
            float fv = vv[jj];
            __half hv = __float2half_rn(fv);
            Vsh[c4 + jj][row] = hv;
            Vsl[c4 + jj][row] = __float2half_rn(fv - __half2float(hv));
        }
    }
    __syncthreads();
    // write transposed rows (each 64-wide segment contiguous in global)
    for (int i = tid; i < 64*8; i += 256) {
        int d = i >> 3, seg = (i & 7) * 8;
        size_t vo = vhead + (size_t)d * TSEQ + kt*64 + seg;
        *(uint4*)(Vh + vo) = *(uint4*)(&Vsh[d][seg]);
        *(uint4*)(Vl + vo) = *(uint4*)(&Vsl[d][seg]);
    }
}

// ---------------- HMMA GEMM: 2-product fp16, 3-stage cp.async ----------------
#define PADK    40
#define TILE_B  (128*PADK*2)       // 10240 B
#define STAGE_B (3*TILE_B)         // 30720 B (Ah, Al, Bh)
#define GSMEM_B (3*STAGE_B)        // 92160 B

#define LOAD_STAGE(kt, s) do {                                                      \
    int _kof = (kt) * 32;                                                           \
    _Pragma("unroll")                                                               \
    for (int _i = 0; _i < 6; _i++) {                                                \
        int _id   = _i * 256 + tid;                                                 \
        int _tile = _id >> 9;                                                       \
        int _row  = (_id >> 2) & 127;                                               \
        int _ch   = _id & 3;                                                        \
        const __half* _g =                                                          \
            (_tile == 0 ? gA0 : _tile == 1 ? gA1 : gB0)                             \
            + (size_t)_row * K + _kof + _ch * 8;                                    \
        uint32_t _sa = sb + (uint32_t)(s) * STAGE_B + (uint32_t)_tile * TILE_B      \
                     + (uint32_t)(_row * PADK + _ch * 8) * 2u;                      \
        asm volatile("cp.async.cg.shared.global [%0], [%1], 16;" :: "r"(_sa), "l"(_g)); \
    }                                                                               \
    asm volatile("cp.async.commit_group;" ::: "memory");                            \
} while (0)

template<bool RES>
__global__ __launch_bounds__(256)
void hgemm_k(const __half* __restrict__ Ah, const __half* __restrict__ Al,
             const __half* __restrict__ Bh,
             const float* __restrict__ res, float* __restrict__ C, int N, int K) {
    extern __shared__ char smem[];
    uint32_t sb = smem_to_u32(smem);
    int tid  = threadIdx.x;
    int warp = tid >> 5, lane = tid & 31;
    int bm = blockIdx.y * 128, bn = blockIdx.x * 128;
    int wm = (warp & 1) * 64, wn = (warp >> 1) * 32;

    const __half* gA0 = Ah + (size_t)bm * K;
    const __half* gA1 = Al + (size_t)bm * K;
    const __half* gB0 = Bh + (size_t)bn * K;

    float acc[4][4][4];
    #pragma unroll
    for (int a = 0; a < 4; a++)
        #pragma unroll
        for (int b = 0; b < 4; b++)
            #pragma unroll
            for (int c = 0; c < 4; c++) acc[a][b][c] = 0.f;

    int nkt = K >> 5;
    LOAD_STAGE(0, 0);
    LOAD_STAGE(1, 1);
    for (int it = 0; it < nkt; it++) {
        int s = it % 3;
        if (it + 2 < nkt) LOAD_STAGE(it + 2, (it + 2) % 3);
        asm volatile("cp.async.wait_group 2;" ::: "memory");
        __syncthreads();
        uint32_t stb = sb + (uint32_t)s * STAGE_B;
        #pragma unroll
        for (int ks = 0; ks < 2; ks++) {
            uint32_t ar[4][4], al2[4][4], br[2][4];
            #pragma unroll
            for (int mi = 0; mi < 4; mi++) {
                uint32_t aoff = (uint32_t)(((wm + mi*16 + (lane & 15)) * PADK)
                                           + ks*16 + (lane >> 4) * 8) * 2u;
                ldsm4(ar[mi],  stb + aoff);
                ldsm4(al2[mi], stb + (uint32_t)TILE_B + aoff);
            }
            #pragma unroll
            for (int nq = 0; nq < 2; nq++)
                ldsm4(br[nq], stb + 2u*(uint32_t)TILE_B
                              + (uint32_t)(((wn + nq*16 + (lane & 15)) * PADK)
                                           + ks*16 + (lane >> 4) * 8) * 2u);
            #pragma unroll
            for (int mi = 0; mi < 4; mi++)
                #pragma unroll
                for (int j = 0; j < 4; j++)
                    mma16816h(acc[mi][j], ar[mi], br[j >> 1][j & 1], br[j >> 1][(j & 1) + 2]);
            #pragma unroll
            for (int mi = 0; mi < 4; mi++)
                #pragma unroll
                for (int j = 0; j < 4; j++)
                    mma16816h(acc[mi][j], al2[mi], br[j >> 1][j & 1], br[j >> 1][(j & 1) + 2]);
        }
        __syncthreads();
    }

    int r0 = lane >> 2, c0 = (lane & 3) * 2;
    #pragma unroll
    for (int mi = 0; mi < 4; mi++) {
        int gr = bm + wm + mi*16 + r0;
        #pragma unroll
        for (int j = 0; j < 4; j++) {
            int gc = bn + wn + j*8 + c0;
            size_t o1 = (size_t)gr * N + gc;
            size_t o2 = (size_t)(gr + 8) * N + gc;
            float2 v1 = make_float2(acc[mi][j][0], acc[mi][j][1]);
            float2 v2 = make_float2(acc[mi][j][2], acc[mi][j][3]);
            if (RES) {
                float2 rr = *(const float2*)(res + o1); v1.x += rr.x; v1.y += rr.y;
                float2 r2 = *(const float2*)(res + o2); v2.x += r2.x; v2.y += r2.y;
            }
            *(float2*)(C + o1) = v1;
            *(float2*)(C + o2) = v2;
        }
    }
}

// ---------------- Flash attention: cp.async K/V tiles + fp16 mma ----------------
#define AQ_ELE (128*APAD)
#define KVTILE (64*APAD*2)            // 9216 B per tile
#define KVSTAGE (4*KVTILE)            // Kh,Kl,Vh,Vl
#define KV_OFF (2*AQ_ELE*2)           // after Qh/Ql
#define YM_OFF (KV_OFF + 2*KVSTAGE)
#define ASMEM_B (YM_OFF + 256)

#define ALOAD(kt, s) do {                                                           \
    _Pragma("unroll")                                                               \
    for (int _i = 0; _i < 8; _i++) {                                                \
        int _id = _i*256 + tid;                                                     \
        int _tile = _id >> 9;                                                       \
        int _row = (_id >> 3) & 63;                                                 \
        int _ch = _id & 7;                                                          \
        const __half* _g;                                                           \
        if (_tile == 0)      _g = gKh + (size_t)((kt)*64 + _row)*HEADD + _ch*8;     \
        else if (_tile == 1) _g = gKl + (size_t)((kt)*64 + _row)*HEADD + _ch*8;     \
        else if (_tile == 2) _g = gVh + (size_t)_row*TSEQ + (kt)*64 + _ch*8;        \
        else                 _g = gVl + (size_t)_row*TSEQ + (kt)*64 + _ch*8;        \
        uint32_t _sa = kvb + (uint32_t)(s)*KVSTAGE + (uint32_t)_tile*KVTILE         \
                     + (uint32_t)(_row*APAD + _ch*8)*2u;                            \
        asm volatile("cp.async.cg.shared.global [%0], [%1], 16;" :: "r"(_sa), "l"(_g)); \
    }                                                                               \
    asm volatile("cp.async.commit_group;" ::: "memory");                            \
} while(0)

__global__ __launch_bounds__(256)
void attn_mma_k(const float* __restrict__ qkv, const int* __restrict__ y_mask,
                const float* __restrict__ trig,
                const __half* __restrict__ Khg, const __half* __restrict__ Klg,
                const __half* __restrict__ Vhg, const __half* __restrict__ Vlg,
                __half* __restrict__ yh, __half* __restrict__ yl) {
    extern __shared__ char smem[];
    uint32_t sb = smem_to_u32(smem);
    uint32_t sQh = sb, sQl = sb + AQ_ELE*2;
    uint32_t kvb = sb + KV_OFF;
    __half* Qh = (__half*)smem;
    __half* Ql = Qh + AQ_ELE;
    int* ymS = (int*)(smem + YM_OFF);

    int qt = (gridDim.x - 1) - blockIdx.x;   // heavy CTAs first
    int h = blockIdx.y, b = blockIdx.z;
    int bq = qt * 128;
    int tid = threadIdx.x, w = tid >> 5, lane = tid & 31;
    const float* base = qkv + (size_t)b * TSEQ * QKVC;
    const __half* gKh = Khg + ((size_t)(b*NHEAD + h)) * TSEQ * HEADD;
    const __half* gKl = Klg + ((size_t)(b*NHEAD + h)) * TSEQ * HEADD;
    const __half* gVh = Vhg + ((size_t)(b*NHEAD + h)) * HEADD * TSEQ;
    const __half* gVl = Vlg + ((size_t)(b*NHEAD + h)) * HEADD * TSEQ;

    int nkv = 2*qt + 2;
    ALOAD(0, 0);

    // Load Q block with fused RoPE (128 x 64 f32 -> split fp16)
    for (int i = tid; i < 128*16; i += 256) {
        int row = i >> 4, c4 = (i & 15) * 4;
        int t = bq + row;
        float4 v = *(const float4*)(base + (size_t)t * QKVC + h*HEADD + c4);
        int pr = c4 >> 1;
        float c0 = trig[t*32 + pr],     s0 = trig[65536 + t*32 + pr];
        float c1 = trig[t*32 + pr + 1], s1 = trig[65536 + t*32 + pr + 1];
        float e0 = v.x*c0 - v.y*s0, o0 = v.x*s0 + v.y*c0;
        float e1 = v.z*c1 - v.w*s1, o1 = v.z*s1 + v.w*c1;
        uint32_t h01, l01, h23, l23;
        splith2(e0, o0, h01, l01);
        splith2(e1, o1, h23, l23);
        int o = row * APAD + c4;
        *(uint32_t*)(Qh + o)     = h01;
        *(uint32_t*)(Qh + o + 2) = h23;
        *(uint32_t*)(Ql + o)     = l01;
        *(uint32_t*)(Ql + o + 2) = l23;
    }
    if (tid < 64) ymS[tid] = y_mask[b * 64 + tid];
    __syncthreads();

    int r0 = lane >> 2;
    int cq = (lane & 3) * 2;
    int wq = bq + w * 16;
    int qi0 = wq + r0, qi1 = qi0 + 8;
    int ymq0 = (qi0 < 64) ? ymS[qi0] : 0;
    int ymq1 = (qi1 < 64) ? ymS[qi1] : 0;

    float Oacc[8][4];
    #pragma unroll
    for (int j = 0; j < 8; j++)
        #pragma unroll
        for (int c = 0; c < 4; c++) Oacc[j][c] = 0.f;
    float mrun0 = -1e30f, mrun1 = -1e30f, l0 = 0.f, l1 = 0.f;

    const float LS = 0.18033688011112042f;  // 0.125 * log2(e)

    for (int kt = 0; kt < nkv; kt++) {
        int s = kt & 1;
        if (kt + 1 < nkv) {
            ALOAD(kt + 1, s ^ 1);
            asm volatile("cp.async.wait_group 1;" ::: "memory");
        } else {
            asm volatile("cp.async.wait_group 0;" ::: "memory");
        }
        __syncthreads();
        uint32_t bKh = kvb + (uint32_t)s * KVSTAGE;
        uint32_t bKl = bKh + KVTILE;
        uint32_t bVh = bKh + 2*KVTILE;
        uint32_t bVl = bKh + 3*KVTILE;

        // ---- S = Q K^T (3-product fp16 split) ----
        float S[8][4];
        #pragma unroll
        for (int j = 0; j < 8; j++)
            #pragma unroll
            for (int c = 0; c < 4; c++) S[j][c] = 0.f;

        #pragma unroll
        for (int ks = 0; ks < 4; ks++) {
            uint32_t ah[4], al[4];
            uint32_t aoff = (uint32_t)(((w*16 + (lane & 15)) * APAD) + ks*16 + (lane >> 4) * 8) * 2u;
            ldsm4(ah, sQh + aoff);
            ldsm4(al, sQl + aoff);
            #pragma unroll
            for (int nt = 0; nt < 4; nt++) {
                uint32_t bh[4], bl[4];
                uint32_t boff = (uint32_t)(((nt*16 + (lane & 15)) * APAD) + ks*16 + (lane >> 4) * 8) * 2u;
                ldsm4(bh, bKh + boff);
                ldsm4(bl, bKl + boff);
                int t0 = nt*2, t1 = nt*2 + 1;
                mma16816h(S[t0], ah, bh[0], bh[2]);
                mma16816h(S[t1], ah, bh[1], bh[3]);
                mma16816h(S[t0], ah, bl[0], bl[2]);
                mma16816h(S[t1], ah, bl[1], bl[3]);
                mma16816h(S[t0], al, bh[0], bh[2]);
                mma16816h(S[t1], al, bh[1], bh[3]);
            }
        }

        // ---- mask + scale (log2 domain) ----
        bool needmask = (kt*64 + 63 > wq) || (wq < 64 && kt == 0);
        int kbase = kt * 64;
        if (needmask) {
            #pragma unroll
            for (int j = 0; j < 8; j++) {
                int kj = kbase + j*8 + cq;
                bool tx0 = ymq0 && (kj < 64);
                bool tx1 = ymq1 && (kj < 64);
                S[j][0] = ((kj   <= qi0) || (tx0 && ymS[kj]  )) ? S[j][0]*LS : -1e30f;
                S[j][1] = ((kj+1 <= qi0) || (tx0 && (kj+1<64) && ymS[kj+1])) ? S[j][1]*LS : -1e30f;
                S[j][2] = ((kj   <= qi1) || (tx1 && ymS[kj]  )) ? S[j][2]*LS : -1e30f;
                S[j][3] = ((kj+1 <= qi1) || (tx1 && (kj+1<64) && ymS[kj+1])) ? S[j][3]*LS : -1e30f;
            }
        } else {
            #pragma unroll
            for (int j = 0; j < 8; j++)
                #pragma unroll
                for (int c = 0; c < 4; c++) S[j][c] *= LS;
        }

        // ---- online softmax (base-2) ----
        float tmax0 = -1e30f, tmax1 = -1e30f;
        #pragma unroll
        for (int j = 0; j < 8; j++) {
            tmax0 = fmaxf(tmax0, fmaxf(S[j][0], S[j][1]));
            tmax1 = fmaxf(tmax1, fmaxf(S[j][2], S[j][3]));
        }
        tmax0 = fmaxf(tmax0, __shfl_xor_sync(0xffffffffu, tmax0, 1));
        tmax0 = fmaxf(tmax0, __shfl_xor_sync(0xffffffffu, tmax0, 2));
        tmax1 = fmaxf(tmax1, __shfl_xor_sync(0xffffffffu, tmax1, 1));
        tmax1 = fmaxf(tmax1, __shfl_xor_sync(0xffffffffu, tmax1, 2));
        float mnew0 = fmaxf(mrun0, tmax0);
        float mnew1 = fmaxf(mrun1, tmax1);
        float corr0 = exp2f(mrun0 - mnew0);
        float corr1 = exp2f(mrun1 - mnew1);
        mrun0 = mnew0; mrun1 = mnew1;

        // ---- P = 2^(S-m) packed fp16 (direct A-frags) + row sums ----
        uint32_t ph[4][4];
        float sum0 = 0.f, sum1 = 0.f;
        #pragma unroll
        for (int ks = 0; ks < 4; ks++) {
            int t0 = ks*2, t1 = ks*2 + 1;
            ph[ks][0] = ex2x2(S[t0][0]-mnew0, S[t0][1]-mnew0);
            ph[ks][1] = ex2x2(S[t0][2]-mnew1, S[t0][3]-mnew1);
            ph[ks][2] = ex2x2(S[t1][0]-mnew0, S[t1][1]-mnew0);
            ph[ks][3] = ex2x2(S[t1][2]-mnew1, S[t1][3]-mnew1);
            __half2 p0 = *(__half2*)&ph[ks][0];
            __half2 p1 = *(__half2*)&ph[ks][1];
            __half2 p2 = *(__half2*)&ph[ks][2];
            __half2 p3 = *(__half2*)&ph[ks][3];
            sum0 += __low2float(p0) + __high2float(p0) + __low2float(p2) + __high2float(p2);
            sum1 += __low2float(p1) + __high2float(p1) + __low2float(p3) + __high2float(p3);
        }
        sum0 += __shfl_xor_sync(0xffffffffu, sum0, 1);
        sum0 += __shfl_xor_sync(0xffffffffu, sum0, 2);
        sum1 += __shfl_xor_sync(0xffffffffu, sum1, 1);
        sum1 += __shfl_xor_sync(0xffffffffu, sum1, 2);
        l0 = l0 * corr0 + sum0;
        l1 = l1 * corr1 + sum1;

        #pragma unroll
        for (int j = 0; j < 8; j++) {
            Oacc[j][0] *= corr0; Oacc[j][1] *= corr0;
            Oacc[j][2] *= corr1; Oacc[j][3] *= corr1;
        }

        // ---- O += P V (2-product) ----
        #pragma unroll
        for (int ks = 0; ks < 4; ks++) {
            #pragma unroll
            for (int nt = 0; nt < 4; nt++) {
                uint32_t bh[4], bl[4];
                uint32_t boff = (uint32_t)(((nt*16 + (lane & 15)) * APAD) + ks*16 + (lane >> 4) * 8) * 2u;
                ldsm4(bh, bVh + boff);
                ldsm4(bl, bVl + boff);
                int t0 = nt*2, t1 = nt*2 + 1;
                mma16816h(Oacc[t0], ph[ks], bh[0], bh[2]);
                mma16816h(Oacc[t1], ph[ks], bh[1], bh[3]);
                mma16816h(Oacc[t0], ph[ks], bl[0], bl[2]);
                mma16816h(Oacc[t1], ph[ks], bl[1], bl[3]);
            }
        }
        __syncthreads();
    }

    // ---- epilogue: normalize + split-fp16 store ----
    float inv0 = 1.0f / l0;
    float inv1 = 1.0f / l1;
    size_t yo0 = (size_t)(b * TSEQ + qi0) * NEMBD + h * HEADD;
    size_t yo1 = (size_t)(b * TSEQ + qi1) * NEMBD + h * HEADD;
    #pragma unroll
    for (int j = 0; j < 8; j++) {
        int d = j*8 + cq;
        uint32_t hh, ll;
        splith2(Oacc[j][0]*inv0, Oacc[j][1]*inv0, hh, ll);
        *(uint32_t*)(yh + yo0 + d) = hh;
        *(uint32_t*)(yl + yo0 + d) = ll;
        splith2(Oacc[j][2]*inv1, Oacc[j][3]*inv1, hh, ll);
        *(uint32_t*)(yh + yo1 + d) = hh;
        *(uint32_t*)(yl + yo1 + d) = ll;
    }
}

// ---------------- SwiGLU + fp16 split ----------------
__global__ void swiglu_split_k(const float* __restrict__ a, const float* __restrict__ b,
                               __half* __restrict__ gh, __half* __restrict__ gl) {
    int idx = blockIdx.x * blockDim.x + threadIdx.x;
    float4 av = ((const float4*)a)[idx];
    float4 bv = ((const float4*)b)[idx];
    float v0 = av.x / (1.f + __expf(-av.x)) * bv.x;
    float v1 = av.y / (1.f + __expf(-av.y)) * bv.y;
    float v2 = av.z / (1.f + __expf(-av.z)) * bv.z;
    float v3 = av.w / (1.f + __expf(-av.w)) * bv.w;
    uint32_t h01, l01, h23, l23;
    splith2(v0, v1, h01, l01);
    splith2(v2, v3, h23, l23);
    size_t off = (size_t)idx * 4;
    *(uint32_t*)(gh + off)     = h01;
    *(uint32_t*)(gh + off + 2) = h23;
    *(uint32_t*)(gl + off)     = l01;
    *(uint32_t*)(gl + off + 2) = l23;
}

// ---------------- launch ----------------
static void* sym(const void* s) { void* p = nullptr; cudaGetSymbolAddress(&p, s); return p; }

extern "C" void kernel_launch(void* const* d_in, const int* in_sizes, int n_in,
                              void* d_out, int out_size) {
    const float* x    = (const float*)d_in[0];
    const int*   ym   = (const int*)  d_in[1];
    const float* Wqkv = (const float*)d_in[2];
    const float* Wap  = (const float*)d_in[3];
    const float* s1   = (const float*)d_in[4];
    const float* s2   = (const float*)d_in[5];
    const float* Wfc1 = (const float*)d_in[6];
    const float* Wfc2 = (const float*)d_in[7];
    const float* Wmp  = (const float*)d_in[8];
    float* out = (float*)d_out;

    float* qkv  = (float*)sym(d_qkv);
    float* x1   = (float*)sym(d_x1);
    float* fc1  = (float*)sym(d_fc1);
    float* fc2  = (float*)sym(d_fc2);
    float* trig = (float*)sym(d_trig);
    __half* ah  = (__half*)sym(d_ah);
    __half* al  = (__half*)sym(d_al);
    __half* yh  = (__half*)sym(d_yh);
    __half* yl  = (__half*)sym(d_yl);
    __half* h2h = (__half*)sym(d_h2h);
    __half* h2l = (__half*)sym(d_h2l);
    __half* gh  = (__half*)sym(d_gh);
    __half* gl  = (__half*)sym(d_gl);
    __half* wqh = (__half*)sym(d_wqkvh);
    __half* wah = (__half*)sym(d_waph);
    __half* w1h = (__half*)sym(d_wf1h);
    __half* w2h = (__half*)sym(d_wf2h);
    __half* wmh = (__half*)sym(d_wmph);
    __half* kh  = (__half*)sym(d_kh);
    __half* kl  = (__half*)sym(d_kl);
    __half* vh  = (__half*)sym(d_vh);
    __half* vl  = (__half*)sym(d_vl);

    cudaFuncSetAttribute(hgemm_k<false>, cudaFuncAttributeMaxDynamicSharedMemorySize, GSMEM_B);
    cudaFuncSetAttribute(hgemm_k<true>,  cudaFuncAttributeMaxDynamicSharedMemorySize, GSMEM_B);
    cudaFuncSetAttribute(attn_mma_k,     cudaFuncAttributeMaxDynamicSharedMemorySize, ASMEM_B);

    trig_k<<<65536/256, 256>>>(trig);

    wprep_k<<<dim3(QKVC/32,  NEMBD/32), 256>>>(Wqkv, wqh, NEMBD, QKVC);
    wprep_k<<<dim3(NEMBD/32, NEMBD/32), 256>>>(Wap,  wah, NEMBD, NEMBD);
    wprep_k<<<dim3(NHID/32,  NEMBD/32), 256>>>(Wfc1, w1h, NEMBD, NHID);
    wprep_k<<<dim3(NHID/32,  NEMBD/32), 256>>>(Wfc2, w2h, NEMBD, NHID);
    wprep_k<<<dim3(NEMBD/32, NHID/32),  256>>>(Wmp,  wmh, NHID, NEMBD);

    rmsnorm_split_k<<<MROWS, 256>>>(x, s1, ah, al);
    hgemm_k<false><<<dim3(QKVC/128, MROWS/128), 256, GSMEM_B>>>(ah, al, wqh, nullptr, qkv, QKVC, NEMBD);
    kvprep_k<<<dim3(TSEQ/64, NHEAD, BATCH), 256>>>(qkv, trig, kh, kl, vh, vl);
    attn_mma_k<<<dim3(TSEQ/128, NHEAD, BATCH), 256, ASMEM_B>>>(qkv, ym, trig, kh, kl, vh, vl, yh, yl);
    hgemm_k<true><<<dim3(NEMBD/128, MROWS/128), 256, GSMEM_B>>>(yh, yl, wah, x, x1, NEMBD, NEMBD);
    rmsnorm_split_k<<<MROWS, 256>>>(x1, s2, h2h, h2l);
    hgemm_k<false><<<dim3(NHID/128, MROWS/128), 256, GSMEM_B>>>(h2h, h2l, w1h, nullptr, fc1, NHID, NEMBD);
    hgemm_k<false><<<dim3(NHID/128, MROWS/128), 256, GSMEM_B>>>(h2h, h2l, w2h, nullptr, fc2, NHID, NEMBD);
    swiglu_split_k<<<(MROWS*NHID)/(4*256), 256>>>(fc1, fc2, gh, gl);
    hgemm_k<true><<<dim3(NEMBD/128, MROWS/128), 256, GSMEM_B>>>(gh, gl, wmh, x1, out, NEMBD, NHID);
}

// round 16
// speedup vs baseline: 5.5935x; 1.0326x over previous
#include <cuda_runtime.h>
#include <cuda_fp16.h>
#include <cstdint>

// ---------------- problem constants ----------------
#define BATCH   2
#define TSEQ    2048
#define NEMBD   1024
#define NHEAD   16
#define HEADD   64
#define NHID    2816
#define MROWS   (BATCH*TSEQ)          // 4096
#define QKVC    (3*NEMBD)             // 3072

// ---------------- static scratch (no allocations allowed) ----------------
__device__ float d_qkv[MROWS*QKVC];
__device__ float d_x1 [MROWS*NEMBD];
__device__ float d_trig[131072];

__device__ __half d_ah [MROWS*NEMBD],  d_al [MROWS*NEMBD];
__device__ __half d_yh [MROWS*NEMBD],  d_yl [MROWS*NEMBD];
__device__ __half d_h2h[MROWS*NEMBD],  d_h2l[MROWS*NEMBD];
__device__ __half d_gh [MROWS*NHID],   d_gl [MROWS*NHID];
__device__ __half d_wqkvh[QKVC*NEMBD];
__device__ __half d_waph [NEMBD*NEMBD];
__device__ __half d_w12  [2*NHID*NEMBD];     // interleaved fc1/fc2 (8-col blocks)
__device__ __half d_wmph [NEMBD*NHID];
// precomputed roped split-fp16 K [b,h,t,64] and transposed split V [b,h,d,T]
__device__ __half d_kh[BATCH*NHEAD*TSEQ*HEADD], d_kl[BATCH*NHEAD*TSEQ*HEADD];
__device__ __half d_vh[BATCH*NHEAD*HEADD*TSEQ], d_vl[BATCH*NHEAD*HEADD*TSEQ];

// ---------------- helpers ----------------
__device__ __forceinline__ uint32_t smem_to_u32(const void* p) {
    uint32_t a;
    asm("{ .reg .u64 t; cvta.to.shared.u64 t, %1; cvt.u32.u64 %0, t; }" : "=r"(a) : "l"(p));
    return a;
}
__device__ __forceinline__ void ldsm4(uint32_t r[4], uint32_t addr) {
    asm volatile("ldmatrix.sync.aligned.m8n8.x4.shared.b16 {%0,%1,%2,%3}, [%4];"
        : "=r"(r[0]), "=r"(r[1]), "=r"(r[2]), "=r"(r[3]) : "r"(addr));
}
__device__ __forceinline__ void mma16816h(float c[4], const uint32_t a[4],
                                          uint32_t b0, uint32_t b1) {
    asm volatile("mma.sync.aligned.m16n8k16.row.col.f32.f16.f16.f32 "
        "{%0,%1,%2,%3}, {%4,%5,%6,%7}, {%8,%9}, {%0,%1,%2,%3};"
        : "+f"(c[0]), "+f"(c[1]), "+f"(c[2]), "+f"(c[3])
        : "r"(a[0]), "r"(a[1]), "r"(a[2]), "r"(a[3]), "r"(b0), "r"(b1));
}
__device__ __forceinline__ void splith2(float a, float b, uint32_t& hi, uint32_t& lo) {
    __half ha = __float2half_rn(a), hb = __float2half_rn(b);
    __half2 hh(ha, hb);
    hi = *(uint32_t*)&hh;
    __half2 ll(__float2half_rn(a - __half2float(ha)),
               __float2half_rn(b - __half2float(hb)));
    lo = *(uint32_t*)&ll;
}
__device__ __forceinline__ uint32_t ex2x2(float lo, float hi) {
    uint32_t r;
    asm("{.reg .b32 t;\n\tcvt.rn.f16x2.f32 t, %1, %2;\n\tex2.approx.f16x2 %0, t;}"
        : "=r"(r) : "f"(hi), "f"(lo));
    return r;
}
__device__ __forceinline__ float siluf(float x) {
    return x / (1.f + __expf(-x));
}

// ---------------- trig table (fp64 arg reduction) ----------------
__global__ void trig_k(float* __restrict__ trig) {
    int i = blockIdx.x * blockDim.x + threadIdx.x;
    int pair = i & 31;
    int t    = i >> 5;
    double theta = pow(10000.0, -(double)pair / 32.0);
    double ang   = fmod((double)t * theta, 6.283185307179586);
    trig[i]         = (float)cos(ang);
    trig[65536 + i] = (float)sin(ang);
}

// ---------------- RMSNorm + fp16 split ----------------
__global__ void rmsnorm_split_k(const float* __restrict__ x, const float* __restrict__ scale,
                                __half* __restrict__ oh, __half* __restrict__ ol) {
    int row = blockIdx.x;
    int tid = threadIdx.x;
    const float4* xr = (const float4*)(x + (size_t)row * NEMBD);
    float4 v = xr[tid];
    float ss = v.x*v.x + v.y*v.y + v.z*v.z + v.w*v.w;
    #pragma unroll
    for (int o = 16; o > 0; o >>= 1) ss += __shfl_xor_sync(0xffffffffu, ss, o);
    __shared__ float red[8];
    __shared__ float stot;
    if ((tid & 31) == 0) red[tid >> 5] = ss;
    __syncthreads();
    if (tid == 0) {
        float t = 0.f;
        #pragma unroll
        for (int i = 0; i < 8; i++) t += red[i];
        stot = rsqrtf(t * (1.0f/NEMBD) + 1e-5f);
    }
    __syncthreads();
    float rs = stot;
    float4 s4 = ((const float4*)scale)[tid];
    float o0 = v.x*rs*s4.x, o1 = v.y*rs*s4.y, o2 = v.z*rs*s4.z, o3 = v.w*rs*s4.w;
    uint32_t h01, l01, h23, l23;
    splith2(o0, o1, h01, l01);
    splith2(o2, o3, h23, l23);
    size_t off = (size_t)row * NEMBD + tid*4;
    *(uint32_t*)(oh + off)     = h01;
    *(uint32_t*)(oh + off + 2) = h23;
    *(uint32_t*)(ol + off)     = l01;
    *(uint32_t*)(ol + off + 2) = l23;
}

// ---------------- weight transpose + fp16 quantize ----------------
__global__ void wprep_k(const float* __restrict__ W, __half* __restrict__ Th,
                        int K, int N) {
    __shared__ float s[32][33];
    int n0 = blockIdx.x * 32, k0 = blockIdx.y * 32;
    int c = threadIdx.x & 31, r0 = threadIdx.x >> 5;
    #pragma unroll
    for (int i = 0; i < 4; i++) {
        int r = r0 + i*8;
        s[r][c] = W[(size_t)(k0 + r) * N + n0 + c];
    }
    __syncthreads();
    #pragma unroll
    for (int i = 0; i < 4; i++) {
        int r = r0 + i*8;
        Th[(size_t)(n0 + r) * K + k0 + c] = __float2half_rn(s[c][r]);
    }
}

// interleaved variant: output row nc = (n>>3)*16 + (n&7) + off8 (8-col block interleave)
__global__ void wprep2_k(const float* __restrict__ W, __half* __restrict__ Th,
                         int K, int N, int off8) {
    __shared__ float s[32][33];
    int n0 = blockIdx.x * 32, k0 = blockIdx.y * 32;
    int c = threadIdx.x & 31, r0 = threadIdx.x >> 5;
    #pragma unroll
    for (int i = 0; i < 4; i++) {
        int r = r0 + i*8;
        s[r][c] = W[(size_t)(k0 + r) * N + n0 + c];
    }
    __syncthreads();
    #pragma unroll
    for (int i = 0; i < 4; i++) {
        int r = r0 + i*8;
        int n = n0 + r;
        int nc = ((n >> 3) << 4) + (n & 7) + off8;
        Th[(size_t)nc * K + k0 + c] = __float2half_rn(s[c][r]);
    }
}

// ---------------- K/V prep: rope K, split fp16, transpose V ----------------
#define APAD 72
__global__ void kvprep_k(const float* __restrict__ qkv, const float* __restrict__ trig,
                         __half* __restrict__ Kh, __half* __restrict__ Kl,
                         __half* __restrict__ Vh, __half* __restrict__ Vl) {
    __shared__ __half Vsh[64][APAD], Vsl[64][APAD];
    int kt = blockIdx.x, h = blockIdx.y, b = blockIdx.z;
    int tid = threadIdx.x;
    const float* base = qkv + (size_t)b * TSEQ * QKVC;
    size_t khead = ((size_t)(b*NHEAD + h)) * TSEQ * HEADD;
    size_t vhead = ((size_t)(b*NHEAD + h)) * HEADD * TSEQ;

    for (int i = tid; i < 64*16; i += 256) {
        int row = i >> 4, c4 = (i & 15) * 4;
        int t = kt*64 + row;
        float4 k4 = *(const float4*)(base + (size_t)t * QKVC + NEMBD + h*HEADD + c4);
        int pr = c4 >> 1;
        float c0 = trig[t*32 + pr],     s0 = trig[65536 + t*32 + pr];
        float c1 = trig[t*32 + pr + 1], s1 = trig[65536 + t*32 + pr + 1];
        float e0 = k4.x*c0 - k4.y*s0, o0 = k4.x*s0 + k4.y*c0;
        float e1 = k4.z*c1 - k4.w*s1, o1 = k4.z*s1 + k4.w*c1;
        uint32_t h01, l01, h23, l23;
        splith2(e0, o0, h01, l01);
        splith2(e1, o1, h23, l23);
        size_t ko = khead + (size_t)t * HEADD + c4;
        *(uint32_t*)(Kh + ko)     = h01;
        *(uint32_t*)(Kh + ko + 2) = h23;
        *(uint32_t*)(Kl + ko)     = l01;
        *(uint32_t*)(Kl + ko + 2) = l23;
        float4 v4 = *(const float4*)(base + (size_t)t * QKVC + 2*NEMBD + h*HEADD + c4);
        float vv[4] = {v4.x, v4.y, v4.z, v4.w};
        #pragma unroll
        for (int jj = 0; jj < 4; jj++) {
            float fv = vv[jj];
            __half hv = __float2half_rn(fv);
            Vsh[c4 + jj][row] = hv;
            Vsl[c4 + jj][row] = __float2half_rn(fv - __half2float(hv));
        }
    }
    __syncthreads();
    for (int i = tid; i < 64*8; i += 256) {
        int d = i >> 3, seg = (i & 7) * 8;
        size_t vo = vhead + (size_t)d * TSEQ + kt*64 + seg;
        *(uint4*)(Vh + vo) = *(uint4*)(&Vsh[d][seg]);
        *(uint4*)(Vl + vo) = *(uint4*)(&Vsl[d][seg]);
    }
}

// ---------------- HMMA GEMM: 2-product fp16, 3-stage cp.async ----------------
// MODE 0: C = A@B^T ; MODE 1: C = A@B^T + res ; MODE 2: swiglu-fused (interleaved
// W1/W2 8-col blocks) -> split fp16 Gh/Gl with Nout = N/2 hidden columns.
#define PADK    40
#define TILE_B  (128*PADK*2)       // 10240 B
#define STAGE_B (3*TILE_B)         // 30720 B (Ah, Al, Bh)
#define GSMEM_B (3*STAGE_B)        // 92160 B

#define LOAD_STAGE(kt, s) do {                                                      \
    int _kof = (kt) * 32;                                                           \
    _Pragma("unroll")                                                               \
    for (int _i = 0; _i < 6; _i++) {                                                \
        int _id   = _i * 256 + tid;                                                 \
        int _tile = _id >> 9;                                                       \
        int _row  = (_id >> 2) & 127;                                               \
        int _ch   = _id & 3;                                                        \
        const __half* _g =                                                          \
            (_tile == 0 ? gA0 : _tile == 1 ? gA1 : gB0)                             \
            + (size_t)_row * K + _kof + _ch * 8;                                    \
        uint32_t _sa = sb + (uint32_t)(s) * STAGE_B + (uint32_t)_tile * TILE_B      \
                     + (uint32_t)(_row * PADK + _ch * 8) * 2u;                      \
        asm volatile("cp.async.cg.shared.global [%0], [%1], 16;" :: "r"(_sa), "l"(_g)); \
    }                                                                               \
    asm volatile("cp.async.commit_group;" ::: "memory");                            \
} while (0)

template<int MODE>
__global__ __launch_bounds__(256)
void hgemm_k(const __half* __restrict__ Ah, const __half* __restrict__ Al,
             const __half* __restrict__ Bh,
             const float* __restrict__ res, float* __restrict__ C,
             __half* __restrict__ Gh, __half* __restrict__ Gl,
             int N, int K) {
    extern __shared__ char smem[];
    uint32_t sb = smem_to_u32(smem);
    int tid  = threadIdx.x;
    int warp = tid >> 5, lane = tid & 31;
    int bm = blockIdx.y * 128, bn = blockIdx.x * 128;
    int wm = (warp & 1) * 64, wn = (warp >> 1) * 32;

    const __half* gA0 = Ah + (size_t)bm * K;
    const __half* gA1 = Al + (size_t)bm * K;
    const __half* gB0 = Bh + (size_t)bn * K;

    float acc[4][4][4];
    #pragma unroll
    for (int a = 0; a < 4; a++)
        #pragma unroll
        for (int b = 0; b < 4; b++)
            #pragma unroll
            for (int c = 0; c < 4; c++) acc[a][b][c] = 0.f;

    int nkt = K >> 5;
    LOAD_STAGE(0, 0);
    LOAD_STAGE(1, 1);
    for (int it = 0; it < nkt; it++) {
        int s = it % 3;
        if (it + 2 < nkt) LOAD_STAGE(it + 2, (it + 2) % 3);
        asm volatile("cp.async.wait_group 2;" ::: "memory");
        __syncthreads();
        uint32_t stb = sb + (uint32_t)s * STAGE_B;
        #pragma unroll
        for (int ks = 0; ks < 2; ks++) {
            uint32_t ar[4][4], al2[4][4], br[2][4];
            #pragma unroll
            for (int mi = 0; mi < 4; mi++) {
                uint32_t aoff = (uint32_t)(((wm + mi*16 + (lane & 15)) * PADK)
                                           + ks*16 + (lane >> 4) * 8) * 2u;
                ldsm4(ar[mi],  stb + aoff);
                ldsm4(al2[mi], stb + (uint32_t)TILE_B + aoff);
            }
            #pragma unroll
            for (int nq = 0; nq < 2; nq++)
                ldsm4(br[nq], stb + 2u*(uint32_t)TILE_B
                              + (uint32_t)(((wn + nq*16 + (lane & 15)) * PADK)
                                           + ks*16 + (lane >> 4) * 8) * 2u);
            #pragma unroll
            for (int mi = 0; mi < 4; mi++)
                #pragma unroll
                for (int j = 0; j < 4; j++)
                    mma16816h(acc[mi][j], ar[mi], br[j >> 1][j & 1], br[j >> 1][(j & 1) + 2]);
            #pragma unroll
            for (int mi = 0; mi < 4; mi++)
                #pragma unroll
                for (int j = 0; j < 4; j++)
                    mma16816h(acc[mi][j], al2[mi], br[j >> 1][j & 1], br[j >> 1][(j & 1) + 2]);
        }
        __syncthreads();
    }

    int r0 = lane >> 2, c0 = (lane & 3) * 2;
    if (MODE == 2) {
        // swiglu-fused: even-j frag = W1 cols, odd-j frag = W2 cols (same hidden idx)
        int Nout = N >> 1;
        #pragma unroll
        for (int mi = 0; mi < 4; mi++) {
            int gr = bm + wm + mi*16 + r0;
            #pragma unroll
            for (int jp = 0; jp < 2; jp++) {
                int f = ((bn + wn) >> 1) + jp*8 + c0;
                float* a = acc[mi][2*jp];
                float* bq = acc[mi][2*jp + 1];
                float m0 = siluf(a[0]) * bq[0];
                float m1 = siluf(a[1]) * bq[1];
                float m2 = siluf(a[2]) * bq[2];
                float m3 = siluf(a[3]) * bq[3];
                uint32_t hh, ll;
                size_t o1 = (size_t)gr * Nout + f;
                size_t o2 = (size_t)(gr + 8) * Nout + f;
                splith2(m0, m1, hh, ll);
                *(uint32_t*)(Gh + o1) = hh;
                *(uint32_t*)(Gl + o1) = ll;
                splith2(m2, m3, hh, ll);
                *(uint32_t*)(Gh + o2) = hh;
                *(uint32_t*)(Gl + o2) = ll;
            }
        }
    } else {
        #pragma unroll
        for (int mi = 0; mi < 4; mi++) {
            int gr = bm + wm + mi*16 + r0;
            #pragma unroll
            for (int j = 0; j < 4; j++) {
                int gc = bn + wn + j*8 + c0;
                size_t o1 = (size_t)gr * N + gc;
                size_t o2 = (size_t)(gr + 8) * N + gc;
                float2 v1 = make_float2(acc[mi][j][0], acc[mi][j][1]);
                float2 v2 = make_float2(acc[mi][j][2], acc[mi][j][3]);
                if (MODE == 1) {
                    float2 rr = *(const float2*)(res + o1); v1.x += rr.x; v1.y += rr.y;
                    float2 r2 = *(const float2*)(res + o2); v2.x += r2.x; v2.y += r2.y;
                }
                *(float2*)(C + o1) = v1;
                *(float2*)(C + o2) = v2;
            }
        }
    }
}

// ---------------- Flash attention: cp.async K/V tiles + fp16 mma ----------------
#define AQ_ELE (128*APAD)
#define KVTILE (64*APAD*2)
#define KVSTAGE (4*KVTILE)
#define KV_OFF (2*AQ_ELE*2)
#define YM_OFF (KV_OFF + 2*KVSTAGE)
#define ASMEM_B (YM_OFF + 256)

#define ALOAD(kt, s) do {                                                           \
    _Pragma("unroll")                                                               \
    for (int _i = 0; _i < 8; _i++) {                                                \
        int _id = _i*256 + tid;                                                     \
        int _tile = _id >> 9;                                                       \
        int _row = (_id >> 3) & 63;                                                 \
        int _ch = _id & 7;                                                          \
        const __half* _g;                                                           \
        if (_tile == 0)      _g = gKh + (size_t)((kt)*64 + _row)*HEADD + _ch*8;     \
        else if (_tile == 1) _g = gKl + (size_t)((kt)*64 + _row)*HEADD + _ch*8;     \
        else if (_tile == 2) _g = gVh + (size_t)_row*TSEQ + (kt)*64 + _ch*8;        \
        else                 _g = gVl + (size_t)_row*TSEQ + (kt)*64 + _ch*8;        \
        uint32_t _sa = kvb + (uint32_t)(s)*KVSTAGE + (uint32_t)_tile*KVTILE         \
                     + (uint32_t)(_row*APAD + _ch*8)*2u;                            \
        asm volatile("cp.async.cg.shared.global [%0], [%1], 16;" :: "r"(_sa), "l"(_g)); \
    }                                                                               \
    asm volatile("cp.async.commit_group;" ::: "memory");                            \
} while(0)

__global__ __launch_bounds__(256)
void attn_mma_k(const float* __restrict__ qkv, const int* __restrict__ y_mask,
                const float* __restrict__ trig,
                const __half* __restrict__ Khg, const __half* __restrict__ Klg,
                const __half* __restrict__ Vhg, const __half* __restrict__ Vlg,
                __half* __restrict__ yh, __half* __restrict__ yl) {
    extern __shared__ char smem[];
    uint32_t sb = smem_to_u32(smem);
    uint32_t sQh = sb, sQl = sb + AQ_ELE*2;
    uint32_t kvb = sb + KV_OFF;
    __half* Qh = (__half*)smem;
    __half* Ql = Qh + AQ_ELE;
    int* ymS = (int*)(smem + YM_OFF);

    int qt = (gridDim.x - 1) - blockIdx.x;
    int h = blockIdx.y, b = blockIdx.z;
    int bq = qt * 128;
    int tid = threadIdx.x, w = tid >> 5, lane = tid & 31;
    const float* base = qkv + (size_t)b * TSEQ * QKVC;
    const __half* gKh = Khg + ((size_t)(b*NHEAD + h)) * TSEQ * HEADD;
    const __half* gKl = Klg + ((size_t)(b*NHEAD + h)) * TSEQ * HEADD;
    const __half* gVh = Vhg + ((size_t)(b*NHEAD + h)) * HEADD * TSEQ;
    const __half* gVl = Vlg + ((size_t)(b*NHEAD + h)) * HEADD * TSEQ;

    int nkv = 2*qt + 2;
    ALOAD(0, 0);

    for (int i = tid; i < 128*16; i += 256) {
        int row = i >> 4, c4 = (i & 15) * 4;
        int t = bq + row;
        float4 v = *(const float4*)(base + (size_t)t * QKVC + h*HEADD + c4);
        int pr = c4 >> 1;
        float c0 = trig[t*32 + pr],     s0 = trig[65536 + t*32 + pr];
        float c1 = trig[t*32 + pr + 1], s1 = trig[65536 + t*32 + pr + 1];
        float e0 = v.x*c0 - v.y*s0, o0 = v.x*s0 + v.y*c0;
        float e1 = v.z*c1 - v.w*s1, o1 = v.z*s1 + v.w*c1;
        uint32_t h01, l01, h23, l23;
        splith2(e0, o0, h01, l01);
        splith2(e1, o1, h23, l23);
        int o = row * APAD + c4;
        *(uint32_t*)(Qh + o)     = h01;
        *(uint32_t*)(Qh + o + 2) = h23;
        *(uint32_t*)(Ql + o)     = l01;
        *(uint32_t*)(Ql + o + 2) = l23;
    }
    if (tid < 64) ymS[tid] = y_mask[b * 64 + tid];
    __syncthreads();

    int r0 = lane >> 2;
    int cq = (lane & 3) * 2;
    int wq = bq + w * 16;
    int qi0 = wq + r0, qi1 = qi0 + 8;
    int ymq0 = (qi0 < 64) ? ymS[qi0] : 0;
    int ymq1 = (qi1 < 64) ? ymS[qi1] : 0;

    float Oacc[8][4];
    #pragma unroll
    for (int j = 0; j < 8; j++)
        #pragma unroll
        for (int c = 0; c < 4; c++) Oacc[j][c] = 0.f;
    float mrun0 = -1e30f, mrun1 = -1e30f, l0 = 0.f, l1 = 0.f;

    const float LS = 0.18033688011112042f;  // 0.125 * log2(e)

    for (int kt = 0; kt < nkv; kt++) {
        int s = kt & 1;
        if (kt + 1 < nkv) {
            ALOAD(kt + 1, s ^ 1);
            asm volatile("cp.async.wait_group 1;" ::: "memory");
        } else {
            asm volatile("cp.async.wait_group 0;" ::: "memory");
        }
        __syncthreads();
        uint32_t bKh = kvb + (uint32_t)s * KVSTAGE;
        uint32_t bKl = bKh + KVTILE;
        uint32_t bVh = bKh + 2*KVTILE;
        uint32_t bVl = bKh + 3*KVTILE;

        float S[8][4];
        #pragma unroll
        for (int j = 0; j < 8; j++)
            #pragma unroll
            for (int c = 0; c < 4; c++) S[j][c] = 0.f;

        #pragma unroll
        for (int ks = 0; ks < 4; ks++) {
            uint32_t ah[4], al[4];
            uint32_t aoff = (uint32_t)(((w*16 + (lane & 15)) * APAD) + ks*16 + (lane >> 4) * 8) * 2u;
            ldsm4(ah, sQh + aoff);
            ldsm4(al, sQl + aoff);
            #pragma unroll
            for (int nt = 0; nt < 4; nt++) {
                uint32_t bh[4], bl[4];
                uint32_t boff = (uint32_t)(((nt*16 + (lane & 15)) * APAD) + ks*16 + (lane >> 4) * 8) * 2u;
                ldsm4(bh, bKh + boff);
                ldsm4(bl, bKl + boff);
                int t0 = nt*2, t1 = nt*2 + 1;
                mma16816h(S[t0], ah, bh[0], bh[2]);
                mma16816h(S[t1], ah, bh[1], bh[3]);
                mma16816h(S[t0], ah, bl[0], bl[2]);
                mma16816h(S[t1], ah, bl[1], bl[3]);
                mma16816h(S[t0], al, bh[0], bh[2]);
                mma16816h(S[t1], al, bh[1], bh[3]);
            }
        }

        bool needmask = (kt*64 + 63 > wq) || (wq < 64 && kt == 0);
        int kbase = kt * 64;
        if (needmask) {
            #pragma unroll
            for (int j = 0; j < 8; j++) {
                int kj = kbase + j*8 + cq;
                bool tx0 = ymq0 && (kj < 64);
                bool tx1 = ymq1 && (kj < 64);
                S[j][0] = ((kj   <= qi0) || (tx0 && ymS[kj]  )) ? S[j][0]*LS : -1e30f;
                S[j][1] = ((kj+1 <= qi0) || (tx0 && (kj+1<64) && ymS[kj+1])) ? S[j][1]*LS : -1e30f;
                S[j][2] = ((kj   <= qi1) || (tx1 && ymS[kj]  )) ? S[j][2]*LS : -1e30f;
                S[j][3] = ((kj+1 <= qi1) || (tx1 && (kj+1<64) && ymS[kj+1])) ? S[j][3]*LS : -1e30f;
            }
        } else {
            #pragma unroll
            for (int j = 0; j < 8; j++)
                #pragma unroll
                for (int c = 0; c < 4; c++) S[j][c] *= LS;
        }

        float tmax0 = -1e30f, tmax1 = -1e30f;
        #pragma unroll
        for (int j = 0; j < 8; j++) {
            tmax0 = fmaxf(tmax0, fmaxf(S[j][0], S[j][1]));
            tmax1 = fmaxf(tmax1, fmaxf(S[j][2], S[j][3]));
        }
        tmax0 = fmaxf(tmax0, __shfl_xor_sync(0xffffffffu, tmax0, 1));
        tmax0 = fmaxf(tmax0, __shfl_xor_sync(0xffffffffu, tmax0, 2));
        tmax1 = fmaxf(tmax1, __shfl_xor_sync(0xffffffffu, tmax1, 1));
        tmax1 = fmaxf(tmax1, __shfl_xor_sync(0xffffffffu, tmax1, 2));
        float mnew0 = fmaxf(mrun0, tmax0);
        float mnew1 = fmaxf(mrun1, tmax1);
        float corr0 = exp2f(mrun0 - mnew0);
        float corr1 = exp2f(mrun1 - mnew1);
        mrun0 = mnew0; mrun1 = mnew1;

        uint32_t ph[4][4];
        float sum0 = 0.f, sum1 = 0.f;
        #pragma unroll
        for (int ks = 0; ks < 4; ks++) {
            int t0 = ks*2, t1 = ks*2 + 1;
            ph[ks][0] = ex2x2(S[t0][0]-mnew0, S[t0][1]-mnew0);
            ph[ks][1] = ex2x2(S[t0][2]-mnew1, S[t0][3]-mnew1);
            ph[ks][2] = ex2x2(S[t1][0]-mnew0, S[t1][1]-mnew0);
            ph[ks][3] = ex2x2(S[t1][2]-mnew1, S[t1][3]-mnew1);
            __half2 p0 = *(__half2*)&ph[ks][0];
            __half2 p1 = *(__half2*)&ph[ks][1];
            __half2 p2 = *(__half2*)&ph[ks][2];
            __half2 p3 = *(__half2*)&ph[ks][3];
            sum0 += __low2float(p0) + __high2float(p0) + __low2float(p2) + __high2float(p2);
            sum1 += __low2float(p1) + __high2float(p1) + __low2float(p3) + __high2float(p3);
        }
        sum0 += __shfl_xor_sync(0xffffffffu, sum0, 1);
        sum0 += __shfl_xor_sync(0xffffffffu, sum0, 2);
        sum1 += __shfl_xor_sync(0xffffffffu, sum1, 1);
        sum1 += __shfl_xor_sync(0xffffffffu, sum1, 2);
        l0 = l0 * corr0 + sum0;
        l1 = l1 * corr1 + sum1;

        #pragma unroll
        for (int j = 0; j < 8; j++) {
            Oacc[j][0] *= corr0; Oacc[j][1] *= corr0;
            Oacc[j][2] *= corr1; Oacc[j][3] *= corr1;
        }

        #pragma unroll
        for (int ks = 0; ks < 4; ks++) {
            #pragma unroll
            for (int nt = 0; nt < 4; nt++) {
                uint32_t bh[4], bl[4];
                uint32_t boff = (uint32_t)(((nt*16 + (lane & 15)) * APAD) + ks*16 + (lane >> 4) * 8) * 2u;
                ldsm4(bh, bVh + boff);
                ldsm4(bl, bVl + boff);
                int t0 = nt*2, t1 = nt*2 + 1;
                mma16816h(Oacc[t0], ph[ks], bh[0], bh[2]);
                mma16816h(Oacc[t1], ph[ks], bh[1], bh[3]);
                mma16816h(Oacc[t0], ph[ks], bl[0], bl[2]);
                mma16816h(Oacc[t1], ph[ks], bl[1], bl[3]);
            }
        }
        __syncthreads();
    }

    float inv0 = 1.0f / l0;
    float inv1 = 1.0f / l1;
    size_t yo0 = (size_t)(b * TSEQ + qi0) * NEMBD + h * HEADD;
    size_t yo1 = (size_t)(b * TSEQ + qi1) * NEMBD + h * HEADD;
    #pragma unroll
    for (int j = 0; j < 8; j++) {
        int d = j*8 + cq;
        uint32_t hh, ll;
        splith2(Oacc[j][0]*inv0, Oacc[j][1]*inv0, hh, ll);
        *(uint32_t*)(yh + yo0 + d) = hh;
        *(uint32_t*)(yl + yo0 + d) = ll;
        splith2(Oacc[j][2]*inv1, Oacc[j][3]*inv1, hh, ll);
        *(uint32_t*)(yh + yo1 + d) = hh;
        *(uint32_t*)(yl + yo1 + d) = ll;
    }
}

// ---------------- launch ----------------
static void* sym(const void* s) { void* p = nullptr; cudaGetSymbolAddress(&p, s); return p; }

extern "C" void kernel_launch(void* const* d_in, const int* in_sizes, int n_in,
                              void* d_out, int out_size) {
    const float* x    = (const float*)d_in[0];
    const int*   ym   = (const int*)  d_in[1];
    const float* Wqkv = (const float*)d_in[2];
    const float* Wap  = (const float*)d_in[3];
    const float* s1   = (const float*)d_in[4];
    const float* s2   = (const float*)d_in[5];
    const float* Wfc1 = (const float*)d_in[6];
    const float* Wfc2 = (const float*)d_in[7];
    const float* Wmp  = (const float*)d_in[8];
    float* out = (float*)d_out;

    float* qkv  = (float*)sym(d_qkv);
    float* x1   = (float*)sym(d_x1);
    float* trig = (float*)sym(d_trig);
    __half* ah  = (__half*)sym(d_ah);
    __half* al  = (__half*)sym(d_al);
    __half* yh  = (__half*)sym(d_yh);
    __half* yl  = (__half*)sym(d_yl);
    __half* h2h = (__half*)sym(d_h2h);
    __half* h2l = (__half*)sym(d_h2l);
    __half* gh  = (__half*)sym(d_gh);
    __half* gl  = (__half*)sym(d_gl);
    __half* wqh = (__half*)sym(d_wqkvh);
    __half* wah = (__half*)sym(d_waph);
    __half* w12 = (__half*)sym(d_w12);
    __half* wmh = (__half*)sym(d_wmph);
    __half* kh  = (__half*)sym(d_kh);
    __half* kl  = (__half*)sym(d_kl);
    __half* vh  = (__half*)sym(d_vh);
    __half* vl  = (__half*)sym(d_vl);

    cudaFuncSetAttribute(hgemm_k<0>, cudaFuncAttributeMaxDynamicSharedMemorySize, GSMEM_B);
    cudaFuncSetAttribute(hgemm_k<1>, cudaFuncAttributeMaxDynamicSharedMemorySize, GSMEM_B);
    cudaFuncSetAttribute(hgemm_k<2>, cudaFuncAttributeMaxDynamicSharedMemorySize, GSMEM_B);
    cudaFuncSetAttribute(attn_mma_k, cudaFuncAttributeMaxDynamicSharedMemorySize, ASMEM_B);

    trig_k<<<65536/256, 256>>>(trig);

    wprep_k<<<dim3(QKVC/32,  NEMBD/32), 256>>>(Wqkv, wqh, NEMBD, QKVC);
    wprep_k<<<dim3(NEMBD/32, NEMBD/32), 256>>>(Wap,  wah, NEMBD, NEMBD);
    wprep2_k<<<dim3(NHID/32, NEMBD/32), 256>>>(Wfc1, w12, NEMBD, NHID, 0);
    wprep2_k<<<dim3(NHID/32, NEMBD/32), 256>>>(Wfc2, w12, NEMBD, NHID, 8);
    wprep_k<<<dim3(NEMBD/32, NHID/32),  256>>>(Wmp,  wmh, NHID, NEMBD);

    rmsnorm_split_k<<<MROWS, 256>>>(x, s1, ah, al);
    hgemm_k<0><<<dim3(QKVC/128, MROWS/128), 256, GSMEM_B>>>(ah, al, wqh, nullptr, qkv, nullptr, nullptr, QKVC, NEMBD);
    kvprep_k<<<dim3(TSEQ/64, NHEAD, BATCH), 256>>>(qkv, trig, kh, kl, vh, vl);
    attn_mma_k<<<dim3(TSEQ/128, NHEAD, BATCH), 256, ASMEM_B>>>(qkv, ym, trig, kh, kl, vh, vl, yh, yl);
    hgemm_k<1><<<dim3(NEMBD/128, MROWS/128), 256, GSMEM_B>>>(yh, yl, wah, x, x1, nullptr, nullptr, NEMBD, NEMBD);
    rmsnorm_split_k<<<MROWS, 256>>>(x1, s2, h2h, h2l);
    // fused fc1+fc2+swiglu: N = 2*NHID interleaved, outputs split gh/gl [MROWS, NHID]
    hgemm_k<2><<<dim3(2*NHID/128, MROWS/128), 256, GSMEM_B>>>(h2h, h2l, w12, nullptr, nullptr, gh, gl, 2*NHID, NEMBD);
    hgemm_k<1><<<dim3(NEMBD/128, MROWS/128), 256, GSMEM_B>>>(gh, gl, wmh, x1, out, nullptr, nullptr, NEMBD, NHID);
}